// round 7
// baseline (speedup 1.0000x reference)
#include <cuda_runtime.h>
#include <math.h>
#include <cstdint>

// ---------------- problem constants ----------------
#define Bc   8
#define Sc   512
#define Dc   512
#define NHc  8
#define DHc  64
#define Lc   6
#define HIDc 2048
#define EPSc 1e-5f
#define BSc  (Bc * Sc)          // 4096 tokens
#define SCALEc 0.125f           // 1/sqrt(64)

// ---------------- device scratch ----------------
__device__ float g_x[BSc * Dc];
__device__ float g_y[BSc * Dc];
__device__ float g_q[BSc * Dc];
__device__ float g_attn[BSc * Dc];
__device__ float g_tmp[BSc * Dc];
__device__ float g_hid[BSc * HIDc];      // FFN hidden / fused QKV / fused KV scratch
__device__ unsigned char g_mx[BSc];
__device__ unsigned char g_my[BSc];
// transposed (tf32-rounded) weights: [N][K]
__device__ float g_wt_enc_attn[Lc * 4 * Dc * Dc];
__device__ float g_wt_dec_self[Lc * 4 * Dc * Dc];
__device__ float g_wt_dec_cross[Lc * 4 * Dc * Dc];
__device__ float g_wt_enc_f1[Lc * Dc * HIDc];
__device__ float g_wt_enc_f2[Lc * Dc * HIDc];
__device__ float g_wt_dec_f1[Lc * Dc * HIDc];
__device__ float g_wt_dec_f2[Lc * Dc * HIDc];

__device__ __forceinline__ float neg_inf_f() { return __int_as_float(0xff800000u); }

__device__ __forceinline__ uint32_t round_tf32(float v) {
    uint32_t u; asm("cvt.rna.tf32.f32 %0, %1;" : "=r"(u) : "f"(v)); return u;
}
__device__ __forceinline__ uint32_t smem_u32(const void* p) {
    uint32_t a;
    asm("{ .reg .u64 t; cvta.to.shared.u64 t, %1; cvt.u32.u64 %0, t; }" : "=r"(a) : "l"(p));
    return a;
}

// mma.sync m16n8k8 tf32 (sm_80+ family-compatible; NO tcgen05 on this toolchain)
__device__ __forceinline__ void mma_16n8k8(float c[4], const uint32_t a[4], const uint32_t b[2]) {
    asm volatile(
        "mma.sync.aligned.m16n8k8.row.col.f32.tf32.tf32.f32 "
        "{%0,%1,%2,%3}, {%4,%5,%6,%7}, {%8,%9}, {%0,%1,%2,%3};"
        : "+f"(c[0]), "+f"(c[1]), "+f"(c[2]), "+f"(c[3])
        : "r"(a[0]), "r"(a[1]), "r"(a[2]), "r"(a[3]), "r"(b[0]), "r"(b[1]));
}

// ---------------- weight transpose (with tf32 rounding) ----------------
__global__ void transpose_tf32(const float* __restrict__ in, float* __restrict__ out,
                               int R, int C) {
    __shared__ float tile[32][33];
    const float* src = in + (size_t)blockIdx.z * R * C;
    float* dst = out + (size_t)blockIdx.z * R * C;
    int c0 = blockIdx.x * 32, r0 = blockIdx.y * 32;
    int tx = threadIdx.x, ty = threadIdx.y;          // 32 x 8
    #pragma unroll
    for (int i = 0; i < 32; i += 8)
        tile[ty + i][tx] = src[(size_t)(r0 + ty + i) * C + c0 + tx];
    __syncthreads();
    #pragma unroll
    for (int i = 0; i < 32; i += 8) {
        float v = tile[tx][ty + i];
        dst[(size_t)(c0 + ty + i) * R + r0 + tx] = __uint_as_float(round_tf32(v));
    }
}

// ---------------- tf32 mma GEMM, 3-stage cp.async ring ----------------
// C[M,N] = A[M,K] @ BT[N,K]^T + bias (+ resid).
// 128x128 CTA tile, 4 warps (2M x 2N), warp tile 64x64 (mi=4, ni=8), K-chunk 32.
// LDS per mma: 4/ni + 2/mi = 1.0 (was 1.5 with 64x32 warp tiles).
#define PADK 36                         // (row*36+k)%32 == (row*4+k)%32 -> conflict-free
#define GBUF (128 * PADK)               // uint32s per operand tile
#define STAGES 3
#define GEMM_SMEM (STAGES * 2 * GBUF * 4)   // 110592 bytes -> 2 CTAs/SM

template<bool RELU>
__global__ void __launch_bounds__(128) gemm_mma(const float* __restrict__ A,
                                                const float* __restrict__ BT,
                                                const float* __restrict__ bias,
                                                const float* __restrict__ resid,
                                                float* __restrict__ C,
                                                int M, int N, int K) {
    extern __shared__ uint32_t gs[];
    uint32_t sbase = smem_u32(gs);
    int tid = threadIdx.x;
    int lane = tid & 31, wid = tid >> 5;       // 4 warps
    int wm = wid & 1;                          // 2 x 64 rows
    int wn = wid >> 1;                         // 2 x 64 cols
    int row0 = blockIdx.y * 128, col0 = blockIdx.x * 128;
    int g = lane >> 2, tg = lane & 3;
    int lr = tid >> 3, lc = (tid & 7) * 4;     // 16 rows per pass, 8 passes

    float acc[4][8][4];
    #pragma unroll
    for (int mi = 0; mi < 4; mi++)
        #pragma unroll
        for (int ni = 0; ni < 8; ni++)
            #pragma unroll
            for (int r = 0; r < 4; r++) acc[mi][ni][r] = 0.0f;

    int nch = K >> 5;

    // prefetch chunk 0 into stage 0
    {
        uint32_t abase = sbase;
        uint32_t bbase = sbase + GBUF * 4;
        #pragma unroll
        for (int i = 0; i < 8; ++i) {
            int r = lr + i * 16;
            uint32_t off = (uint32_t)(r * PADK + lc) * 4;
            const float* pa = &A[(size_t)(row0 + r) * K + lc];
            asm volatile("cp.async.cg.shared.global [%0], [%1], 16;" :: "r"(abase + off), "l"(pa));
            const float* pb = &BT[(size_t)(col0 + r) * K + lc];
            asm volatile("cp.async.cg.shared.global [%0], [%1], 16;" :: "r"(bbase + off), "l"(pb));
        }
        asm volatile("cp.async.commit_group;" ::: "memory");
    }

    for (int c = 0; c < nch; ++c) {
        // depth-1 prefetch into stage (c+1)%3; stage was last computed at iter c-2,
        // already ordered by the single barrier at iter c-1.
        if (c + 1 < nch) {
            int k0 = (c + 1) << 5;
            uint32_t abase = sbase + (uint32_t)(((c + 1) % STAGES) * 2 * GBUF) * 4;
            uint32_t bbase = abase + GBUF * 4;
            #pragma unroll
            for (int i = 0; i < 8; ++i) {
                int r = lr + i * 16;
                uint32_t off = (uint32_t)(r * PADK + lc) * 4;
                const float* pa = &A[(size_t)(row0 + r) * K + k0 + lc];
                asm volatile("cp.async.cg.shared.global [%0], [%1], 16;" :: "r"(abase + off), "l"(pa));
                const float* pb = &BT[(size_t)(col0 + r) * K + k0 + lc];
                asm volatile("cp.async.cg.shared.global [%0], [%1], 16;" :: "r"(bbase + off), "l"(pb));
            }
        }
        asm volatile("cp.async.commit_group;" ::: "memory");
        asm volatile("cp.async.wait_group 1;" ::: "memory");
        __syncthreads();

        const uint32_t* As = gs + (c % STAGES) * 2 * GBUF;
        const uint32_t* Bs = As + GBUF;

        #pragma unroll
        for (int ki = 0; ki < 4; ++ki) {
            int ak = ki * 8 + tg;
            uint32_t afr[4][4];
            #pragma unroll
            for (int mi = 0; mi < 4; mi++) {
                int r = wm * 64 + mi * 16 + g;
                afr[mi][0] = round_tf32(__uint_as_float(As[(r)     * PADK + ak]));
                afr[mi][1] = round_tf32(__uint_as_float(As[(r + 8) * PADK + ak]));
                afr[mi][2] = round_tf32(__uint_as_float(As[(r)     * PADK + ak + 4]));
                afr[mi][3] = round_tf32(__uint_as_float(As[(r + 8) * PADK + ak + 4]));
            }
            uint32_t bfr[8][2];
            #pragma unroll
            for (int ni = 0; ni < 8; ni++) {
                int n = wn * 64 + ni * 8 + g;
                bfr[ni][0] = Bs[n * PADK + ak];
                bfr[ni][1] = Bs[n * PADK + ak + 4];
            }
            #pragma unroll
            for (int mi = 0; mi < 4; mi++)
                #pragma unroll
                for (int ni = 0; ni < 8; ni++)
                    mma_16n8k8(acc[mi][ni], afr[mi], bfr[ni]);
        }
        // no trailing barrier (3-stage ring)
    }

    #pragma unroll
    for (int mi = 0; mi < 4; mi++) {
        int r0r = row0 + wm * 64 + mi * 16 + g;
        #pragma unroll
        for (int ni = 0; ni < 8; ni++) {
            int cb = col0 + wn * 64 + ni * 8 + tg * 2;
            float b0 = bias[cb], b1 = bias[cb + 1];
            float v0 = acc[mi][ni][0] + b0, v1 = acc[mi][ni][1] + b1;
            float v2 = acc[mi][ni][2] + b0, v3 = acc[mi][ni][3] + b1;
            if (resid) {
                float2 r0v = *reinterpret_cast<const float2*>(&resid[(size_t)(r0r)     * N + cb]);
                float2 r1v = *reinterpret_cast<const float2*>(&resid[(size_t)(r0r + 8) * N + cb]);
                v0 += r0v.x; v1 += r0v.y; v2 += r1v.x; v3 += r1v.y;
            }
            if (RELU) { v0 = fmaxf(v0, 0.f); v1 = fmaxf(v1, 0.f);
                        v2 = fmaxf(v2, 0.f); v3 = fmaxf(v3, 0.f); }
            *reinterpret_cast<float2*>(&C[(size_t)(r0r)     * N + cb]) = make_float2(v0, v1);
            *reinterpret_cast<float2*>(&C[(size_t)(r0r + 8) * N + cb]) = make_float2(v2, v3);
        }
    }
}

// ---------------- fused flash attention (tf32 mma), strided q/k/v ----------------
#define FPAD 68
#define FLASH_SMEM ((128 + 64 + 64 + 128) * FPAD * 4 + 64)

__global__ void __launch_bounds__(256) flash_attn(
    const float* __restrict__ q, int ldq,
    const float* __restrict__ k, const float* __restrict__ v, int ldkv,
    const unsigned char* __restrict__ mqg, const unsigned char* __restrict__ mkg,
    float* __restrict__ o, int causal)
{
    extern __shared__ char sm[];
    uint32_t* Qs = reinterpret_cast<uint32_t*>(sm);
    uint32_t* Ks = Qs + 128 * FPAD;
    uint32_t* Vt = Ks + 64 * FPAD;
    uint32_t* Ps = Vt + 64 * FPAD;
    unsigned char* mks = reinterpret_cast<unsigned char*>(Ps + 128 * FPAD);

    int tid = threadIdx.x, lane = tid & 31, wid = tid >> 5;
    int bh = blockIdx.y, b = bh >> 3, h = bh & 7;
    int q0 = blockIdx.x * 128;
    const float* Qg = q + (size_t)b * Sc * ldq + h * DHc;
    const float* Kg = k + (size_t)b * Sc * ldkv + h * DHc;
    const float* Vg = v + (size_t)b * Sc * ldkv + h * DHc;
    int g = lane >> 2, tg = lane & 3;
    int rg = wid * 16 + g;
    int qi0 = q0 + rg, qi1 = qi0 + 8;

    #pragma unroll
    for (int i = 0; i < 8; ++i) {
        int idx = tid + i * 256;
        int r = idx >> 4, c = (idx & 15) * 4;
        float4 va = *reinterpret_cast<const float4*>(&Qg[(size_t)(q0 + r) * ldq + c]);
        Qs[r * FPAD + c + 0] = round_tf32(va.x);
        Qs[r * FPAD + c + 1] = round_tf32(va.y);
        Qs[r * FPAD + c + 2] = round_tf32(va.z);
        Qs[r * FPAD + c + 3] = round_tf32(va.w);
    }
    bool mrow0 = mqg[b * Sc + qi0] != 0;
    bool mrow1 = mqg[b * Sc + qi1] != 0;

    float m0 = -1e30f, m1 = -1e30f, l0 = 0.f, l1 = 0.f;
    float oacc[8][4];
    #pragma unroll
    for (int ni = 0; ni < 8; ni++) { oacc[ni][0] = oacc[ni][1] = oacc[ni][2] = oacc[ni][3] = 0.f; }

    int nkt = causal ? ((q0 >> 6) + 2) : (Sc / 64);
    for (int kt = 0; kt < nkt; ++kt) {
        int k0 = kt * 64;
        __syncthreads();
        #pragma unroll
        for (int i = 0; i < 4; ++i) {
            int idx = tid + i * 256;
            int r = idx >> 4, c = (idx & 15) * 4;
            float4 vk = *reinterpret_cast<const float4*>(&Kg[(size_t)(k0 + r) * ldkv + c]);
            Ks[r * FPAD + c + 0] = round_tf32(vk.x);
            Ks[r * FPAD + c + 1] = round_tf32(vk.y);
            Ks[r * FPAD + c + 2] = round_tf32(vk.z);
            Ks[r * FPAD + c + 3] = round_tf32(vk.w);
            float4 vv = *reinterpret_cast<const float4*>(&Vg[(size_t)(k0 + r) * ldkv + c]);
            Vt[(c + 0) * FPAD + r] = round_tf32(vv.x);
            Vt[(c + 1) * FPAD + r] = round_tf32(vv.y);
            Vt[(c + 2) * FPAD + r] = round_tf32(vv.z);
            Vt[(c + 3) * FPAD + r] = round_tf32(vv.w);
        }
        if (tid < 64) mks[tid] = mkg[b * Sc + k0 + tid];
        __syncthreads();

        float s[8][4];
        #pragma unroll
        for (int ni = 0; ni < 8; ni++) { s[ni][0] = s[ni][1] = s[ni][2] = s[ni][3] = 0.f; }
        #pragma unroll
        for (int ki = 0; ki < 8; ++ki) {
            int ak = ki * 8 + tg;
            uint32_t a[4] = { Qs[rg * FPAD + ak],       Qs[(rg + 8) * FPAD + ak],
                              Qs[rg * FPAD + ak + 4],   Qs[(rg + 8) * FPAD + ak + 4] };
            #pragma unroll
            for (int ni = 0; ni < 8; ni++) {
                uint32_t bfr[2] = { Ks[(ni * 8 + g) * FPAD + ak],
                                    Ks[(ni * 8 + g) * FPAD + ak + 4] };
                mma_16n8k8(s[ni], a, bfr);
            }
        }

        float rmax0 = neg_inf_f(), rmax1 = neg_inf_f();
        #pragma unroll
        for (int ni = 0; ni < 8; ni++) {
            int cloc = ni * 8 + 2 * tg;
            int cg = k0 + cloc;
            bool mkA = mks[cloc] != 0, mkB = mks[cloc + 1] != 0;
            float v0 = (mrow0 || mkA || (causal && cg     > qi0)) ? neg_inf_f() : s[ni][0] * SCALEc;
            float v1 = (mrow0 || mkB || (causal && cg + 1 > qi0)) ? neg_inf_f() : s[ni][1] * SCALEc;
            float v2 = (mrow1 || mkA || (causal && cg     > qi1)) ? neg_inf_f() : s[ni][2] * SCALEc;
            float v3 = (mrow1 || mkB || (causal && cg + 1 > qi1)) ? neg_inf_f() : s[ni][3] * SCALEc;
            s[ni][0] = v0; s[ni][1] = v1; s[ni][2] = v2; s[ni][3] = v3;
            rmax0 = fmaxf(rmax0, fmaxf(v0, v1));
            rmax1 = fmaxf(rmax1, fmaxf(v2, v3));
        }
        rmax0 = fmaxf(rmax0, __shfl_xor_sync(0xffffffffu, rmax0, 1));
        rmax0 = fmaxf(rmax0, __shfl_xor_sync(0xffffffffu, rmax0, 2));
        rmax1 = fmaxf(rmax1, __shfl_xor_sync(0xffffffffu, rmax1, 1));
        rmax1 = fmaxf(rmax1, __shfl_xor_sync(0xffffffffu, rmax1, 2));

        float mn0 = fmaxf(m0, rmax0), mn1 = fmaxf(m1, rmax1);
        float sc0 = __expf(m0 - mn0), sc1 = __expf(m1 - mn1);
        float rs0 = 0.f, rs1 = 0.f;
        #pragma unroll
        for (int ni = 0; ni < 8; ni++) {
            int cloc = ni * 8 + 2 * tg;
            float p0 = __expf(s[ni][0] - mn0), p1 = __expf(s[ni][1] - mn0);
            float p2 = __expf(s[ni][2] - mn1), p3 = __expf(s[ni][3] - mn1);
            rs0 += p0 + p1; rs1 += p2 + p3;
            Ps[rg * FPAD + cloc]           = round_tf32(p0);
            Ps[rg * FPAD + cloc + 1]       = round_tf32(p1);
            Ps[(rg + 8) * FPAD + cloc]     = round_tf32(p2);
            Ps[(rg + 8) * FPAD + cloc + 1] = round_tf32(p3);
        }
        rs0 += __shfl_xor_sync(0xffffffffu, rs0, 1);
        rs0 += __shfl_xor_sync(0xffffffffu, rs0, 2);
        rs1 += __shfl_xor_sync(0xffffffffu, rs1, 1);
        rs1 += __shfl_xor_sync(0xffffffffu, rs1, 2);
        l0 = l0 * sc0 + rs0; l1 = l1 * sc1 + rs1;
        m0 = mn0; m1 = mn1;
        #pragma unroll
        for (int ni = 0; ni < 8; ni++) {
            oacc[ni][0] *= sc0; oacc[ni][1] *= sc0;
            oacc[ni][2] *= sc1; oacc[ni][3] *= sc1;
        }
        __syncwarp();

        #pragma unroll
        for (int ki = 0; ki < 8; ++ki) {
            int ak = ki * 8 + tg;
            uint32_t a[4] = { Ps[rg * FPAD + ak],       Ps[(rg + 8) * FPAD + ak],
                              Ps[rg * FPAD + ak + 4],   Ps[(rg + 8) * FPAD + ak + 4] };
            #pragma unroll
            for (int ni = 0; ni < 8; ni++) {
                uint32_t bfr[2] = { Vt[(ni * 8 + g) * FPAD + ak],
                                    Vt[(ni * 8 + g) * FPAD + ak + 4] };
                mma_16n8k8(oacc[ni], a, bfr);
            }
        }
    }

    float inv0 = (l0 > 0.f) ? 1.f / l0 : 0.f;
    float inv1 = (l1 > 0.f) ? 1.f / l1 : 0.f;
    size_t ob0 = ((size_t)b * Sc + qi0) * Dc + h * DHc;
    size_t ob1 = ((size_t)b * Sc + qi1) * Dc + h * DHc;
    #pragma unroll
    for (int ni = 0; ni < 8; ni++) {
        int cc = ni * 8 + 2 * tg;
        *reinterpret_cast<float2*>(&o[ob0 + cc]) = make_float2(oacc[ni][0] * inv0, oacc[ni][1] * inv0);
        *reinterpret_cast<float2*>(&o[ob1 + cc]) = make_float2(oacc[ni][2] * inv1, oacc[ni][3] * inv1);
    }
}

// ---------------- embedding + positional encoding (+ pad mask) ----------------
__global__ void embed_pe_kernel(const int* __restrict__ toks,
                                const float* __restrict__ emb,
                                float* __restrict__ out,
                                unsigned char* __restrict__ mask) {
    int pos = blockIdx.x % Sc;
    int b   = blockIdx.x / Sc;
    int tok = toks[b * Sc + pos];
    int t = threadIdx.x;
    if (t == 0) mask[b * Sc + pos] = (tok == 0) ? 1 : 0;
    const float c = -logf(10000.0f) / (float)Dc;
    size_t base = ((size_t)b * Sc + pos) * Dc;
    #pragma unroll
    for (int d = t; d < Dc; d += 256) {
        int i = d >> 1;
        float freq = __expf((float)(2 * i) * c);
        float ang  = (float)pos * freq;
        float pe   = (d & 1) ? cosf(ang) : sinf(ang);
        out[base + d] = emb[(size_t)tok * Dc + d] + pe;
    }
}

// ---------------- out = LayerNorm(xin) * gamma + beta  (warp per row) ----------------
__global__ void __launch_bounds__(256) ln_kernel(const float* __restrict__ xin,
                                                 const float* __restrict__ gamma,
                                                 const float* __restrict__ beta,
                                                 float* __restrict__ out) {
    int warp = threadIdx.x >> 5, lane = threadIdx.x & 31;
    size_t row = (size_t)blockIdx.x * 8 + warp;
    size_t base = row * Dc;
    float4 v[4];
    float sum = 0.f;
    #pragma unroll
    for (int i = 0; i < 4; ++i) {
        v[i] = *reinterpret_cast<const float4*>(&xin[base + lane * 4 + i * 128]);
        sum += v[i].x + v[i].y + v[i].z + v[i].w;
    }
    #pragma unroll
    for (int s = 16; s > 0; s >>= 1) sum += __shfl_xor_sync(0xffffffffu, sum, s);
    float mu = sum * (1.0f / Dc);
    float var = 0.f;
    #pragma unroll
    for (int i = 0; i < 4; ++i) {
        v[i].x -= mu; v[i].y -= mu; v[i].z -= mu; v[i].w -= mu;
        var += v[i].x * v[i].x + v[i].y * v[i].y + v[i].z * v[i].z + v[i].w * v[i].w;
    }
    #pragma unroll
    for (int s = 16; s > 0; s >>= 1) var += __shfl_xor_sync(0xffffffffu, var, s);
    float inv = rsqrtf(var * (1.0f / Dc) + EPSc);
    #pragma unroll
    for (int i = 0; i < 4; ++i) {
        int col = lane * 4 + i * 128;
        float4 gv = *reinterpret_cast<const float4*>(&gamma[col]);
        float4 bv = *reinterpret_cast<const float4*>(&beta[col]);
        float4 o;
        o.x = v[i].x * inv * gv.x + bv.x;
        o.y = v[i].y * inv * gv.y + bv.y;
        o.z = v[i].z * inv * gv.z + bv.z;
        o.w = v[i].w * inv * gv.w + bv.w;
        *reinterpret_cast<float4*>(&out[base + col]) = o;
    }
}

// ---------------- host orchestration ----------------
static void launch_gemm(const float* A, const float* BT, const float* bias,
                        const float* resid, float* C, int M, int N, int K, bool relu) {
    dim3 grid(N / 128, M / 128);
    if (relu) gemm_mma<true ><<<grid, 128, GEMM_SMEM>>>(A, BT, bias, resid, C, M, N, K);
    else      gemm_mma<false><<<grid, 128, GEMM_SMEM>>>(A, BT, bias, resid, C, M, N, K);
}

// out-proj epilogue fuses the residual; caller then runs single-input LN.
static void run_mha(const float* xq, const float* xkv, bool same,
                    const unsigned char* mq, const unsigned char* mk, int causal,
                    const float* wT, const float* b, const float* resid,
                    float* qkvp, float* qsep, float* attnp, float* outp) {
    dim3 gfl(Sc / 128, Bc * NHc);
    if (same) {
        launch_gemm(xq, wT, b, nullptr, qkvp, BSc, 3 * Dc, Dc, false);
        flash_attn<<<gfl, 256, FLASH_SMEM>>>(qkvp, 3 * Dc, qkvp + Dc, qkvp + 2 * Dc, 3 * Dc,
                                             mq, mk, attnp, causal);
    } else {
        launch_gemm(xq,  wT,                   b,      nullptr, qsep, BSc, Dc,     Dc, false);
        launch_gemm(xkv, wT + (size_t)Dc * Dc, b + Dc, nullptr, qkvp, BSc, 2 * Dc, Dc, false);
        flash_attn<<<gfl, 256, FLASH_SMEM>>>(qsep, Dc, qkvp, qkvp + Dc, 2 * Dc,
                                             mq, mk, attnp, causal);
    }
    launch_gemm(attnp, wT + 3 * (size_t)Dc * Dc, b + 3 * Dc, resid, outp, BSc, Dc, Dc, false);
}

extern "C" void kernel_launch(void* const* d_in, const int* in_sizes, int n_in,
                              void* d_out, int out_size) {
    const int*   inputs  = (const int*)d_in[0];
    const int*   outputs = (const int*)d_in[1];
    const float* emi = (const float*)d_in[2];
    const float* emo = (const float*)d_in[3];
    const float* enc_attn_w = (const float*)d_in[4];
    const float* enc_attn_b = (const float*)d_in[5];
    const float* enc_ln     = (const float*)d_in[6];
    const float* enc_ffn_w1 = (const float*)d_in[7];
    const float* enc_ffn_b1 = (const float*)d_in[8];
    const float* enc_ffn_w2 = (const float*)d_in[9];
    const float* enc_ffn_b2 = (const float*)d_in[10];
    const float* dec_self_w  = (const float*)d_in[11];
    const float* dec_self_b  = (const float*)d_in[12];
    const float* dec_cross_w = (const float*)d_in[13];
    const float* dec_cross_b = (const float*)d_in[14];
    const float* dec_ln      = (const float*)d_in[15];
    const float* dec_ffn_w1 = (const float*)d_in[16];
    const float* dec_ffn_b1 = (const float*)d_in[17];
    const float* dec_ffn_w2 = (const float*)d_in[18];
    const float* dec_ffn_b2 = (const float*)d_in[19];

    float *xp, *yp, *qp, *attnp, *tmpp, *hidp;
    float *wta_enc, *wta_self, *wta_cross, *wt_ef1, *wt_ef2, *wt_df1, *wt_df2;
    unsigned char *mxp, *myp;
    cudaGetSymbolAddress((void**)&xp, g_x);
    cudaGetSymbolAddress((void**)&yp, g_y);
    cudaGetSymbolAddress((void**)&qp, g_q);
    cudaGetSymbolAddress((void**)&attnp, g_attn);
    cudaGetSymbolAddress((void**)&tmpp, g_tmp);
    cudaGetSymbolAddress((void**)&hidp, g_hid);
    cudaGetSymbolAddress((void**)&mxp, g_mx);
    cudaGetSymbolAddress((void**)&myp, g_my);
    cudaGetSymbolAddress((void**)&wta_enc,   g_wt_enc_attn);
    cudaGetSymbolAddress((void**)&wta_self,  g_wt_dec_self);
    cudaGetSymbolAddress((void**)&wta_cross, g_wt_dec_cross);
    cudaGetSymbolAddress((void**)&wt_ef1, g_wt_enc_f1);
    cudaGetSymbolAddress((void**)&wt_ef2, g_wt_enc_f2);
    cudaGetSymbolAddress((void**)&wt_df1, g_wt_dec_f1);
    cudaGetSymbolAddress((void**)&wt_df2, g_wt_dec_f2);

    cudaFuncSetAttribute(flash_attn, cudaFuncAttributeMaxDynamicSharedMemorySize, FLASH_SMEM);
    cudaFuncSetAttribute(gemm_mma<false>, cudaFuncAttributeMaxDynamicSharedMemorySize, GEMM_SMEM);
    cudaFuncSetAttribute(gemm_mma<true >, cudaFuncAttributeMaxDynamicSharedMemorySize, GEMM_SMEM);

    // -------- weight transposes (tf32-rounded) --------
    dim3 tblk(32, 8);
    transpose_tf32<<<dim3(Dc / 32, Dc / 32, Lc * 4), tblk>>>(enc_attn_w,  wta_enc,   Dc, Dc);
    transpose_tf32<<<dim3(Dc / 32, Dc / 32, Lc * 4), tblk>>>(dec_self_w,  wta_self,  Dc, Dc);
    transpose_tf32<<<dim3(Dc / 32, Dc / 32, Lc * 4), tblk>>>(dec_cross_w, wta_cross, Dc, Dc);
    transpose_tf32<<<dim3(HIDc / 32, Dc / 32, Lc), tblk>>>(enc_ffn_w1, wt_ef1, Dc, HIDc);
    transpose_tf32<<<dim3(Dc / 32, HIDc / 32, Lc), tblk>>>(enc_ffn_w2, wt_ef2, HIDc, Dc);
    transpose_tf32<<<dim3(HIDc / 32, Dc / 32, Lc), tblk>>>(dec_ffn_w1, wt_df1, Dc, HIDc);
    transpose_tf32<<<dim3(Dc / 32, HIDc / 32, Lc), tblk>>>(dec_ffn_w2, wt_df2, HIDc, Dc);

    dim3 blk(256);
    embed_pe_kernel<<<BSc, blk>>>(inputs,  emi, xp, mxp);
    embed_pe_kernel<<<BSc, blk>>>(outputs, emo, yp, myp);

    int lng = BSc / 8;   // 512 blocks, warp per row

    // ---------------- encoder ----------------
    for (int l = 0; l < Lc; ++l) {
        const float* wT = wta_enc + (size_t)l * 4 * Dc * Dc;
        const float* ab = enc_attn_b + (size_t)l * 4 * Dc;
        run_mha(xp, xp, true, mxp, mxp, 0, wT, ab, xp, hidp, qp, attnp, tmpp);
        const float* ln0 = enc_ln + (((size_t)l * 2 + 0) * 2) * Dc;
        ln_kernel<<<lng, blk>>>(tmpp, ln0, ln0 + Dc, xp);
        launch_gemm(xp, wt_ef1 + (size_t)l * Dc * HIDc, enc_ffn_b1 + (size_t)l * HIDc,
                    nullptr, hidp, BSc, HIDc, Dc, true);
        launch_gemm(hidp, wt_ef2 + (size_t)l * Dc * HIDc, enc_ffn_b2 + (size_t)l * Dc,
                    xp, tmpp, BSc, Dc, HIDc, false);
        const float* ln1 = enc_ln + (((size_t)l * 2 + 1) * 2) * Dc;
        ln_kernel<<<lng, blk>>>(tmpp, ln1, ln1 + Dc, xp);
    }

    // ---------------- decoder ----------------
    float* fout = (float*)d_out;
    for (int l = 0; l < Lc; ++l) {
        const float* swT = wta_self + (size_t)l * 4 * Dc * Dc;
        const float* sb  = dec_self_b + (size_t)l * 4 * Dc;
        run_mha(yp, yp, true, myp, myp, 1, swT, sb, yp, hidp, qp, attnp, tmpp);
        const float* ln0 = dec_ln + (((size_t)l * 3 + 0) * 2) * Dc;
        ln_kernel<<<lng, blk>>>(tmpp, ln0, ln0 + Dc, yp);

        const float* cwT = wta_cross + (size_t)l * 4 * Dc * Dc;
        const float* cb  = dec_cross_b + (size_t)l * 4 * Dc;
        run_mha(yp, xp, false, myp, mxp, 0, cwT, cb, yp, hidp, qp, attnp, tmpp);
        const float* ln1 = dec_ln + (((size_t)l * 3 + 1) * 2) * Dc;
        ln_kernel<<<lng, blk>>>(tmpp, ln1, ln1 + Dc, yp);

        launch_gemm(yp, wt_df1 + (size_t)l * Dc * HIDc, dec_ffn_b1 + (size_t)l * HIDc,
                    nullptr, hidp, BSc, HIDc, Dc, true);
        launch_gemm(hidp, wt_df2 + (size_t)l * Dc * HIDc, dec_ffn_b2 + (size_t)l * Dc,
                    yp, tmpp, BSc, Dc, HIDc, false);
        const float* ln2 = dec_ln + (((size_t)l * 3 + 2) * 2) * Dc;
        float* dst = (l == Lc - 1) ? fout : yp;
        ln_kernel<<<lng, blk>>>(tmpp, ln2, ln2 + Dc, dst);
    }
    (void)in_sizes; (void)n_in; (void)out_size;
}

// round 8
// speedup vs baseline: 1.3480x; 1.3480x over previous
#include <cuda_runtime.h>
#include <cuda_fp16.h>
#include <math.h>
#include <cstdint>

// ---------------- problem constants ----------------
#define Bc   8
#define Sc   512
#define Dc   512
#define NHc  8
#define DHc  64
#define Lc   6
#define HIDc 2048
#define EPSc 1e-5f
#define BSc  (Bc * Sc)          // 4096 tokens
#define SCALEc 0.125f           // 1/sqrt(64)

// ---------------- device scratch ----------------
__device__ float g_x[BSc * Dc];
__device__ float g_y[BSc * Dc];
__device__ float g_q[BSc * Dc];
__device__ float g_attn[BSc * Dc];
__device__ float g_tmp[BSc * Dc];
__device__ float g_hid[BSc * HIDc];      // FFN hidden / fused QKV / fused KV scratch
__device__ unsigned char g_mx[BSc];
__device__ unsigned char g_my[BSc];
// transposed fp16 weights: [N][K]
__device__ __half g_wt_enc_attn[Lc * 4 * Dc * Dc];
__device__ __half g_wt_dec_self[Lc * 4 * Dc * Dc];
__device__ __half g_wt_dec_cross[Lc * 4 * Dc * Dc];
__device__ __half g_wt_enc_f1[Lc * Dc * HIDc];
__device__ __half g_wt_enc_f2[Lc * Dc * HIDc];
__device__ __half g_wt_dec_f1[Lc * Dc * HIDc];
__device__ __half g_wt_dec_f2[Lc * Dc * HIDc];

__device__ __forceinline__ float neg_inf_f() { return __int_as_float(0xff800000u); }

__device__ __forceinline__ uint32_t round_tf32(float v) {
    uint32_t u; asm("cvt.rna.tf32.f32 %0, %1;" : "=r"(u) : "f"(v)); return u;
}
__device__ __forceinline__ uint32_t smem_u32(const void* p) {
    uint32_t a;
    asm("{ .reg .u64 t; cvta.to.shared.u64 t, %1; cvt.u32.u64 %0, t; }" : "=r"(a) : "l"(p));
    return a;
}
__device__ __forceinline__ uint32_t pack_h2(float2 f) {
    __half2 h = __floats2half2_rn(f.x, f.y);
    return *reinterpret_cast<uint32_t*>(&h);
}

// mma.sync m16n8k16 fp16 (fp32 accum) — dense GEMM path
__device__ __forceinline__ void mma_16n8k16_f16(float c[4], const uint32_t a[4], const uint32_t b[2]) {
    asm volatile(
        "mma.sync.aligned.m16n8k16.row.col.f32.f16.f16.f32 "
        "{%0,%1,%2,%3}, {%4,%5,%6,%7}, {%8,%9}, {%0,%1,%2,%3};"
        : "+f"(c[0]), "+f"(c[1]), "+f"(c[2]), "+f"(c[3])
        : "r"(a[0]), "r"(a[1]), "r"(a[2]), "r"(a[3]), "r"(b[0]), "r"(b[1]));
}
// mma.sync m16n8k8 tf32 — flash attention path (unchanged, verified)
__device__ __forceinline__ void mma_16n8k8(float c[4], const uint32_t a[4], const uint32_t b[2]) {
    asm volatile(
        "mma.sync.aligned.m16n8k8.row.col.f32.tf32.tf32.f32 "
        "{%0,%1,%2,%3}, {%4,%5,%6,%7}, {%8,%9}, {%0,%1,%2,%3};"
        : "+f"(c[0]), "+f"(c[1]), "+f"(c[2]), "+f"(c[3])
        : "r"(a[0]), "r"(a[1]), "r"(a[2]), "r"(a[3]), "r"(b[0]), "r"(b[1]));
}

// ---------------- weight transpose (fp32 -> fp16) ----------------
__global__ void transpose_h(const float* __restrict__ in, __half* __restrict__ out,
                            int R, int C) {
    __shared__ float tile[32][33];
    const float* src = in + (size_t)blockIdx.z * R * C;
    __half* dst = out + (size_t)blockIdx.z * R * C;
    int c0 = blockIdx.x * 32, r0 = blockIdx.y * 32;
    int tx = threadIdx.x, ty = threadIdx.y;          // 32 x 8
    #pragma unroll
    for (int i = 0; i < 32; i += 8)
        tile[ty + i][tx] = src[(size_t)(r0 + ty + i) * C + c0 + tx];
    __syncthreads();
    #pragma unroll
    for (int i = 0; i < 32; i += 8)
        dst[(size_t)(c0 + ty + i) * R + r0 + tx] = __float2half_rn(tile[tx][ty + i]);
}

// ---------------- fp16 mma GEMM, 3-stage cp.async ring ----------------
// C[M,N] = A[M,K](fp32) @ BT[N,K](fp16)^T + bias (+ resid).
// 128x128 CTA tile, 8 warps (2M x 4N), warp tile 64x32, K-chunk 32, K=16/mma.
#define APAD 40                          // fp32 words per A row; 40%32==8 -> float2 frag loads conflict-free
#define ABUF (128 * APAD)                // b32 per A tile
#define BPAD 20                          // b32 per B row (16 used, 20%32 -> banks 20g+tg all distinct)
#define BBUF (128 * BPAD)                // b32 per B tile
#define STG_B32 (ABUF + BBUF)            // 7680 b32 = 30720 B
#define STAGES 3
#define GEMM_SMEM (STAGES * STG_B32 * 4) // 92160 B -> 2 CTAs/SM

template<bool RELU>
__global__ void __launch_bounds__(256) gemm_mma(const float* __restrict__ A,
                                                const __half* __restrict__ BT,
                                                const float* __restrict__ bias,
                                                const float* __restrict__ resid,
                                                float* __restrict__ C,
                                                int M, int N, int K) {
    extern __shared__ uint32_t gs[];
    uint32_t sbase = smem_u32(gs);
    int tid = threadIdx.x;
    int lane = tid & 31, wid = tid >> 5;
    int wm = wid & 1;                    // 2 x 64 rows
    int wn = wid >> 1;                   // 4 x 32 cols
    int row0 = blockIdx.y * 128, col0 = blockIdx.x * 128;
    int g = lane >> 2, tg = lane & 3;

    float acc[4][4][4];
    #pragma unroll
    for (int mi = 0; mi < 4; mi++)
        #pragma unroll
        for (int ni = 0; ni < 4; ni++)
            #pragma unroll
            for (int r = 0; r < 4; r++) acc[mi][ni][r] = 0.0f;

    int nch = K >> 5;

    // ---- prefetch helper pattern (A: 4 passes of 16B, B: 2 passes of 16B) ----
    // A: idx = tid + i*256 -> r = idx>>3 (0..127), c8 = idx&7 (x4 fp32)
    // B: idx = tid + i*256 -> n = idx>>2 (0..127), ch = idx&3 (x8 halves)
    {
        uint32_t ab = sbase;
        uint32_t bb = sbase + ABUF * 4;
        #pragma unroll
        for (int i = 0; i < 4; ++i) {
            int idx = tid + i * 256;
            int r = idx >> 3, c8 = idx & 7;
            const float* pa = &A[(size_t)(row0 + r) * K + c8 * 4];
            asm volatile("cp.async.cg.shared.global [%0], [%1], 16;"
                         :: "r"(ab + (uint32_t)(r * APAD + c8 * 4) * 4), "l"(pa));
        }
        #pragma unroll
        for (int i = 0; i < 2; ++i) {
            int idx = tid + i * 256;
            int n = idx >> 2, ch = idx & 3;
            const __half* pb = &BT[(size_t)(col0 + n) * K + ch * 8];
            asm volatile("cp.async.cg.shared.global [%0], [%1], 16;"
                         :: "r"(bb + (uint32_t)(n * BPAD + ch * 4) * 4), "l"(pb));
        }
        asm volatile("cp.async.commit_group;" ::: "memory");
    }

    for (int c = 0; c < nch; ++c) {
        if (c + 1 < nch) {
            int k0 = (c + 1) << 5;
            uint32_t stoff = (uint32_t)(((c + 1) % STAGES) * STG_B32) * 4;
            uint32_t ab = sbase + stoff;
            uint32_t bb = ab + ABUF * 4;
            #pragma unroll
            for (int i = 0; i < 4; ++i) {
                int idx = tid + i * 256;
                int r = idx >> 3, c8 = idx & 7;
                const float* pa = &A[(size_t)(row0 + r) * K + k0 + c8 * 4];
                asm volatile("cp.async.cg.shared.global [%0], [%1], 16;"
                             :: "r"(ab + (uint32_t)(r * APAD + c8 * 4) * 4), "l"(pa));
            }
            #pragma unroll
            for (int i = 0; i < 2; ++i) {
                int idx = tid + i * 256;
                int n = idx >> 2, ch = idx & 3;
                const __half* pb = &BT[(size_t)(col0 + n) * K + k0 + ch * 8];
                asm volatile("cp.async.cg.shared.global [%0], [%1], 16;"
                             :: "r"(bb + (uint32_t)(n * BPAD + ch * 4) * 4), "l"(pb));
            }
        }
        asm volatile("cp.async.commit_group;" ::: "memory");
        asm volatile("cp.async.wait_group 1;" ::: "memory");
        __syncthreads();

        const uint32_t* St = gs + (c % STAGES) * STG_B32;
        const float2* As2 = reinterpret_cast<const float2*>(St);   // A as float2 (2 k's)
        const uint32_t* Bs = St + ABUF;                            // B as half2 words

        #pragma unroll
        for (int ki = 0; ki < 2; ++ki) {                // K=16 per mma
            int kh = ki * 8;                            // float2 / half2-word offset
            uint32_t afr[4][4];
            #pragma unroll
            for (int mi = 0; mi < 4; mi++) {
                int r = wm * 64 + mi * 16 + g;
                // a0=(r,kb+2tg) a1=(r+8,kb+2tg) a2=(r,kb+8+2tg) a3=(r+8,kb+8+2tg)
                afr[mi][0] = pack_h2(As2[(r)     * (APAD / 2) + kh + tg]);
                afr[mi][1] = pack_h2(As2[(r + 8) * (APAD / 2) + kh + tg]);
                afr[mi][2] = pack_h2(As2[(r)     * (APAD / 2) + kh + tg + 4]);
                afr[mi][3] = pack_h2(As2[(r + 8) * (APAD / 2) + kh + tg + 4]);
            }
            uint32_t bfr[4][2];
            #pragma unroll
            for (int ni = 0; ni < 4; ni++) {
                int n = wn * 32 + ni * 8 + g;
                bfr[ni][0] = Bs[n * BPAD + kh + tg];      // halves kb+2tg, kb+2tg+1
                bfr[ni][1] = Bs[n * BPAD + kh + tg + 4];  // halves kb+8+2tg, +1
            }
            #pragma unroll
            for (int mi = 0; mi < 4; mi++)
                #pragma unroll
                for (int ni = 0; ni < 4; ni++)
                    mma_16n8k16_f16(acc[mi][ni], afr[mi], bfr[ni]);
        }
        // no trailing barrier (3-stage ring; next iteration's barrier orders reuse)
    }

    #pragma unroll
    for (int mi = 0; mi < 4; mi++) {
        int r0r = row0 + wm * 64 + mi * 16 + g;
        #pragma unroll
        for (int ni = 0; ni < 4; ni++) {
            int cb = col0 + wn * 32 + ni * 8 + tg * 2;
            float b0 = bias[cb], b1 = bias[cb + 1];
            float v0 = acc[mi][ni][0] + b0, v1 = acc[mi][ni][1] + b1;
            float v2 = acc[mi][ni][2] + b0, v3 = acc[mi][ni][3] + b1;
            if (resid) {
                float2 r0v = *reinterpret_cast<const float2*>(&resid[(size_t)(r0r)     * N + cb]);
                float2 r1v = *reinterpret_cast<const float2*>(&resid[(size_t)(r0r + 8) * N + cb]);
                v0 += r0v.x; v1 += r0v.y; v2 += r1v.x; v3 += r1v.y;
            }
            if (RELU) { v0 = fmaxf(v0, 0.f); v1 = fmaxf(v1, 0.f);
                        v2 = fmaxf(v2, 0.f); v3 = fmaxf(v3, 0.f); }
            *reinterpret_cast<float2*>(&C[(size_t)(r0r)     * N + cb]) = make_float2(v0, v1);
            *reinterpret_cast<float2*>(&C[(size_t)(r0r + 8) * N + cb]) = make_float2(v2, v3);
        }
    }
}

// ---------------- fused flash attention (tf32 mma), strided q/k/v ----------------
#define FPAD 68
#define FLASH_SMEM ((128 + 64 + 64 + 128) * FPAD * 4 + 64)

__global__ void __launch_bounds__(256) flash_attn(
    const float* __restrict__ q, int ldq,
    const float* __restrict__ k, const float* __restrict__ v, int ldkv,
    const unsigned char* __restrict__ mqg, const unsigned char* __restrict__ mkg,
    float* __restrict__ o, int causal)
{
    extern __shared__ char sm[];
    uint32_t* Qs = reinterpret_cast<uint32_t*>(sm);
    uint32_t* Ks = Qs + 128 * FPAD;
    uint32_t* Vt = Ks + 64 * FPAD;
    uint32_t* Ps = Vt + 64 * FPAD;
    unsigned char* mks = reinterpret_cast<unsigned char*>(Ps + 128 * FPAD);

    int tid = threadIdx.x, lane = tid & 31, wid = tid >> 5;
    int bh = blockIdx.y, b = bh >> 3, h = bh & 7;
    int q0 = blockIdx.x * 128;
    const float* Qg = q + (size_t)b * Sc * ldq + h * DHc;
    const float* Kg = k + (size_t)b * Sc * ldkv + h * DHc;
    const float* Vg = v + (size_t)b * Sc * ldkv + h * DHc;
    int g = lane >> 2, tg = lane & 3;
    int rg = wid * 16 + g;
    int qi0 = q0 + rg, qi1 = qi0 + 8;

    #pragma unroll
    for (int i = 0; i < 8; ++i) {
        int idx = tid + i * 256;
        int r = idx >> 4, c = (idx & 15) * 4;
        float4 va = *reinterpret_cast<const float4*>(&Qg[(size_t)(q0 + r) * ldq + c]);
        Qs[r * FPAD + c + 0] = round_tf32(va.x);
        Qs[r * FPAD + c + 1] = round_tf32(va.y);
        Qs[r * FPAD + c + 2] = round_tf32(va.z);
        Qs[r * FPAD + c + 3] = round_tf32(va.w);
    }
    bool mrow0 = mqg[b * Sc + qi0] != 0;
    bool mrow1 = mqg[b * Sc + qi1] != 0;

    float m0 = -1e30f, m1 = -1e30f, l0 = 0.f, l1 = 0.f;
    float oacc[8][4];
    #pragma unroll
    for (int ni = 0; ni < 8; ni++) { oacc[ni][0] = oacc[ni][1] = oacc[ni][2] = oacc[ni][3] = 0.f; }

    int nkt = causal ? ((q0 >> 6) + 2) : (Sc / 64);
    for (int kt = 0; kt < nkt; ++kt) {
        int k0 = kt * 64;
        __syncthreads();
        #pragma unroll
        for (int i = 0; i < 4; ++i) {
            int idx = tid + i * 256;
            int r = idx >> 4, c = (idx & 15) * 4;
            float4 vk = *reinterpret_cast<const float4*>(&Kg[(size_t)(k0 + r) * ldkv + c]);
            Ks[r * FPAD + c + 0] = round_tf32(vk.x);
            Ks[r * FPAD + c + 1] = round_tf32(vk.y);
            Ks[r * FPAD + c + 2] = round_tf32(vk.z);
            Ks[r * FPAD + c + 3] = round_tf32(vk.w);
            float4 vv = *reinterpret_cast<const float4*>(&Vg[(size_t)(k0 + r) * ldkv + c]);
            Vt[(c + 0) * FPAD + r] = round_tf32(vv.x);
            Vt[(c + 1) * FPAD + r] = round_tf32(vv.y);
            Vt[(c + 2) * FPAD + r] = round_tf32(vv.z);
            Vt[(c + 3) * FPAD + r] = round_tf32(vv.w);
        }
        if (tid < 64) mks[tid] = mkg[b * Sc + k0 + tid];
        __syncthreads();

        float s[8][4];
        #pragma unroll
        for (int ni = 0; ni < 8; ni++) { s[ni][0] = s[ni][1] = s[ni][2] = s[ni][3] = 0.f; }
        #pragma unroll
        for (int ki = 0; ki < 8; ++ki) {
            int ak = ki * 8 + tg;
            uint32_t a[4] = { Qs[rg * FPAD + ak],       Qs[(rg + 8) * FPAD + ak],
                              Qs[rg * FPAD + ak + 4],   Qs[(rg + 8) * FPAD + ak + 4] };
            #pragma unroll
            for (int ni = 0; ni < 8; ni++) {
                uint32_t bfr[2] = { Ks[(ni * 8 + g) * FPAD + ak],
                                    Ks[(ni * 8 + g) * FPAD + ak + 4] };
                mma_16n8k8(s[ni], a, bfr);
            }
        }

        float rmax0 = neg_inf_f(), rmax1 = neg_inf_f();
        #pragma unroll
        for (int ni = 0; ni < 8; ni++) {
            int cloc = ni * 8 + 2 * tg;
            int cg = k0 + cloc;
            bool mkA = mks[cloc] != 0, mkB = mks[cloc + 1] != 0;
            float v0 = (mrow0 || mkA || (causal && cg     > qi0)) ? neg_inf_f() : s[ni][0] * SCALEc;
            float v1 = (mrow0 || mkB || (causal && cg + 1 > qi0)) ? neg_inf_f() : s[ni][1] * SCALEc;
            float v2 = (mrow1 || mkA || (causal && cg     > qi1)) ? neg_inf_f() : s[ni][2] * SCALEc;
            float v3 = (mrow1 || mkB || (causal && cg + 1 > qi1)) ? neg_inf_f() : s[ni][3] * SCALEc;
            s[ni][0] = v0; s[ni][1] = v1; s[ni][2] = v2; s[ni][3] = v3;
            rmax0 = fmaxf(rmax0, fmaxf(v0, v1));
            rmax1 = fmaxf(rmax1, fmaxf(v2, v3));
        }
        rmax0 = fmaxf(rmax0, __shfl_xor_sync(0xffffffffu, rmax0, 1));
        rmax0 = fmaxf(rmax0, __shfl_xor_sync(0xffffffffu, rmax0, 2));
        rmax1 = fmaxf(rmax1, __shfl_xor_sync(0xffffffffu, rmax1, 1));
        rmax1 = fmaxf(rmax1, __shfl_xor_sync(0xffffffffu, rmax1, 2));

        float mn0 = fmaxf(m0, rmax0), mn1 = fmaxf(m1, rmax1);
        float sc0 = __expf(m0 - mn0), sc1 = __expf(m1 - mn1);
        float rs0 = 0.f, rs1 = 0.f;
        #pragma unroll
        for (int ni = 0; ni < 8; ni++) {
            int cloc = ni * 8 + 2 * tg;
            float p0 = __expf(s[ni][0] - mn0), p1 = __expf(s[ni][1] - mn0);
            float p2 = __expf(s[ni][2] - mn1), p3 = __expf(s[ni][3] - mn1);
            rs0 += p0 + p1; rs1 += p2 + p3;
            Ps[rg * FPAD + cloc]           = round_tf32(p0);
            Ps[rg * FPAD + cloc + 1]       = round_tf32(p1);
            Ps[(rg + 8) * FPAD + cloc]     = round_tf32(p2);
            Ps[(rg + 8) * FPAD + cloc + 1] = round_tf32(p3);
        }
        rs0 += __shfl_xor_sync(0xffffffffu, rs0, 1);
        rs0 += __shfl_xor_sync(0xffffffffu, rs0, 2);
        rs1 += __shfl_xor_sync(0xffffffffu, rs1, 1);
        rs1 += __shfl_xor_sync(0xffffffffu, rs1, 2);
        l0 = l0 * sc0 + rs0; l1 = l1 * sc1 + rs1;
        m0 = mn0; m1 = mn1;
        #pragma unroll
        for (int ni = 0; ni < 8; ni++) {
            oacc[ni][0] *= sc0; oacc[ni][1] *= sc0;
            oacc[ni][2] *= sc1; oacc[ni][3] *= sc1;
        }
        __syncwarp();

        #pragma unroll
        for (int ki = 0; ki < 8; ++ki) {
            int ak = ki * 8 + tg;
            uint32_t a[4] = { Ps[rg * FPAD + ak],       Ps[(rg + 8) * FPAD + ak],
                              Ps[rg * FPAD + ak + 4],   Ps[(rg + 8) * FPAD + ak + 4] };
            #pragma unroll
            for (int ni = 0; ni < 8; ni++) {
                uint32_t bfr[2] = { Vt[(ni * 8 + g) * FPAD + ak],
                                    Vt[(ni * 8 + g) * FPAD + ak + 4] };
                mma_16n8k8(oacc[ni], a, bfr);
            }
        }
    }

    float inv0 = (l0 > 0.f) ? 1.f / l0 : 0.f;
    float inv1 = (l1 > 0.f) ? 1.f / l1 : 0.f;
    size_t ob0 = ((size_t)b * Sc + qi0) * Dc + h * DHc;
    size_t ob1 = ((size_t)b * Sc + qi1) * Dc + h * DHc;
    #pragma unroll
    for (int ni = 0; ni < 8; ni++) {
        int cc = ni * 8 + 2 * tg;
        *reinterpret_cast<float2*>(&o[ob0 + cc]) = make_float2(oacc[ni][0] * inv0, oacc[ni][1] * inv0);
        *reinterpret_cast<float2*>(&o[ob1 + cc]) = make_float2(oacc[ni][2] * inv1, oacc[ni][3] * inv1);
    }
}

// ---------------- embedding + positional encoding (+ pad mask) ----------------
__global__ void embed_pe_kernel(const int* __restrict__ toks,
                                const float* __restrict__ emb,
                                float* __restrict__ out,
                                unsigned char* __restrict__ mask) {
    int pos = blockIdx.x % Sc;
    int b   = blockIdx.x / Sc;
    int tok = toks[b * Sc + pos];
    int t = threadIdx.x;
    if (t == 0) mask[b * Sc + pos] = (tok == 0) ? 1 : 0;
    const float c = -logf(10000.0f) / (float)Dc;
    size_t base = ((size_t)b * Sc + pos) * Dc;
    #pragma unroll
    for (int d = t; d < Dc; d += 256) {
        int i = d >> 1;
        float freq = __expf((float)(2 * i) * c);
        float ang  = (float)pos * freq;
        float pe   = (d & 1) ? cosf(ang) : sinf(ang);
        out[base + d] = emb[(size_t)tok * Dc + d] + pe;
    }
}

// ---------------- out = LayerNorm(xin) * gamma + beta  (warp per row) ----------------
__global__ void __launch_bounds__(256) ln_kernel(const float* __restrict__ xin,
                                                 const float* __restrict__ gamma,
                                                 const float* __restrict__ beta,
                                                 float* __restrict__ out) {
    int warp = threadIdx.x >> 5, lane = threadIdx.x & 31;
    size_t row = (size_t)blockIdx.x * 8 + warp;
    size_t base = row * Dc;
    float4 v[4];
    float sum = 0.f;
    #pragma unroll
    for (int i = 0; i < 4; ++i) {
        v[i] = *reinterpret_cast<const float4*>(&xin[base + lane * 4 + i * 128]);
        sum += v[i].x + v[i].y + v[i].z + v[i].w;
    }
    #pragma unroll
    for (int s = 16; s > 0; s >>= 1) sum += __shfl_xor_sync(0xffffffffu, sum, s);
    float mu = sum * (1.0f / Dc);
    float var = 0.f;
    #pragma unroll
    for (int i = 0; i < 4; ++i) {
        v[i].x -= mu; v[i].y -= mu; v[i].z -= mu; v[i].w -= mu;
        var += v[i].x * v[i].x + v[i].y * v[i].y + v[i].z * v[i].z + v[i].w * v[i].w;
    }
    #pragma unroll
    for (int s = 16; s > 0; s >>= 1) var += __shfl_xor_sync(0xffffffffu, var, s);
    float inv = rsqrtf(var * (1.0f / Dc) + EPSc);
    #pragma unroll
    for (int i = 0; i < 4; ++i) {
        int col = lane * 4 + i * 128;
        float4 gv = *reinterpret_cast<const float4*>(&gamma[col]);
        float4 bv = *reinterpret_cast<const float4*>(&beta[col]);
        float4 o;
        o.x = v[i].x * inv * gv.x + bv.x;
        o.y = v[i].y * inv * gv.y + bv.y;
        o.z = v[i].z * inv * gv.z + bv.z;
        o.w = v[i].w * inv * gv.w + bv.w;
        *reinterpret_cast<float4*>(&out[base + col]) = o;
    }
}

// ---------------- host orchestration ----------------
static void launch_gemm(const float* A, const __half* BT, const float* bias,
                        const float* resid, float* C, int M, int N, int K, bool relu) {
    dim3 grid(N / 128, M / 128);
    if (relu) gemm_mma<true ><<<grid, 256, GEMM_SMEM>>>(A, BT, bias, resid, C, M, N, K);
    else      gemm_mma<false><<<grid, 256, GEMM_SMEM>>>(A, BT, bias, resid, C, M, N, K);
}

// out-proj epilogue fuses the residual; caller then runs single-input LN.
static void run_mha(const float* xq, const float* xkv, bool same,
                    const unsigned char* mq, const unsigned char* mk, int causal,
                    const __half* wT, const float* b, const float* resid,
                    float* qkvp, float* qsep, float* attnp, float* outp) {
    dim3 gfl(Sc / 128, Bc * NHc);
    if (same) {
        launch_gemm(xq, wT, b, nullptr, qkvp, BSc, 3 * Dc, Dc, false);
        flash_attn<<<gfl, 256, FLASH_SMEM>>>(qkvp, 3 * Dc, qkvp + Dc, qkvp + 2 * Dc, 3 * Dc,
                                             mq, mk, attnp, causal);
    } else {
        launch_gemm(xq,  wT,                   b,      nullptr, qsep, BSc, Dc,     Dc, false);
        launch_gemm(xkv, wT + (size_t)Dc * Dc, b + Dc, nullptr, qkvp, BSc, 2 * Dc, Dc, false);
        flash_attn<<<gfl, 256, FLASH_SMEM>>>(qsep, Dc, qkvp, qkvp + Dc, 2 * Dc,
                                             mq, mk, attnp, causal);
    }
    launch_gemm(attnp, wT + 3 * (size_t)Dc * Dc, b + 3 * Dc, resid, outp, BSc, Dc, Dc, false);
}

extern "C" void kernel_launch(void* const* d_in, const int* in_sizes, int n_in,
                              void* d_out, int out_size) {
    const int*   inputs  = (const int*)d_in[0];
    const int*   outputs = (const int*)d_in[1];
    const float* emi = (const float*)d_in[2];
    const float* emo = (const float*)d_in[3];
    const float* enc_attn_w = (const float*)d_in[4];
    const float* enc_attn_b = (const float*)d_in[5];
    const float* enc_ln     = (const float*)d_in[6];
    const float* enc_ffn_w1 = (const float*)d_in[7];
    const float* enc_ffn_b1 = (const float*)d_in[8];
    const float* enc_ffn_w2 = (const float*)d_in[9];
    const float* enc_ffn_b2 = (const float*)d_in[10];
    const float* dec_self_w  = (const float*)d_in[11];
    const float* dec_self_b  = (const float*)d_in[12];
    const float* dec_cross_w = (const float*)d_in[13];
    const float* dec_cross_b = (const float*)d_in[14];
    const float* dec_ln      = (const float*)d_in[15];
    const float* dec_ffn_w1 = (const float*)d_in[16];
    const float* dec_ffn_b1 = (const float*)d_in[17];
    const float* dec_ffn_w2 = (const float*)d_in[18];
    const float* dec_ffn_b2 = (const float*)d_in[19];

    float *xp, *yp, *qp, *attnp, *tmpp, *hidp;
    __half *wta_enc, *wta_self, *wta_cross, *wt_ef1, *wt_ef2, *wt_df1, *wt_df2;
    unsigned char *mxp, *myp;
    cudaGetSymbolAddress((void**)&xp, g_x);
    cudaGetSymbolAddress((void**)&yp, g_y);
    cudaGetSymbolAddress((void**)&qp, g_q);
    cudaGetSymbolAddress((void**)&attnp, g_attn);
    cudaGetSymbolAddress((void**)&tmpp, g_tmp);
    cudaGetSymbolAddress((void**)&hidp, g_hid);
    cudaGetSymbolAddress((void**)&mxp, g_mx);
    cudaGetSymbolAddress((void**)&myp, g_my);
    cudaGetSymbolAddress((void**)&wta_enc,   g_wt_enc_attn);
    cudaGetSymbolAddress((void**)&wta_self,  g_wt_dec_self);
    cudaGetSymbolAddress((void**)&wta_cross, g_wt_dec_cross);
    cudaGetSymbolAddress((void**)&wt_ef1, g_wt_enc_f1);
    cudaGetSymbolAddress((void**)&wt_ef2, g_wt_enc_f2);
    cudaGetSymbolAddress((void**)&wt_df1, g_wt_dec_f1);
    cudaGetSymbolAddress((void**)&wt_df2, g_wt_dec_f2);

    cudaFuncSetAttribute(flash_attn, cudaFuncAttributeMaxDynamicSharedMemorySize, FLASH_SMEM);
    cudaFuncSetAttribute(gemm_mma<false>, cudaFuncAttributeMaxDynamicSharedMemorySize, GEMM_SMEM);
    cudaFuncSetAttribute(gemm_mma<true >, cudaFuncAttributeMaxDynamicSharedMemorySize, GEMM_SMEM);

    // -------- weight transposes (fp32 -> fp16, [N][K]) --------
    dim3 tblk(32, 8);
    transpose_h<<<dim3(Dc / 32, Dc / 32, Lc * 4), tblk>>>(enc_attn_w,  wta_enc,   Dc, Dc);
    transpose_h<<<dim3(Dc / 32, Dc / 32, Lc * 4), tblk>>>(dec_self_w,  wta_self,  Dc, Dc);
    transpose_h<<<dim3(Dc / 32, Dc / 32, Lc * 4), tblk>>>(dec_cross_w, wta_cross, Dc, Dc);
    transpose_h<<<dim3(HIDc / 32, Dc / 32, Lc), tblk>>>(enc_ffn_w1, wt_ef1, Dc, HIDc);
    transpose_h<<<dim3(Dc / 32, HIDc / 32, Lc), tblk>>>(enc_ffn_w2, wt_ef2, HIDc, Dc);
    transpose_h<<<dim3(HIDc / 32, Dc / 32, Lc), tblk>>>(dec_ffn_w1, wt_df1, Dc, HIDc);
    transpose_h<<<dim3(Dc / 32, HIDc / 32, Lc), tblk>>>(dec_ffn_w2, wt_df2, HIDc, Dc);

    dim3 blk(256);
    embed_pe_kernel<<<BSc, blk>>>(inputs,  emi, xp, mxp);
    embed_pe_kernel<<<BSc, blk>>>(outputs, emo, yp, myp);

    int lng = BSc / 8;   // 512 blocks, warp per row

    // ---------------- encoder ----------------
    for (int l = 0; l < Lc; ++l) {
        const __half* wT = wta_enc + (size_t)l * 4 * Dc * Dc;
        const float* ab = enc_attn_b + (size_t)l * 4 * Dc;
        run_mha(xp, xp, true, mxp, mxp, 0, wT, ab, xp, hidp, qp, attnp, tmpp);
        const float* ln0 = enc_ln + (((size_t)l * 2 + 0) * 2) * Dc;
        ln_kernel<<<lng, blk>>>(tmpp, ln0, ln0 + Dc, xp);
        launch_gemm(xp, wt_ef1 + (size_t)l * Dc * HIDc, enc_ffn_b1 + (size_t)l * HIDc,
                    nullptr, hidp, BSc, HIDc, Dc, true);
        launch_gemm(hidp, wt_ef2 + (size_t)l * Dc * HIDc, enc_ffn_b2 + (size_t)l * Dc,
                    xp, tmpp, BSc, Dc, HIDc, false);
        const float* ln1 = enc_ln + (((size_t)l * 2 + 1) * 2) * Dc;
        ln_kernel<<<lng, blk>>>(tmpp, ln1, ln1 + Dc, xp);
    }

    // ---------------- decoder ----------------
    float* fout = (float*)d_out;
    for (int l = 0; l < Lc; ++l) {
        const __half* swT = wta_self + (size_t)l * 4 * Dc * Dc;
        const float* sb  = dec_self_b + (size_t)l * 4 * Dc;
        run_mha(yp, yp, true, myp, myp, 1, swT, sb, yp, hidp, qp, attnp, tmpp);
        const float* ln0 = dec_ln + (((size_t)l * 3 + 0) * 2) * Dc;
        ln_kernel<<<lng, blk>>>(tmpp, ln0, ln0 + Dc, yp);

        const __half* cwT = wta_cross + (size_t)l * 4 * Dc * Dc;
        const float* cb  = dec_cross_b + (size_t)l * 4 * Dc;
        run_mha(yp, xp, false, myp, mxp, 0, cwT, cb, yp, hidp, qp, attnp, tmpp);
        const float* ln1 = dec_ln + (((size_t)l * 3 + 1) * 2) * Dc;
        ln_kernel<<<lng, blk>>>(tmpp, ln1, ln1 + Dc, yp);

        launch_gemm(yp, wt_df1 + (size_t)l * Dc * HIDc, dec_ffn_b1 + (size_t)l * HIDc,
                    nullptr, hidp, BSc, HIDc, Dc, true);
        launch_gemm(hidp, wt_df2 + (size_t)l * Dc * HIDc, dec_ffn_b2 + (size_t)l * Dc,
                    yp, tmpp, BSc, Dc, HIDc, false);
        const float* ln2 = dec_ln + (((size_t)l * 3 + 2) * 2) * Dc;
        float* dst = (l == Lc - 1) ? fout : yp;
        ln_kernel<<<lng, blk>>>(tmpp, ln2, ln2 + Dc, dst);
    }
    (void)in_sizes; (void)n_in; (void)out_size;
}

// round 9
// speedup vs baseline: 1.4872x; 1.1032x over previous
#include <cuda_runtime.h>
#include <cuda_fp16.h>
#include <math.h>
#include <cstdint>

// ---------------- problem constants ----------------
#define Bc   8
#define Sc   512
#define Dc   512
#define NHc  8
#define DHc  64
#define Lc   6
#define HIDc 2048
#define EPSc 1e-5f
#define BSc  (Bc * Sc)          // 4096 tokens
#define SCALEc 0.125f           // 1/sqrt(64)

// ---------------- device scratch ----------------
__device__ float g_x[BSc * Dc];
__device__ float g_y[BSc * Dc];
__device__ float g_q[BSc * Dc];
__device__ float g_attn[BSc * Dc];
__device__ float g_tmp[BSc * Dc];
__device__ float g_hid[BSc * HIDc];      // FFN hidden / fused QKV / fused KV scratch
__device__ unsigned char g_mx[BSc];
__device__ unsigned char g_my[BSc];
// transposed fp16 weights: [N][K]
__device__ __half g_wt_enc_attn[Lc * 4 * Dc * Dc];
__device__ __half g_wt_dec_self[Lc * 4 * Dc * Dc];
__device__ __half g_wt_dec_cross[Lc * 4 * Dc * Dc];
__device__ __half g_wt_enc_f1[Lc * Dc * HIDc];
__device__ __half g_wt_enc_f2[Lc * Dc * HIDc];
__device__ __half g_wt_dec_f1[Lc * Dc * HIDc];
__device__ __half g_wt_dec_f2[Lc * Dc * HIDc];

__device__ __forceinline__ float neg_inf_f() { return __int_as_float(0xff800000u); }

__device__ __forceinline__ uint32_t smem_u32(const void* p) {
    uint32_t a;
    asm("{ .reg .u64 t; cvta.to.shared.u64 t, %1; cvt.u32.u64 %0, t; }" : "=r"(a) : "l"(p));
    return a;
}
__device__ __forceinline__ uint32_t pack_h2(float2 f) {
    __half2 h = __floats2half2_rn(f.x, f.y);
    return *reinterpret_cast<uint32_t*>(&h);
}

// mma.sync m16n8k16 fp16 (fp32 accum)
__device__ __forceinline__ void mma_16n8k16_f16(float c[4], const uint32_t a[4], const uint32_t b[2]) {
    asm volatile(
        "mma.sync.aligned.m16n8k16.row.col.f32.f16.f16.f32 "
        "{%0,%1,%2,%3}, {%4,%5,%6,%7}, {%8,%9}, {%0,%1,%2,%3};"
        : "+f"(c[0]), "+f"(c[1]), "+f"(c[2]), "+f"(c[3])
        : "r"(a[0]), "r"(a[1]), "r"(a[2]), "r"(a[3]), "r"(b[0]), "r"(b[1]));
}

// ---------------- weight transpose (fp32 -> fp16) ----------------
__global__ void transpose_h(const float* __restrict__ in, __half* __restrict__ out,
                            int R, int C) {
    __shared__ float tile[32][33];
    const float* src = in + (size_t)blockIdx.z * R * C;
    __half* dst = out + (size_t)blockIdx.z * R * C;
    int c0 = blockIdx.x * 32, r0 = blockIdx.y * 32;
    int tx = threadIdx.x, ty = threadIdx.y;          // 32 x 8
    #pragma unroll
    for (int i = 0; i < 32; i += 8)
        tile[ty + i][tx] = src[(size_t)(r0 + ty + i) * C + c0 + tx];
    __syncthreads();
    #pragma unroll
    for (int i = 0; i < 32; i += 8)
        dst[(size_t)(c0 + ty + i) * R + r0 + tx] = __float2half_rn(tile[tx][ty + i]);
}

// ---------------- fp16 mma GEMM, 3-stage cp.async ring ----------------
// C[M,N] = A[M,K](fp32) @ BT[N,K](fp16)^T + bias (+ resid).
// 128x128 CTA tile, 8 warps (2M x 4N), warp tile 64x32, K-chunk 32, K=16/mma.
#define APAD 40                          // fp32 words per A row
#define ABUF (128 * APAD)
#define BPAD 20                          // b32 per B row
#define BBUF (128 * BPAD)
#define STG_B32 (ABUF + BBUF)            // 7680 b32 = 30720 B
#define STAGES 3
#define GEMM_SMEM (STAGES * STG_B32 * 4) // 92160 B -> 2 CTAs/SM

template<bool RELU>
__global__ void __launch_bounds__(256) gemm_mma(const float* __restrict__ A,
                                                const __half* __restrict__ BT,
                                                const float* __restrict__ bias,
                                                const float* __restrict__ resid,
                                                float* __restrict__ C,
                                                int M, int N, int K) {
    extern __shared__ uint32_t gs[];
    uint32_t sbase = smem_u32(gs);
    int tid = threadIdx.x;
    int lane = tid & 31, wid = tid >> 5;
    int wm = wid & 1;
    int wn = wid >> 1;
    int row0 = blockIdx.y * 128, col0 = blockIdx.x * 128;
    int g = lane >> 2, tg = lane & 3;

    float acc[4][4][4];
    #pragma unroll
    for (int mi = 0; mi < 4; mi++)
        #pragma unroll
        for (int ni = 0; ni < 4; ni++)
            #pragma unroll
            for (int r = 0; r < 4; r++) acc[mi][ni][r] = 0.0f;

    int nch = K >> 5;

    {
        uint32_t ab = sbase;
        uint32_t bb = sbase + ABUF * 4;
        #pragma unroll
        for (int i = 0; i < 4; ++i) {
            int idx = tid + i * 256;
            int r = idx >> 3, c8 = idx & 7;
            const float* pa = &A[(size_t)(row0 + r) * K + c8 * 4];
            asm volatile("cp.async.cg.shared.global [%0], [%1], 16;"
                         :: "r"(ab + (uint32_t)(r * APAD + c8 * 4) * 4), "l"(pa));
        }
        #pragma unroll
        for (int i = 0; i < 2; ++i) {
            int idx = tid + i * 256;
            int n = idx >> 2, ch = idx & 3;
            const __half* pb = &BT[(size_t)(col0 + n) * K + ch * 8];
            asm volatile("cp.async.cg.shared.global [%0], [%1], 16;"
                         :: "r"(bb + (uint32_t)(n * BPAD + ch * 4) * 4), "l"(pb));
        }
        asm volatile("cp.async.commit_group;" ::: "memory");
    }

    for (int c = 0; c < nch; ++c) {
        if (c + 1 < nch) {
            int k0 = (c + 1) << 5;
            uint32_t stoff = (uint32_t)(((c + 1) % STAGES) * STG_B32) * 4;
            uint32_t ab = sbase + stoff;
            uint32_t bb = ab + ABUF * 4;
            #pragma unroll
            for (int i = 0; i < 4; ++i) {
                int idx = tid + i * 256;
                int r = idx >> 3, c8 = idx & 7;
                const float* pa = &A[(size_t)(row0 + r) * K + k0 + c8 * 4];
                asm volatile("cp.async.cg.shared.global [%0], [%1], 16;"
                             :: "r"(ab + (uint32_t)(r * APAD + c8 * 4) * 4), "l"(pa));
            }
            #pragma unroll
            for (int i = 0; i < 2; ++i) {
                int idx = tid + i * 256;
                int n = idx >> 2, ch = idx & 3;
                const __half* pb = &BT[(size_t)(col0 + n) * K + k0 + ch * 8];
                asm volatile("cp.async.cg.shared.global [%0], [%1], 16;"
                             :: "r"(bb + (uint32_t)(n * BPAD + ch * 4) * 4), "l"(pb));
            }
        }
        asm volatile("cp.async.commit_group;" ::: "memory");
        asm volatile("cp.async.wait_group 1;" ::: "memory");
        __syncthreads();

        const uint32_t* St = gs + (c % STAGES) * STG_B32;
        const float2* As2 = reinterpret_cast<const float2*>(St);
        const uint32_t* Bs = St + ABUF;

        #pragma unroll
        for (int ki = 0; ki < 2; ++ki) {
            int kh = ki * 8;
            uint32_t afr[4][4];
            #pragma unroll
            for (int mi = 0; mi < 4; mi++) {
                int r = wm * 64 + mi * 16 + g;
                afr[mi][0] = pack_h2(As2[(r)     * (APAD / 2) + kh + tg]);
                afr[mi][1] = pack_h2(As2[(r + 8) * (APAD / 2) + kh + tg]);
                afr[mi][2] = pack_h2(As2[(r)     * (APAD / 2) + kh + tg + 4]);
                afr[mi][3] = pack_h2(As2[(r + 8) * (APAD / 2) + kh + tg + 4]);
            }
            uint32_t bfr[4][2];
            #pragma unroll
            for (int ni = 0; ni < 4; ni++) {
                int n = wn * 32 + ni * 8 + g;
                bfr[ni][0] = Bs[n * BPAD + kh + tg];
                bfr[ni][1] = Bs[n * BPAD + kh + tg + 4];
            }
            #pragma unroll
            for (int mi = 0; mi < 4; mi++)
                #pragma unroll
                for (int ni = 0; ni < 4; ni++)
                    mma_16n8k16_f16(acc[mi][ni], afr[mi], bfr[ni]);
        }
    }

    #pragma unroll
    for (int mi = 0; mi < 4; mi++) {
        int r0r = row0 + wm * 64 + mi * 16 + g;
        #pragma unroll
        for (int ni = 0; ni < 4; ni++) {
            int cb = col0 + wn * 32 + ni * 8 + tg * 2;
            float b0 = bias[cb], b1 = bias[cb + 1];
            float v0 = acc[mi][ni][0] + b0, v1 = acc[mi][ni][1] + b1;
            float v2 = acc[mi][ni][2] + b0, v3 = acc[mi][ni][3] + b1;
            if (resid) {
                float2 r0v = *reinterpret_cast<const float2*>(&resid[(size_t)(r0r)     * N + cb]);
                float2 r1v = *reinterpret_cast<const float2*>(&resid[(size_t)(r0r + 8) * N + cb]);
                v0 += r0v.x; v1 += r0v.y; v2 += r1v.x; v3 += r1v.y;
            }
            if (RELU) { v0 = fmaxf(v0, 0.f); v1 = fmaxf(v1, 0.f);
                        v2 = fmaxf(v2, 0.f); v3 = fmaxf(v3, 0.f); }
            *reinterpret_cast<float2*>(&C[(size_t)(r0r)     * N + cb]) = make_float2(v0, v1);
            *reinterpret_cast<float2*>(&C[(size_t)(r0r + 8) * N + cb]) = make_float2(v2, v3);
        }
    }
}

// ---------------- fused flash attention (fp16 mma m16n8k16) ----------------
// Word layout: 36 b32 (=72 halves) per row; banks (4g+tg) conflict-free.
#define FW 36
#define FLASH_SMEM ((128 + 64 + 64 + 128) * FW * 4 + 64)

__global__ void __launch_bounds__(256) flash_attn(
    const float* __restrict__ q, int ldq,
    const float* __restrict__ k, const float* __restrict__ v, int ldkv,
    const unsigned char* __restrict__ mqg, const unsigned char* __restrict__ mkg,
    float* __restrict__ o, int causal)
{
    extern __shared__ char sm[];
    uint32_t* Qs = reinterpret_cast<uint32_t*>(sm);        // [128][FW] half2 words
    uint32_t* Ks = Qs + 128 * FW;                          // [64][FW]
    uint32_t* Vt = Ks + 64 * FW;                           // [64 dh][FW] (keys packed)
    uint32_t* Ps = Vt + 64 * FW;                           // [128][FW]
    __half* Vth = reinterpret_cast<__half*>(Vt);           // [64][72] halves
    unsigned char* mks = reinterpret_cast<unsigned char*>(Ps + 128 * FW);

    int tid = threadIdx.x, lane = tid & 31, wid = tid >> 5;
    int bh = blockIdx.y, b = bh >> 3, h = bh & 7;
    int q0 = blockIdx.x * 128;
    const float* Qg = q + (size_t)b * Sc * ldq + h * DHc;
    const float* Kg = k + (size_t)b * Sc * ldkv + h * DHc;
    const float* Vg = v + (size_t)b * Sc * ldkv + h * DHc;
    int g = lane >> 2, tg = lane & 3;
    int rg = wid * 16 + g;
    int qi0 = q0 + rg, qi1 = qi0 + 8;

    // load Q tile [128 x 64] -> fp16 half2 words
    #pragma unroll
    for (int i = 0; i < 8; ++i) {
        int idx = tid + i * 256;
        int r = idx >> 4, c = (idx & 15) * 4;
        float4 va = *reinterpret_cast<const float4*>(&Qg[(size_t)(q0 + r) * ldq + c]);
        uint2 w = make_uint2(pack_h2(make_float2(va.x, va.y)),
                             pack_h2(make_float2(va.z, va.w)));
        *reinterpret_cast<uint2*>(&Qs[r * FW + (c >> 1)]) = w;
    }
    bool mrow0 = mqg[b * Sc + qi0] != 0;
    bool mrow1 = mqg[b * Sc + qi1] != 0;

    float m0 = -1e30f, m1 = -1e30f, l0 = 0.f, l1 = 0.f;
    float oacc[8][4];
    #pragma unroll
    for (int ni = 0; ni < 8; ni++) { oacc[ni][0] = oacc[ni][1] = oacc[ni][2] = oacc[ni][3] = 0.f; }

    int nkt = causal ? ((q0 >> 6) + 2) : (Sc / 64);
    for (int kt = 0; kt < nkt; ++kt) {
        int k0 = kt * 64;
        __syncthreads();
        #pragma unroll
        for (int i = 0; i < 4; ++i) {
            int idx = tid + i * 256;
            int r = idx >> 4, c = (idx & 15) * 4;
            float4 vk = *reinterpret_cast<const float4*>(&Kg[(size_t)(k0 + r) * ldkv + c]);
            uint2 w = make_uint2(pack_h2(make_float2(vk.x, vk.y)),
                                 pack_h2(make_float2(vk.z, vk.w)));
            *reinterpret_cast<uint2*>(&Ks[r * FW + (c >> 1)]) = w;
            float4 vv = *reinterpret_cast<const float4*>(&Vg[(size_t)(k0 + r) * ldkv + c]);
            Vth[(c + 0) * (2 * FW) + r] = __float2half_rn(vv.x);   // transposed: [dh][key]
            Vth[(c + 1) * (2 * FW) + r] = __float2half_rn(vv.y);
            Vth[(c + 2) * (2 * FW) + r] = __float2half_rn(vv.z);
            Vth[(c + 3) * (2 * FW) + r] = __float2half_rn(vv.w);
        }
        if (tid < 64) mks[tid] = mkg[b * Sc + k0 + tid];
        __syncthreads();

        // ---- S = Q @ K^T  (K=64, 4 mma k-steps of 16) ----
        float s[8][4];
        #pragma unroll
        for (int ni = 0; ni < 8; ni++) { s[ni][0] = s[ni][1] = s[ni][2] = s[ni][3] = 0.f; }
        #pragma unroll
        for (int ki = 0; ki < 4; ++ki) {
            int kh = ki * 8;
            uint32_t a[4] = { Qs[rg * FW + kh + tg],       Qs[(rg + 8) * FW + kh + tg],
                              Qs[rg * FW + kh + tg + 4],   Qs[(rg + 8) * FW + kh + tg + 4] };
            #pragma unroll
            for (int ni = 0; ni < 8; ni++) {
                int n = ni * 8 + g;
                uint32_t bfr[2] = { Ks[n * FW + kh + tg], Ks[n * FW + kh + tg + 4] };
                mma_16n8k16_f16(s[ni], a, bfr);
            }
        }

        // ---- scale + mask ----
        float rmax0 = neg_inf_f(), rmax1 = neg_inf_f();
        #pragma unroll
        for (int ni = 0; ni < 8; ni++) {
            int cloc = ni * 8 + 2 * tg;
            int cg = k0 + cloc;
            bool mkA = mks[cloc] != 0, mkB = mks[cloc + 1] != 0;
            float v0 = (mrow0 || mkA || (causal && cg     > qi0)) ? neg_inf_f() : s[ni][0] * SCALEc;
            float v1 = (mrow0 || mkB || (causal && cg + 1 > qi0)) ? neg_inf_f() : s[ni][1] * SCALEc;
            float v2 = (mrow1 || mkA || (causal && cg     > qi1)) ? neg_inf_f() : s[ni][2] * SCALEc;
            float v3 = (mrow1 || mkB || (causal && cg + 1 > qi1)) ? neg_inf_f() : s[ni][3] * SCALEc;
            s[ni][0] = v0; s[ni][1] = v1; s[ni][2] = v2; s[ni][3] = v3;
            rmax0 = fmaxf(rmax0, fmaxf(v0, v1));
            rmax1 = fmaxf(rmax1, fmaxf(v2, v3));
        }
        rmax0 = fmaxf(rmax0, __shfl_xor_sync(0xffffffffu, rmax0, 1));
        rmax0 = fmaxf(rmax0, __shfl_xor_sync(0xffffffffu, rmax0, 2));
        rmax1 = fmaxf(rmax1, __shfl_xor_sync(0xffffffffu, rmax1, 1));
        rmax1 = fmaxf(rmax1, __shfl_xor_sync(0xffffffffu, rmax1, 2));

        float mn0 = fmaxf(m0, rmax0), mn1 = fmaxf(m1, rmax1);
        float sc0 = __expf(m0 - mn0), sc1 = __expf(m1 - mn1);
        float rs0 = 0.f, rs1 = 0.f;
        #pragma unroll
        for (int ni = 0; ni < 8; ni++) {
            float p0 = __expf(s[ni][0] - mn0), p1 = __expf(s[ni][1] - mn0);
            float p2 = __expf(s[ni][2] - mn1), p3 = __expf(s[ni][3] - mn1);
            rs0 += p0 + p1; rs1 += p2 + p3;
            Ps[rg * FW + ni * 4 + tg]       = pack_h2(make_float2(p0, p1));
            Ps[(rg + 8) * FW + ni * 4 + tg] = pack_h2(make_float2(p2, p3));
        }
        rs0 += __shfl_xor_sync(0xffffffffu, rs0, 1);
        rs0 += __shfl_xor_sync(0xffffffffu, rs0, 2);
        rs1 += __shfl_xor_sync(0xffffffffu, rs1, 1);
        rs1 += __shfl_xor_sync(0xffffffffu, rs1, 2);
        l0 = l0 * sc0 + rs0; l1 = l1 * sc1 + rs1;
        m0 = mn0; m1 = mn1;
        #pragma unroll
        for (int ni = 0; ni < 8; ni++) {
            oacc[ni][0] *= sc0; oacc[ni][1] *= sc0;
            oacc[ni][2] *= sc1; oacc[ni][3] *= sc1;
        }
        __syncwarp();    // Ps rows are warp-exclusive

        // ---- O += P @ V  (K=64 keys, 4 mma k-steps) ----
        #pragma unroll
        for (int ki = 0; ki < 4; ++ki) {
            int kh = ki * 8;
            uint32_t a[4] = { Ps[rg * FW + kh + tg],       Ps[(rg + 8) * FW + kh + tg],
                              Ps[rg * FW + kh + tg + 4],   Ps[(rg + 8) * FW + kh + tg + 4] };
            #pragma unroll
            for (int ni = 0; ni < 8; ni++) {
                int n = ni * 8 + g;                        // dh index
                uint32_t bfr[2] = { Vt[n * FW + kh + tg], Vt[n * FW + kh + tg + 4] };
                mma_16n8k16_f16(oacc[ni], a, bfr);
            }
        }
    }

    float inv0 = (l0 > 0.f) ? 1.f / l0 : 0.f;
    float inv1 = (l1 > 0.f) ? 1.f / l1 : 0.f;
    size_t ob0 = ((size_t)b * Sc + qi0) * Dc + h * DHc;
    size_t ob1 = ((size_t)b * Sc + qi1) * Dc + h * DHc;
    #pragma unroll
    for (int ni = 0; ni < 8; ni++) {
        int cc = ni * 8 + 2 * tg;
        *reinterpret_cast<float2*>(&o[ob0 + cc]) = make_float2(oacc[ni][0] * inv0, oacc[ni][1] * inv0);
        *reinterpret_cast<float2*>(&o[ob1 + cc]) = make_float2(oacc[ni][2] * inv1, oacc[ni][3] * inv1);
    }
}

// ---------------- embedding + positional encoding (+ pad mask) ----------------
__global__ void embed_pe_kernel(const int* __restrict__ toks,
                                const float* __restrict__ emb,
                                float* __restrict__ out,
                                unsigned char* __restrict__ mask) {
    int pos = blockIdx.x % Sc;
    int b   = blockIdx.x / Sc;
    int tok = toks[b * Sc + pos];
    int t = threadIdx.x;
    if (t == 0) mask[b * Sc + pos] = (tok == 0) ? 1 : 0;
    const float c = -logf(10000.0f) / (float)Dc;
    size_t base = ((size_t)b * Sc + pos) * Dc;
    #pragma unroll
    for (int d = t; d < Dc; d += 256) {
        int i = d >> 1;
        float freq = __expf((float)(2 * i) * c);
        float ang  = (float)pos * freq;
        float pe   = (d & 1) ? cosf(ang) : sinf(ang);
        out[base + d] = emb[(size_t)tok * Dc + d] + pe;
    }
}

// ---------------- out = LayerNorm(xin) * gamma + beta  (warp per row) ----------------
__global__ void __launch_bounds__(256) ln_kernel(const float* __restrict__ xin,
                                                 const float* __restrict__ gamma,
                                                 const float* __restrict__ beta,
                                                 float* __restrict__ out) {
    int warp = threadIdx.x >> 5, lane = threadIdx.x & 31;
    size_t row = (size_t)blockIdx.x * 8 + warp;
    size_t base = row * Dc;
    float4 v[4];
    float sum = 0.f;
    #pragma unroll
    for (int i = 0; i < 4; ++i) {
        v[i] = *reinterpret_cast<const float4*>(&xin[base + lane * 4 + i * 128]);
        sum += v[i].x + v[i].y + v[i].z + v[i].w;
    }
    #pragma unroll
    for (int s = 16; s > 0; s >>= 1) sum += __shfl_xor_sync(0xffffffffu, sum, s);
    float mu = sum * (1.0f / Dc);
    float var = 0.f;
    #pragma unroll
    for (int i = 0; i < 4; ++i) {
        v[i].x -= mu; v[i].y -= mu; v[i].z -= mu; v[i].w -= mu;
        var += v[i].x * v[i].x + v[i].y * v[i].y + v[i].z * v[i].z + v[i].w * v[i].w;
    }
    #pragma unroll
    for (int s = 16; s > 0; s >>= 1) var += __shfl_xor_sync(0xffffffffu, var, s);
    float inv = rsqrtf(var * (1.0f / Dc) + EPSc);
    #pragma unroll
    for (int i = 0; i < 4; ++i) {
        int col = lane * 4 + i * 128;
        float4 gv = *reinterpret_cast<const float4*>(&gamma[col]);
        float4 bv = *reinterpret_cast<const float4*>(&beta[col]);
        float4 o;
        o.x = v[i].x * inv * gv.x + bv.x;
        o.y = v[i].y * inv * gv.y + bv.y;
        o.z = v[i].z * inv * gv.z + bv.z;
        o.w = v[i].w * inv * gv.w + bv.w;
        *reinterpret_cast<float4*>(&out[base + col]) = o;
    }
}

// ---------------- host orchestration ----------------
static void launch_gemm(const float* A, const __half* BT, const float* bias,
                        const float* resid, float* C, int M, int N, int K, bool relu) {
    dim3 grid(N / 128, M / 128);
    if (relu) gemm_mma<true ><<<grid, 256, GEMM_SMEM>>>(A, BT, bias, resid, C, M, N, K);
    else      gemm_mma<false><<<grid, 256, GEMM_SMEM>>>(A, BT, bias, resid, C, M, N, K);
}

static void run_mha(const float* xq, const float* xkv, bool same,
                    const unsigned char* mq, const unsigned char* mk, int causal,
                    const __half* wT, const float* b, const float* resid,
                    float* qkvp, float* qsep, float* attnp, float* outp) {
    dim3 gfl(Sc / 128, Bc * NHc);
    if (same) {
        launch_gemm(xq, wT, b, nullptr, qkvp, BSc, 3 * Dc, Dc, false);
        flash_attn<<<gfl, 256, FLASH_SMEM>>>(qkvp, 3 * Dc, qkvp + Dc, qkvp + 2 * Dc, 3 * Dc,
                                             mq, mk, attnp, causal);
    } else {
        launch_gemm(xq,  wT,                   b,      nullptr, qsep, BSc, Dc,     Dc, false);
        launch_gemm(xkv, wT + (size_t)Dc * Dc, b + Dc, nullptr, qkvp, BSc, 2 * Dc, Dc, false);
        flash_attn<<<gfl, 256, FLASH_SMEM>>>(qsep, Dc, qkvp, qkvp + Dc, 2 * Dc,
                                             mq, mk, attnp, causal);
    }
    launch_gemm(attnp, wT + 3 * (size_t)Dc * Dc, b + 3 * Dc, resid, outp, BSc, Dc, Dc, false);
}

extern "C" void kernel_launch(void* const* d_in, const int* in_sizes, int n_in,
                              void* d_out, int out_size) {
    const int*   inputs  = (const int*)d_in[0];
    const int*   outputs = (const int*)d_in[1];
    const float* emi = (const float*)d_in[2];
    const float* emo = (const float*)d_in[3];
    const float* enc_attn_w = (const float*)d_in[4];
    const float* enc_attn_b = (const float*)d_in[5];
    const float* enc_ln     = (const float*)d_in[6];
    const float* enc_ffn_w1 = (const float*)d_in[7];
    const float* enc_ffn_b1 = (const float*)d_in[8];
    const float* enc_ffn_w2 = (const float*)d_in[9];
    const float* enc_ffn_b2 = (const float*)d_in[10];
    const float* dec_self_w  = (const float*)d_in[11];
    const float* dec_self_b  = (const float*)d_in[12];
    const float* dec_cross_w = (const float*)d_in[13];
    const float* dec_cross_b = (const float*)d_in[14];
    const float* dec_ln      = (const float*)d_in[15];
    const float* dec_ffn_w1 = (const float*)d_in[16];
    const float* dec_ffn_b1 = (const float*)d_in[17];
    const float* dec_ffn_w2 = (const float*)d_in[18];
    const float* dec_ffn_b2 = (const float*)d_in[19];

    float *xp, *yp, *qp, *attnp, *tmpp, *hidp;
    __half *wta_enc, *wta_self, *wta_cross, *wt_ef1, *wt_ef2, *wt_df1, *wt_df2;
    unsigned char *mxp, *myp;
    cudaGetSymbolAddress((void**)&xp, g_x);
    cudaGetSymbolAddress((void**)&yp, g_y);
    cudaGetSymbolAddress((void**)&qp, g_q);
    cudaGetSymbolAddress((void**)&attnp, g_attn);
    cudaGetSymbolAddress((void**)&tmpp, g_tmp);
    cudaGetSymbolAddress((void**)&hidp, g_hid);
    cudaGetSymbolAddress((void**)&mxp, g_mx);
    cudaGetSymbolAddress((void**)&myp, g_my);
    cudaGetSymbolAddress((void**)&wta_enc,   g_wt_enc_attn);
    cudaGetSymbolAddress((void**)&wta_self,  g_wt_dec_self);
    cudaGetSymbolAddress((void**)&wta_cross, g_wt_dec_cross);
    cudaGetSymbolAddress((void**)&wt_ef1, g_wt_enc_f1);
    cudaGetSymbolAddress((void**)&wt_ef2, g_wt_enc_f2);
    cudaGetSymbolAddress((void**)&wt_df1, g_wt_dec_f1);
    cudaGetSymbolAddress((void**)&wt_df2, g_wt_dec_f2);

    cudaFuncSetAttribute(flash_attn, cudaFuncAttributeMaxDynamicSharedMemorySize, FLASH_SMEM);
    cudaFuncSetAttribute(gemm_mma<false>, cudaFuncAttributeMaxDynamicSharedMemorySize, GEMM_SMEM);
    cudaFuncSetAttribute(gemm_mma<true >, cudaFuncAttributeMaxDynamicSharedMemorySize, GEMM_SMEM);

    // -------- weight transposes (fp32 -> fp16, [N][K]) --------
    dim3 tblk(32, 8);
    transpose_h<<<dim3(Dc / 32, Dc / 32, Lc * 4), tblk>>>(enc_attn_w,  wta_enc,   Dc, Dc);
    transpose_h<<<dim3(Dc / 32, Dc / 32, Lc * 4), tblk>>>(dec_self_w,  wta_self,  Dc, Dc);
    transpose_h<<<dim3(Dc / 32, Dc / 32, Lc * 4), tblk>>>(dec_cross_w, wta_cross, Dc, Dc);
    transpose_h<<<dim3(HIDc / 32, Dc / 32, Lc), tblk>>>(enc_ffn_w1, wt_ef1, Dc, HIDc);
    transpose_h<<<dim3(Dc / 32, HIDc / 32, Lc), tblk>>>(enc_ffn_w2, wt_ef2, HIDc, Dc);
    transpose_h<<<dim3(HIDc / 32, Dc / 32, Lc), tblk>>>(dec_ffn_w1, wt_df1, Dc, HIDc);
    transpose_h<<<dim3(Dc / 32, HIDc / 32, Lc), tblk>>>(dec_ffn_w2, wt_df2, HIDc, Dc);

    dim3 blk(256);
    embed_pe_kernel<<<BSc, blk>>>(inputs,  emi, xp, mxp);
    embed_pe_kernel<<<BSc, blk>>>(outputs, emo, yp, myp);

    int lng = BSc / 8;   // 512 blocks, warp per row

    // ---------------- encoder ----------------
    for (int l = 0; l < Lc; ++l) {
        const __half* wT = wta_enc + (size_t)l * 4 * Dc * Dc;
        const float* ab = enc_attn_b + (size_t)l * 4 * Dc;
        run_mha(xp, xp, true, mxp, mxp, 0, wT, ab, xp, hidp, qp, attnp, tmpp);
        const float* ln0 = enc_ln + (((size_t)l * 2 + 0) * 2) * Dc;
        ln_kernel<<<lng, blk>>>(tmpp, ln0, ln0 + Dc, xp);
        launch_gemm(xp, wt_ef1 + (size_t)l * Dc * HIDc, enc_ffn_b1 + (size_t)l * HIDc,
                    nullptr, hidp, BSc, HIDc, Dc, true);
        launch_gemm(hidp, wt_ef2 + (size_t)l * Dc * HIDc, enc_ffn_b2 + (size_t)l * Dc,
                    xp, tmpp, BSc, Dc, HIDc, false);
        const float* ln1 = enc_ln + (((size_t)l * 2 + 1) * 2) * Dc;
        ln_kernel<<<lng, blk>>>(tmpp, ln1, ln1 + Dc, xp);
    }

    // ---------------- decoder ----------------
    float* fout = (float*)d_out;
    for (int l = 0; l < Lc; ++l) {
        const __half* swT = wta_self + (size_t)l * 4 * Dc * Dc;
        const float* sb  = dec_self_b + (size_t)l * 4 * Dc;
        run_mha(yp, yp, true, myp, myp, 1, swT, sb, yp, hidp, qp, attnp, tmpp);
        const float* ln0 = dec_ln + (((size_t)l * 3 + 0) * 2) * Dc;
        ln_kernel<<<lng, blk>>>(tmpp, ln0, ln0 + Dc, yp);

        const __half* cwT = wta_cross + (size_t)l * 4 * Dc * Dc;
        const float* cb  = dec_cross_b + (size_t)l * 4 * Dc;
        run_mha(yp, xp, false, myp, mxp, 0, cwT, cb, yp, hidp, qp, attnp, tmpp);
        const float* ln1 = dec_ln + (((size_t)l * 3 + 1) * 2) * Dc;
        ln_kernel<<<lng, blk>>>(tmpp, ln1, ln1 + Dc, yp);

        launch_gemm(yp, wt_df1 + (size_t)l * Dc * HIDc, dec_ffn_b1 + (size_t)l * HIDc,
                    nullptr, hidp, BSc, HIDc, Dc, true);
        launch_gemm(hidp, wt_df2 + (size_t)l * Dc * HIDc, dec_ffn_b2 + (size_t)l * Dc,
                    yp, tmpp, BSc, Dc, HIDc, false);
        const float* ln2 = dec_ln + (((size_t)l * 3 + 2) * 2) * Dc;
        float* dst = (l == Lc - 1) ? fout : yp;
        ln_kernel<<<lng, blk>>>(tmpp, ln2, ln2 + Dc, dst);
    }
    (void)in_sizes; (void)n_in; (void)out_size;
}

// round 10
// speedup vs baseline: 1.5596x; 1.0487x over previous
#include <cuda_runtime.h>
#include <cuda_fp16.h>
#include <math.h>
#include <cstdint>

// ---------------- problem constants ----------------
#define Bc   8
#define Sc   512
#define Dc   512
#define NHc  8
#define DHc  64
#define Lc   6
#define HIDc 2048
#define EPSc 1e-5f
#define BSc  (Bc * Sc)          // 4096 tokens
#define SCALEc 0.125f           // 1/sqrt(64)

// ---------------- device scratch ----------------
__device__ float  g_x[BSc * Dc];          // fp32 residual stream (encoder)
__device__ float  g_y[BSc * Dc];          // fp32 residual stream (decoder)
__device__ float  g_tmp[BSc * Dc];        // fp32 GEMM output pre-LN
__device__ __half g_xh[BSc * Dc];         // fp16 activation copies
__device__ __half g_yh[BSc * Dc];
__device__ __half g_qkvh[BSc * 3 * Dc];
__device__ __half g_qh[BSc * Dc];
__device__ __half g_attnh[BSc * Dc];
__device__ __half g_hidh[BSc * HIDc];
__device__ unsigned char g_mx[BSc];
__device__ unsigned char g_my[BSc];
// transposed fp16 weights: [N][K]
__device__ __half g_wt_enc_attn[Lc * 4 * Dc * Dc];
__device__ __half g_wt_dec_self[Lc * 4 * Dc * Dc];
__device__ __half g_wt_dec_cross[Lc * 4 * Dc * Dc];
__device__ __half g_wt_enc_f1[Lc * Dc * HIDc];
__device__ __half g_wt_enc_f2[Lc * Dc * HIDc];
__device__ __half g_wt_dec_f1[Lc * Dc * HIDc];
__device__ __half g_wt_dec_f2[Lc * Dc * HIDc];

__device__ __forceinline__ float neg_inf_f() { return __int_as_float(0xff800000u); }

__device__ __forceinline__ uint32_t smem_u32(const void* p) {
    uint32_t a;
    asm("{ .reg .u64 t; cvta.to.shared.u64 t, %1; cvt.u32.u64 %0, t; }" : "=r"(a) : "l"(p));
    return a;
}
__device__ __forceinline__ uint32_t pack_h2(float2 f) {
    __half2 h = __floats2half2_rn(f.x, f.y);
    return *reinterpret_cast<uint32_t*>(&h);
}

// mma.sync m16n8k16 fp16 (fp32 accum)
__device__ __forceinline__ void mma_16n8k16_f16(float c[4], const uint32_t a[4], const uint32_t b[2]) {
    asm volatile(
        "mma.sync.aligned.m16n8k16.row.col.f32.f16.f16.f32 "
        "{%0,%1,%2,%3}, {%4,%5,%6,%7}, {%8,%9}, {%0,%1,%2,%3};"
        : "+f"(c[0]), "+f"(c[1]), "+f"(c[2]), "+f"(c[3])
        : "r"(a[0]), "r"(a[1]), "r"(a[2]), "r"(a[3]), "r"(b[0]), "r"(b[1]));
}

// ---------------- weight transpose (fp32 -> fp16) ----------------
__global__ void transpose_h(const float* __restrict__ in, __half* __restrict__ out,
                            int R, int C) {
    __shared__ float tile[32][33];
    const float* src = in + (size_t)blockIdx.z * R * C;
    __half* dst = out + (size_t)blockIdx.z * R * C;
    int c0 = blockIdx.x * 32, r0 = blockIdx.y * 32;
    int tx = threadIdx.x, ty = threadIdx.y;          // 32 x 8
    #pragma unroll
    for (int i = 0; i < 32; i += 8)
        tile[ty + i][tx] = src[(size_t)(r0 + ty + i) * C + c0 + tx];
    __syncthreads();
    #pragma unroll
    for (int i = 0; i < 32; i += 8)
        dst[(size_t)(c0 + ty + i) * R + r0 + tx] = __float2half_rn(tile[tx][ty + i]);
}

// ---------------- fp16 mma GEMM (fp16 A and B), 3-stage cp.async ring ----------------
// C[M,N] = A[M,K] @ BT[N,K]^T + bias (+ resid). Output fp32 or fp16.
// 128x128 CTA tile, 8 warps (2M x 4N), warp tile 64x32, K-chunk 32, K=16/mma.
#define PAD20 20                         // b32 words per 32-half row (16 used)
#define TBUF (128 * PAD20)               // words per operand tile
#define STG_B32 (2 * TBUF)               // 5120 words = 20480 B / stage
#define STAGES 3
#define GEMM_SMEM (STAGES * STG_B32 * 4) // 61440 B

template<bool RELU, bool HALFOUT>
__global__ void __launch_bounds__(256) gemm_mma(const __half* __restrict__ A,
                                                const __half* __restrict__ BT,
                                                const float* __restrict__ bias,
                                                const float* __restrict__ resid,
                                                void* __restrict__ Cout,
                                                int M, int N, int K) {
    extern __shared__ uint32_t gs[];
    uint32_t sbase = smem_u32(gs);
    int tid = threadIdx.x;
    int lane = tid & 31, wid = tid >> 5;
    int wm = wid & 1;
    int wn = wid >> 1;
    int row0 = blockIdx.y * 128, col0 = blockIdx.x * 128;
    int g = lane >> 2, tg = lane & 3;

    float acc[4][4][4];
    #pragma unroll
    for (int mi = 0; mi < 4; mi++)
        #pragma unroll
        for (int ni = 0; ni < 4; ni++)
            #pragma unroll
            for (int r = 0; r < 4; r++) acc[mi][ni][r] = 0.0f;

    int nch = K >> 5;

    // prefetch chunk 0 into stage 0 (A and B tiles identical geometry: 128 rows x 32 halves)
    {
        uint32_t ab = sbase;
        uint32_t bb = sbase + TBUF * 4;
        #pragma unroll
        for (int i = 0; i < 2; ++i) {
            int idx = tid + i * 256;
            int n = idx >> 2, ch = idx & 3;
            const __half* pa = &A[(size_t)(row0 + n) * K + ch * 8];
            asm volatile("cp.async.cg.shared.global [%0], [%1], 16;"
                         :: "r"(ab + (uint32_t)(n * PAD20 + ch * 4) * 4), "l"(pa));
            const __half* pb = &BT[(size_t)(col0 + n) * K + ch * 8];
            asm volatile("cp.async.cg.shared.global [%0], [%1], 16;"
                         :: "r"(bb + (uint32_t)(n * PAD20 + ch * 4) * 4), "l"(pb));
        }
        asm volatile("cp.async.commit_group;" ::: "memory");
    }

    for (int c = 0; c < nch; ++c) {
        if (c + 1 < nch) {
            int k0 = (c + 1) << 5;
            uint32_t stoff = (uint32_t)(((c + 1) % STAGES) * STG_B32) * 4;
            uint32_t ab = sbase + stoff;
            uint32_t bb = ab + TBUF * 4;
            #pragma unroll
            for (int i = 0; i < 2; ++i) {
                int idx = tid + i * 256;
                int n = idx >> 2, ch = idx & 3;
                const __half* pa = &A[(size_t)(row0 + n) * K + k0 + ch * 8];
                asm volatile("cp.async.cg.shared.global [%0], [%1], 16;"
                             :: "r"(ab + (uint32_t)(n * PAD20 + ch * 4) * 4), "l"(pa));
                const __half* pb = &BT[(size_t)(col0 + n) * K + k0 + ch * 8];
                asm volatile("cp.async.cg.shared.global [%0], [%1], 16;"
                             :: "r"(bb + (uint32_t)(n * PAD20 + ch * 4) * 4), "l"(pb));
            }
        }
        asm volatile("cp.async.commit_group;" ::: "memory");
        asm volatile("cp.async.wait_group 1;" ::: "memory");
        __syncthreads();

        const uint32_t* As = gs + (c % STAGES) * STG_B32;
        const uint32_t* Bs = As + TBUF;

        #pragma unroll
        for (int ki = 0; ki < 2; ++ki) {
            int kh = ki * 8;
            uint32_t afr[4][4];
            #pragma unroll
            for (int mi = 0; mi < 4; mi++) {
                int r = wm * 64 + mi * 16 + g;
                afr[mi][0] = As[(r)     * PAD20 + kh + tg];
                afr[mi][1] = As[(r + 8) * PAD20 + kh + tg];
                afr[mi][2] = As[(r)     * PAD20 + kh + tg + 4];
                afr[mi][3] = As[(r + 8) * PAD20 + kh + tg + 4];
            }
            uint32_t bfr[4][2];
            #pragma unroll
            for (int ni = 0; ni < 4; ni++) {
                int n = wn * 32 + ni * 8 + g;
                bfr[ni][0] = Bs[n * PAD20 + kh + tg];
                bfr[ni][1] = Bs[n * PAD20 + kh + tg + 4];
            }
            #pragma unroll
            for (int mi = 0; mi < 4; mi++)
                #pragma unroll
                for (int ni = 0; ni < 4; ni++)
                    mma_16n8k16_f16(acc[mi][ni], afr[mi], bfr[ni]);
        }
    }

    #pragma unroll
    for (int mi = 0; mi < 4; mi++) {
        int r0r = row0 + wm * 64 + mi * 16 + g;
        #pragma unroll
        for (int ni = 0; ni < 4; ni++) {
            int cb = col0 + wn * 32 + ni * 8 + tg * 2;
            float b0 = bias[cb], b1 = bias[cb + 1];
            float v0 = acc[mi][ni][0] + b0, v1 = acc[mi][ni][1] + b1;
            float v2 = acc[mi][ni][2] + b0, v3 = acc[mi][ni][3] + b1;
            if (resid) {
                float2 r0v = *reinterpret_cast<const float2*>(&resid[(size_t)(r0r)     * N + cb]);
                float2 r1v = *reinterpret_cast<const float2*>(&resid[(size_t)(r0r + 8) * N + cb]);
                v0 += r0v.x; v1 += r0v.y; v2 += r1v.x; v3 += r1v.y;
            }
            if (RELU) { v0 = fmaxf(v0, 0.f); v1 = fmaxf(v1, 0.f);
                        v2 = fmaxf(v2, 0.f); v3 = fmaxf(v3, 0.f); }
            if (HALFOUT) {
                __half* Ch = (__half*)Cout;
                *reinterpret_cast<uint32_t*>(&Ch[(size_t)(r0r)     * N + cb]) = pack_h2(make_float2(v0, v1));
                *reinterpret_cast<uint32_t*>(&Ch[(size_t)(r0r + 8) * N + cb]) = pack_h2(make_float2(v2, v3));
            } else {
                float* Cf = (float*)Cout;
                *reinterpret_cast<float2*>(&Cf[(size_t)(r0r)     * N + cb]) = make_float2(v0, v1);
                *reinterpret_cast<float2*>(&Cf[(size_t)(r0r + 8) * N + cb]) = make_float2(v2, v3);
            }
        }
    }
}

// ---------------- fused flash attention (fp16 in / fp16 out, m16n8k16) ----------------
#define FW 36
#define FLASH_SMEM ((128 + 64 + 64 + 128) * FW * 4 + 64)

__global__ void __launch_bounds__(256) flash_attn(
    const __half* __restrict__ q, int ldq,
    const __half* __restrict__ k, const __half* __restrict__ v, int ldkv,
    const unsigned char* __restrict__ mqg, const unsigned char* __restrict__ mkg,
    __half* __restrict__ o, int causal)
{
    extern __shared__ char sm[];
    uint32_t* Qs = reinterpret_cast<uint32_t*>(sm);        // [128][FW] half2 words
    uint32_t* Ks = Qs + 128 * FW;                          // [64][FW]
    uint32_t* Vt = Ks + 64 * FW;                           // [64 dh][FW]
    uint32_t* Ps = Vt + 64 * FW;                           // [128][FW]
    __half* Vth = reinterpret_cast<__half*>(Vt);           // [64][72] halves
    unsigned char* mks = reinterpret_cast<unsigned char*>(Ps + 128 * FW);

    int tid = threadIdx.x, lane = tid & 31, wid = tid >> 5;
    int bh = blockIdx.y, b = bh >> 3, h = bh & 7;
    int q0 = blockIdx.x * 128;
    const __half* Qg = q + (size_t)b * Sc * ldq + h * DHc;
    const __half* Kg = k + (size_t)b * Sc * ldkv + h * DHc;
    const __half* Vg = v + (size_t)b * Sc * ldkv + h * DHc;
    int g = lane >> 2, tg = lane & 3;
    int rg = wid * 16 + g;
    int qi0 = q0 + rg, qi1 = qi0 + 8;

    // load Q tile [128 x 64] fp16 direct (8 halves = 16B per op)
    #pragma unroll
    for (int i = 0; i < 4; ++i) {
        int idx = tid + i * 256;
        int r = idx >> 3, c8 = idx & 7;
        uint4 w = *reinterpret_cast<const uint4*>(&Qg[(size_t)(q0 + r) * ldq + c8 * 8]);
        *reinterpret_cast<uint4*>(&Qs[r * FW + c8 * 4]) = w;
    }
    bool mrow0 = mqg[b * Sc + qi0] != 0;
    bool mrow1 = mqg[b * Sc + qi1] != 0;

    float m0 = -1e30f, m1 = -1e30f, l0 = 0.f, l1 = 0.f;
    float oacc[8][4];
    #pragma unroll
    for (int ni = 0; ni < 8; ni++) { oacc[ni][0] = oacc[ni][1] = oacc[ni][2] = oacc[ni][3] = 0.f; }

    int nkt = causal ? ((q0 >> 6) + 2) : (Sc / 64);
    for (int kt = 0; kt < nkt; ++kt) {
        int k0 = kt * 64;
        __syncthreads();
        #pragma unroll
        for (int i = 0; i < 2; ++i) {
            int idx = tid + i * 256;
            int r = idx >> 3, c8 = idx & 7;
            uint4 wk = *reinterpret_cast<const uint4*>(&Kg[(size_t)(k0 + r) * ldkv + c8 * 8]);
            *reinterpret_cast<uint4*>(&Ks[r * FW + c8 * 4]) = wk;
            uint4 wv = *reinterpret_cast<const uint4*>(&Vg[(size_t)(k0 + r) * ldkv + c8 * 8]);
            const __half* hv = reinterpret_cast<const __half*>(&wv);
            int c = c8 * 8;
            #pragma unroll
            for (int j = 0; j < 8; ++j)
                Vth[(c + j) * (2 * FW) + r] = hv[j];       // transposed: [dh][key]
        }
        if (tid < 64) mks[tid] = mkg[b * Sc + k0 + tid];
        __syncthreads();

        // ---- S = Q @ K^T ----
        float s[8][4];
        #pragma unroll
        for (int ni = 0; ni < 8; ni++) { s[ni][0] = s[ni][1] = s[ni][2] = s[ni][3] = 0.f; }
        #pragma unroll
        for (int ki = 0; ki < 4; ++ki) {
            int kh = ki * 8;
            uint32_t a[4] = { Qs[rg * FW + kh + tg],       Qs[(rg + 8) * FW + kh + tg],
                              Qs[rg * FW + kh + tg + 4],   Qs[(rg + 8) * FW + kh + tg + 4] };
            #pragma unroll
            for (int ni = 0; ni < 8; ni++) {
                int n = ni * 8 + g;
                uint32_t bfr[2] = { Ks[n * FW + kh + tg], Ks[n * FW + kh + tg + 4] };
                mma_16n8k16_f16(s[ni], a, bfr);
            }
        }

        // ---- scale + mask + online softmax ----
        float rmax0 = neg_inf_f(), rmax1 = neg_inf_f();
        #pragma unroll
        for (int ni = 0; ni < 8; ni++) {
            int cloc = ni * 8 + 2 * tg;
            int cg = k0 + cloc;
            bool mkA = mks[cloc] != 0, mkB = mks[cloc + 1] != 0;
            float v0 = (mrow0 || mkA || (causal && cg     > qi0)) ? neg_inf_f() : s[ni][0] * SCALEc;
            float v1 = (mrow0 || mkB || (causal && cg + 1 > qi0)) ? neg_inf_f() : s[ni][1] * SCALEc;
            float v2 = (mrow1 || mkA || (causal && cg     > qi1)) ? neg_inf_f() : s[ni][2] * SCALEc;
            float v3 = (mrow1 || mkB || (causal && cg + 1 > qi1)) ? neg_inf_f() : s[ni][3] * SCALEc;
            s[ni][0] = v0; s[ni][1] = v1; s[ni][2] = v2; s[ni][3] = v3;
            rmax0 = fmaxf(rmax0, fmaxf(v0, v1));
            rmax1 = fmaxf(rmax1, fmaxf(v2, v3));
        }
        rmax0 = fmaxf(rmax0, __shfl_xor_sync(0xffffffffu, rmax0, 1));
        rmax0 = fmaxf(rmax0, __shfl_xor_sync(0xffffffffu, rmax0, 2));
        rmax1 = fmaxf(rmax1, __shfl_xor_sync(0xffffffffu, rmax1, 1));
        rmax1 = fmaxf(rmax1, __shfl_xor_sync(0xffffffffu, rmax1, 2));

        float mn0 = fmaxf(m0, rmax0), mn1 = fmaxf(m1, rmax1);
        float sc0 = __expf(m0 - mn0), sc1 = __expf(m1 - mn1);
        float rs0 = 0.f, rs1 = 0.f;
        #pragma unroll
        for (int ni = 0; ni < 8; ni++) {
            float p0 = __expf(s[ni][0] - mn0), p1 = __expf(s[ni][1] - mn0);
            float p2 = __expf(s[ni][2] - mn1), p3 = __expf(s[ni][3] - mn1);
            rs0 += p0 + p1; rs1 += p2 + p3;
            Ps[rg * FW + ni * 4 + tg]       = pack_h2(make_float2(p0, p1));
            Ps[(rg + 8) * FW + ni * 4 + tg] = pack_h2(make_float2(p2, p3));
        }
        rs0 += __shfl_xor_sync(0xffffffffu, rs0, 1);
        rs0 += __shfl_xor_sync(0xffffffffu, rs0, 2);
        rs1 += __shfl_xor_sync(0xffffffffu, rs1, 1);
        rs1 += __shfl_xor_sync(0xffffffffu, rs1, 2);
        l0 = l0 * sc0 + rs0; l1 = l1 * sc1 + rs1;
        m0 = mn0; m1 = mn1;
        #pragma unroll
        for (int ni = 0; ni < 8; ni++) {
            oacc[ni][0] *= sc0; oacc[ni][1] *= sc0;
            oacc[ni][2] *= sc1; oacc[ni][3] *= sc1;
        }
        __syncwarp();    // Ps rows are warp-exclusive

        // ---- O += P @ V ----
        #pragma unroll
        for (int ki = 0; ki < 4; ++ki) {
            int kh = ki * 8;
            uint32_t a[4] = { Ps[rg * FW + kh + tg],       Ps[(rg + 8) * FW + kh + tg],
                              Ps[rg * FW + kh + tg + 4],   Ps[(rg + 8) * FW + kh + tg + 4] };
            #pragma unroll
            for (int ni = 0; ni < 8; ni++) {
                int n = ni * 8 + g;
                uint32_t bfr[2] = { Vt[n * FW + kh + tg], Vt[n * FW + kh + tg + 4] };
                mma_16n8k16_f16(oacc[ni], a, bfr);
            }
        }
    }

    float inv0 = (l0 > 0.f) ? 1.f / l0 : 0.f;
    float inv1 = (l1 > 0.f) ? 1.f / l1 : 0.f;
    size_t ob0 = ((size_t)b * Sc + qi0) * Dc + h * DHc;
    size_t ob1 = ((size_t)b * Sc + qi1) * Dc + h * DHc;
    #pragma unroll
    for (int ni = 0; ni < 8; ni++) {
        int cc = ni * 8 + 2 * tg;
        *reinterpret_cast<uint32_t*>(&o[ob0 + cc]) =
            pack_h2(make_float2(oacc[ni][0] * inv0, oacc[ni][1] * inv0));
        *reinterpret_cast<uint32_t*>(&o[ob1 + cc]) =
            pack_h2(make_float2(oacc[ni][2] * inv1, oacc[ni][3] * inv1));
    }
}

// ---------------- embedding + PE (+ pad mask), dual fp32/fp16 output ----------------
__global__ void embed_pe_kernel(const int* __restrict__ toks,
                                const float* __restrict__ emb,
                                float* __restrict__ out,
                                __half* __restrict__ outh,
                                unsigned char* __restrict__ mask) {
    int pos = blockIdx.x % Sc;
    int b   = blockIdx.x / Sc;
    int tok = toks[b * Sc + pos];
    int t = threadIdx.x;
    if (t == 0) mask[b * Sc + pos] = (tok == 0) ? 1 : 0;
    const float c = -logf(10000.0f) / (float)Dc;
    size_t base = ((size_t)b * Sc + pos) * Dc;
    #pragma unroll
    for (int d = t; d < Dc; d += 256) {
        int i = d >> 1;
        float freq = __expf((float)(2 * i) * c);
        float ang  = (float)pos * freq;
        float pe   = (d & 1) ? cosf(ang) : sinf(ang);
        float v = emb[(size_t)tok * Dc + d] + pe;
        out[base + d] = v;
        outh[base + d] = __float2half_rn(v);
    }
}

// ---------------- LayerNorm: dual fp32 + fp16 output (warp per row) ----------------
__global__ void __launch_bounds__(256) ln_kernel(const float* __restrict__ xin,
                                                 const float* __restrict__ gamma,
                                                 const float* __restrict__ beta,
                                                 float* __restrict__ out,
                                                 __half* __restrict__ outh) {
    int warp = threadIdx.x >> 5, lane = threadIdx.x & 31;
    size_t row = (size_t)blockIdx.x * 8 + warp;
    size_t base = row * Dc;
    float4 v[4];
    float sum = 0.f;
    #pragma unroll
    for (int i = 0; i < 4; ++i) {
        v[i] = *reinterpret_cast<const float4*>(&xin[base + lane * 4 + i * 128]);
        sum += v[i].x + v[i].y + v[i].z + v[i].w;
    }
    #pragma unroll
    for (int s = 16; s > 0; s >>= 1) sum += __shfl_xor_sync(0xffffffffu, sum, s);
    float mu = sum * (1.0f / Dc);
    float var = 0.f;
    #pragma unroll
    for (int i = 0; i < 4; ++i) {
        v[i].x -= mu; v[i].y -= mu; v[i].z -= mu; v[i].w -= mu;
        var += v[i].x * v[i].x + v[i].y * v[i].y + v[i].z * v[i].z + v[i].w * v[i].w;
    }
    #pragma unroll
    for (int s = 16; s > 0; s >>= 1) var += __shfl_xor_sync(0xffffffffu, var, s);
    float inv = rsqrtf(var * (1.0f / Dc) + EPSc);
    #pragma unroll
    for (int i = 0; i < 4; ++i) {
        int col = lane * 4 + i * 128;
        float4 gv = *reinterpret_cast<const float4*>(&gamma[col]);
        float4 bv = *reinterpret_cast<const float4*>(&beta[col]);
        float4 o;
        o.x = v[i].x * inv * gv.x + bv.x;
        o.y = v[i].y * inv * gv.y + bv.y;
        o.z = v[i].z * inv * gv.z + bv.z;
        o.w = v[i].w * inv * gv.w + bv.w;
        *reinterpret_cast<float4*>(&out[base + col]) = o;
        uint2 hw = make_uint2(pack_h2(make_float2(o.x, o.y)),
                              pack_h2(make_float2(o.z, o.w)));
        *reinterpret_cast<uint2*>(&outh[base + col]) = hw;
    }
}

// ---------------- host orchestration ----------------
static void launch_gemm_f(const __half* A, const __half* BT, const float* bias,
                          const float* resid, float* C, int M, int N, int K) {
    dim3 grid(N / 128, M / 128);
    gemm_mma<false, false><<<grid, 256, GEMM_SMEM>>>(A, BT, bias, resid, C, M, N, K);
}
static void launch_gemm_h(const __half* A, const __half* BT, const float* bias,
                          __half* C, int M, int N, int K, bool relu) {
    dim3 grid(N / 128, M / 128);
    if (relu) gemm_mma<true,  true><<<grid, 256, GEMM_SMEM>>>(A, BT, bias, nullptr, C, M, N, K);
    else      gemm_mma<false, true><<<grid, 256, GEMM_SMEM>>>(A, BT, bias, nullptr, C, M, N, K);
}

static void run_mha(const __half* xqh, const __half* xkvh, bool same,
                    const unsigned char* mq, const unsigned char* mk, int causal,
                    const __half* wT, const float* b, const float* resid,
                    __half* qkvh, __half* qh, __half* attnh, float* outp) {
    dim3 gfl(Sc / 128, Bc * NHc);
    if (same) {
        launch_gemm_h(xqh, wT, b, qkvh, BSc, 3 * Dc, Dc, false);
        flash_attn<<<gfl, 256, FLASH_SMEM>>>(qkvh, 3 * Dc, qkvh + Dc, qkvh + 2 * Dc, 3 * Dc,
                                             mq, mk, attnh, causal);
    } else {
        launch_gemm_h(xqh,  wT,                   b,      qh,   BSc, Dc,     Dc, false);
        launch_gemm_h(xkvh, wT + (size_t)Dc * Dc, b + Dc, qkvh, BSc, 2 * Dc, Dc, false);
        flash_attn<<<gfl, 256, FLASH_SMEM>>>(qh, Dc, qkvh, qkvh + Dc, 2 * Dc,
                                             mq, mk, attnh, causal);
    }
    launch_gemm_f(attnh, wT + 3 * (size_t)Dc * Dc, b + 3 * Dc, resid, outp, BSc, Dc, Dc);
}

extern "C" void kernel_launch(void* const* d_in, const int* in_sizes, int n_in,
                              void* d_out, int out_size) {
    const int*   inputs  = (const int*)d_in[0];
    const int*   outputs = (const int*)d_in[1];
    const float* emi = (const float*)d_in[2];
    const float* emo = (const float*)d_in[3];
    const float* enc_attn_w = (const float*)d_in[4];
    const float* enc_attn_b = (const float*)d_in[5];
    const float* enc_ln     = (const float*)d_in[6];
    const float* enc_ffn_w1 = (const float*)d_in[7];
    const float* enc_ffn_b1 = (const float*)d_in[8];
    const float* enc_ffn_w2 = (const float*)d_in[9];
    const float* enc_ffn_b2 = (const float*)d_in[10];
    const float* dec_self_w  = (const float*)d_in[11];
    const float* dec_self_b  = (const float*)d_in[12];
    const float* dec_cross_w = (const float*)d_in[13];
    const float* dec_cross_b = (const float*)d_in[14];
    const float* dec_ln      = (const float*)d_in[15];
    const float* dec_ffn_w1 = (const float*)d_in[16];
    const float* dec_ffn_b1 = (const float*)d_in[17];
    const float* dec_ffn_w2 = (const float*)d_in[18];
    const float* dec_ffn_b2 = (const float*)d_in[19];

    float *xp, *yp, *tmpp;
    __half *xh, *yh, *qkvh, *qh, *attnh, *hidh;
    __half *wta_enc, *wta_self, *wta_cross, *wt_ef1, *wt_ef2, *wt_df1, *wt_df2;
    unsigned char *mxp, *myp;
    cudaGetSymbolAddress((void**)&xp, g_x);
    cudaGetSymbolAddress((void**)&yp, g_y);
    cudaGetSymbolAddress((void**)&tmpp, g_tmp);
    cudaGetSymbolAddress((void**)&xh, g_xh);
    cudaGetSymbolAddress((void**)&yh, g_yh);
    cudaGetSymbolAddress((void**)&qkvh, g_qkvh);
    cudaGetSymbolAddress((void**)&qh, g_qh);
    cudaGetSymbolAddress((void**)&attnh, g_attnh);
    cudaGetSymbolAddress((void**)&hidh, g_hidh);
    cudaGetSymbolAddress((void**)&mxp, g_mx);
    cudaGetSymbolAddress((void**)&myp, g_my);
    cudaGetSymbolAddress((void**)&wta_enc,   g_wt_enc_attn);
    cudaGetSymbolAddress((void**)&wta_self,  g_wt_dec_self);
    cudaGetSymbolAddress((void**)&wta_cross, g_wt_dec_cross);
    cudaGetSymbolAddress((void**)&wt_ef1, g_wt_enc_f1);
    cudaGetSymbolAddress((void**)&wt_ef2, g_wt_enc_f2);
    cudaGetSymbolAddress((void**)&wt_df1, g_wt_dec_f1);
    cudaGetSymbolAddress((void**)&wt_df2, g_wt_dec_f2);

    cudaFuncSetAttribute(flash_attn, cudaFuncAttributeMaxDynamicSharedMemorySize, FLASH_SMEM);
    cudaFuncSetAttribute(gemm_mma<false, false>, cudaFuncAttributeMaxDynamicSharedMemorySize, GEMM_SMEM);
    cudaFuncSetAttribute(gemm_mma<false, true >, cudaFuncAttributeMaxDynamicSharedMemorySize, GEMM_SMEM);
    cudaFuncSetAttribute(gemm_mma<true,  true >, cudaFuncAttributeMaxDynamicSharedMemorySize, GEMM_SMEM);

    // -------- weight transposes (fp32 -> fp16, [N][K]) --------
    dim3 tblk(32, 8);
    transpose_h<<<dim3(Dc / 32, Dc / 32, Lc * 4), tblk>>>(enc_attn_w,  wta_enc,   Dc, Dc);
    transpose_h<<<dim3(Dc / 32, Dc / 32, Lc * 4), tblk>>>(dec_self_w,  wta_self,  Dc, Dc);
    transpose_h<<<dim3(Dc / 32, Dc / 32, Lc * 4), tblk>>>(dec_cross_w, wta_cross, Dc, Dc);
    transpose_h<<<dim3(HIDc / 32, Dc / 32, Lc), tblk>>>(enc_ffn_w1, wt_ef1, Dc, HIDc);
    transpose_h<<<dim3(Dc / 32, HIDc / 32, Lc), tblk>>>(enc_ffn_w2, wt_ef2, HIDc, Dc);
    transpose_h<<<dim3(HIDc / 32, Dc / 32, Lc), tblk>>>(dec_ffn_w1, wt_df1, Dc, HIDc);
    transpose_h<<<dim3(Dc / 32, HIDc / 32, Lc), tblk>>>(dec_ffn_w2, wt_df2, HIDc, Dc);

    dim3 blk(256);
    embed_pe_kernel<<<BSc, blk>>>(inputs,  emi, xp, xh, mxp);
    embed_pe_kernel<<<BSc, blk>>>(outputs, emo, yp, yh, myp);

    int lng = BSc / 8;   // 512 blocks, warp per row

    // ---------------- encoder ----------------
    for (int l = 0; l < Lc; ++l) {
        const __half* wT = wta_enc + (size_t)l * 4 * Dc * Dc;
        const float* ab = enc_attn_b + (size_t)l * 4 * Dc;
        run_mha(xh, xh, true, mxp, mxp, 0, wT, ab, xp, qkvh, qh, attnh, tmpp);
        const float* ln0 = enc_ln + (((size_t)l * 2 + 0) * 2) * Dc;
        ln_kernel<<<lng, blk>>>(tmpp, ln0, ln0 + Dc, xp, xh);
        launch_gemm_h(xh, wt_ef1 + (size_t)l * Dc * HIDc, enc_ffn_b1 + (size_t)l * HIDc,
                      hidh, BSc, HIDc, Dc, true);
        launch_gemm_f(hidh, wt_ef2 + (size_t)l * Dc * HIDc, enc_ffn_b2 + (size_t)l * Dc,
                      xp, tmpp, BSc, Dc, HIDc);
        const float* ln1 = enc_ln + (((size_t)l * 2 + 1) * 2) * Dc;
        ln_kernel<<<lng, blk>>>(tmpp, ln1, ln1 + Dc, xp, xh);
    }

    // ---------------- decoder ----------------
    float* fout = (float*)d_out;
    for (int l = 0; l < Lc; ++l) {
        const __half* swT = wta_self + (size_t)l * 4 * Dc * Dc;
        const float* sb  = dec_self_b + (size_t)l * 4 * Dc;
        run_mha(yh, yh, true, myp, myp, 1, swT, sb, yp, qkvh, qh, attnh, tmpp);
        const float* ln0 = dec_ln + (((size_t)l * 3 + 0) * 2) * Dc;
        ln_kernel<<<lng, blk>>>(tmpp, ln0, ln0 + Dc, yp, yh);

        const __half* cwT = wta_cross + (size_t)l * 4 * Dc * Dc;
        const float* cb  = dec_cross_b + (size_t)l * 4 * Dc;
        run_mha(yh, xh, false, myp, mxp, 0, cwT, cb, yp, qkvh, qh, attnh, tmpp);
        const float* ln1 = dec_ln + (((size_t)l * 3 + 1) * 2) * Dc;
        ln_kernel<<<lng, blk>>>(tmpp, ln1, ln1 + Dc, yp, yh);

        launch_gemm_h(yh, wt_df1 + (size_t)l * Dc * HIDc, dec_ffn_b1 + (size_t)l * HIDc,
                      hidh, BSc, HIDc, Dc, true);
        launch_gemm_f(hidh, wt_df2 + (size_t)l * Dc * HIDc, dec_ffn_b2 + (size_t)l * Dc,
                      yp, tmpp, BSc, Dc, HIDc);
        const float* ln2 = dec_ln + (((size_t)l * 3 + 2) * 2) * Dc;
        float* dst = (l == Lc - 1) ? fout : yp;
        ln_kernel<<<lng, blk>>>(tmpp, ln2, ln2 + Dc, dst, yh);
    }
    (void)in_sizes; (void)n_in; (void)out_size;
}

// round 11
// speedup vs baseline: 1.7330x; 1.1112x over previous
#include <cuda_runtime.h>
#include <cuda_fp16.h>
#include <math.h>
#include <cstdint>

// ---------------- problem constants ----------------
#define Bc   8
#define Sc   512
#define Dc   512
#define NHc  8
#define DHc  64
#define Lc   6
#define HIDc 2048
#define EPSc 1e-5f
#define BSc  (Bc * Sc)          // 4096 tokens
#define SCALEc 0.125f           // 1/sqrt(64)

// ---------------- device scratch ----------------
__device__ float  g_x[BSc * Dc];          // fp32 residual stream (encoder)
__device__ float  g_y[BSc * Dc];          // fp32 residual stream (decoder)
__device__ float  g_tmp[BSc * Dc];        // fp32 GEMM output pre-LN
__device__ __half g_xh[BSc * Dc];         // fp16 activation copies
__device__ __half g_yh[BSc * Dc];
__device__ __half g_qkvh[BSc * 3 * Dc];
__device__ __half g_qh[BSc * Dc];
__device__ __half g_attnh[BSc * Dc];
__device__ __half g_hidh[BSc * HIDc];
__device__ unsigned char g_mx[BSc];
__device__ unsigned char g_my[BSc];
// transposed fp16 weights: [N][K]
__device__ __half g_wt_enc_attn[Lc * 4 * Dc * Dc];
__device__ __half g_wt_dec_self[Lc * 4 * Dc * Dc];
__device__ __half g_wt_dec_cross[Lc * 4 * Dc * Dc];
__device__ __half g_wt_enc_f1[Lc * Dc * HIDc];
__device__ __half g_wt_enc_f2[Lc * Dc * HIDc];
__device__ __half g_wt_dec_f1[Lc * Dc * HIDc];
__device__ __half g_wt_dec_f2[Lc * Dc * HIDc];

__device__ __forceinline__ float neg_inf_f() { return __int_as_float(0xff800000u); }

__device__ __forceinline__ uint32_t smem_u32(const void* p) {
    uint32_t a;
    asm("{ .reg .u64 t; cvta.to.shared.u64 t, %1; cvt.u32.u64 %0, t; }" : "=r"(a) : "l"(p));
    return a;
}
__device__ __forceinline__ uint32_t pack_h2(float2 f) {
    __half2 h = __floats2half2_rn(f.x, f.y);
    return *reinterpret_cast<uint32_t*>(&h);
}

// mma.sync m16n8k16 fp16 (fp32 accum)
__device__ __forceinline__ void mma_16n8k16_f16(float c[4], const uint32_t a[4], const uint32_t b[2]) {
    asm volatile(
        "mma.sync.aligned.m16n8k16.row.col.f32.f16.f16.f32 "
        "{%0,%1,%2,%3}, {%4,%5,%6,%7}, {%8,%9}, {%0,%1,%2,%3};"
        : "+f"(c[0]), "+f"(c[1]), "+f"(c[2]), "+f"(c[3])
        : "r"(a[0]), "r"(a[1]), "r"(a[2]), "r"(a[3]), "r"(b[0]), "r"(b[1]));
}
// ldmatrix x4 (non-transposed / transposed)
#define LDSM4(r0, r1, r2, r3, addr) \
    asm volatile("ldmatrix.sync.aligned.m8n8.x4.shared.b16 {%0,%1,%2,%3}, [%4];" \
        : "=r"(r0), "=r"(r1), "=r"(r2), "=r"(r3) : "r"(addr))
#define LDSM4T(r0, r1, r2, r3, addr) \
    asm volatile("ldmatrix.sync.aligned.m8n8.x4.trans.shared.b16 {%0,%1,%2,%3}, [%4];" \
        : "=r"(r0), "=r"(r1), "=r"(r2), "=r"(r3) : "r"(addr))

// ---------------- weight transpose (fp32 -> fp16) ----------------
__global__ void transpose_h(const float* __restrict__ in, __half* __restrict__ out,
                            int R, int C) {
    __shared__ float tile[32][33];
    const float* src = in + (size_t)blockIdx.z * R * C;
    __half* dst = out + (size_t)blockIdx.z * R * C;
    int c0 = blockIdx.x * 32, r0 = blockIdx.y * 32;
    int tx = threadIdx.x, ty = threadIdx.y;          // 32 x 8
    #pragma unroll
    for (int i = 0; i < 32; i += 8)
        tile[ty + i][tx] = src[(size_t)(r0 + ty + i) * C + c0 + tx];
    __syncthreads();
    #pragma unroll
    for (int i = 0; i < 32; i += 8)
        dst[(size_t)(c0 + ty + i) * R + r0 + tx] = __float2half_rn(tile[tx][ty + i]);
}

// ---------------- fp16 mma GEMM (ldmatrix fragments), 3-stage cp.async ring ----------------
// 128x128 CTA tile, 8 warps (2M x 4N), warp tile 64x32, K-chunk 32, K=16/mma.
// Row stride PAD20 words: 20*{0..7} mod 32 all-distinct -> conflict-free LDSM phases.
#define PAD20 20
#define TBUF (128 * PAD20)
#define STG_B32 (2 * TBUF)
#define STAGES 3
#define GEMM_SMEM (STAGES * STG_B32 * 4) // 61440 B

template<bool RELU, bool HALFOUT>
__global__ void __launch_bounds__(256) gemm_mma(const __half* __restrict__ A,
                                                const __half* __restrict__ BT,
                                                const float* __restrict__ bias,
                                                const float* __restrict__ resid,
                                                void* __restrict__ Cout,
                                                int M, int N, int K) {
    extern __shared__ uint32_t gs[];
    uint32_t sbase = smem_u32(gs);
    int tid = threadIdx.x;
    int lane = tid & 31, wid = tid >> 5;
    int wm = wid & 1;
    int wn = wid >> 1;
    int row0 = blockIdx.y * 128, col0 = blockIdx.x * 128;
    int g = lane >> 2, tg = lane & 3;
    int lrow = lane & 7, lj = lane >> 3;          // ldmatrix: matrix j, row-in-matrix

    // A x4 matrices: j=0 rows+0 k-lo, j=1 rows+8 k-lo, j=2 rows+0 k-hi, j=3 rows+8 k-hi
    // -> output regs land exactly in a0..a3 of m16n8k16.
    uint32_t a_off[4];
    #pragma unroll
    for (int mi = 0; mi < 4; mi++)
        a_off[mi] = (uint32_t)(((wm * 64 + mi * 16 + (lj & 1) * 8 + lrow) * PAD20
                                + (lj >> 1) * 4) * 4);
    // B x4 (two ni per load): j=0 (ni,k-lo), j=1 (ni,k-hi), j=2 (ni+1,k-lo), j=3 (ni+1,k-hi)
    uint32_t b_off[2];
    #pragma unroll
    for (int pr = 0; pr < 2; pr++)
        b_off[pr] = (uint32_t)(TBUF * 4
                    + ((wn * 32 + pr * 16 + (lane >> 4) * 8 + lrow) * PAD20
                       + ((lane >> 3) & 1) * 4) * 4);

    float acc[4][4][4];
    #pragma unroll
    for (int mi = 0; mi < 4; mi++)
        #pragma unroll
        for (int ni = 0; ni < 4; ni++)
            #pragma unroll
            for (int r = 0; r < 4; r++) acc[mi][ni][r] = 0.0f;

    int nch = K >> 5;

    {
        uint32_t ab = sbase;
        uint32_t bb = sbase + TBUF * 4;
        #pragma unroll
        for (int i = 0; i < 2; ++i) {
            int idx = tid + i * 256;
            int n = idx >> 2, ch = idx & 3;
            const __half* pa = &A[(size_t)(row0 + n) * K + ch * 8];
            asm volatile("cp.async.cg.shared.global [%0], [%1], 16;"
                         :: "r"(ab + (uint32_t)(n * PAD20 + ch * 4) * 4), "l"(pa));
            const __half* pb = &BT[(size_t)(col0 + n) * K + ch * 8];
            asm volatile("cp.async.cg.shared.global [%0], [%1], 16;"
                         :: "r"(bb + (uint32_t)(n * PAD20 + ch * 4) * 4), "l"(pb));
        }
        asm volatile("cp.async.commit_group;" ::: "memory");
    }

    for (int c = 0; c < nch; ++c) {
        if (c + 1 < nch) {
            int k0 = (c + 1) << 5;
            uint32_t stoff = (uint32_t)(((c + 1) % STAGES) * STG_B32) * 4;
            uint32_t ab = sbase + stoff;
            uint32_t bb = ab + TBUF * 4;
            #pragma unroll
            for (int i = 0; i < 2; ++i) {
                int idx = tid + i * 256;
                int n = idx >> 2, ch = idx & 3;
                const __half* pa = &A[(size_t)(row0 + n) * K + k0 + ch * 8];
                asm volatile("cp.async.cg.shared.global [%0], [%1], 16;"
                             :: "r"(ab + (uint32_t)(n * PAD20 + ch * 4) * 4), "l"(pa));
                const __half* pb = &BT[(size_t)(col0 + n) * K + k0 + ch * 8];
                asm volatile("cp.async.cg.shared.global [%0], [%1], 16;"
                             :: "r"(bb + (uint32_t)(n * PAD20 + ch * 4) * 4), "l"(pb));
            }
        }
        asm volatile("cp.async.commit_group;" ::: "memory");
        asm volatile("cp.async.wait_group 1;" ::: "memory");
        __syncthreads();

        uint32_t stb = sbase + (uint32_t)((c % STAGES) * STG_B32) * 4;

        #pragma unroll
        for (int ki = 0; ki < 2; ++ki) {
            uint32_t ko = (uint32_t)ki * 32;          // 8 words per mma k-step
            uint32_t afr[4][4];
            #pragma unroll
            for (int mi = 0; mi < 4; mi++)
                LDSM4(afr[mi][0], afr[mi][1], afr[mi][2], afr[mi][3], stb + a_off[mi] + ko);
            uint32_t bfr[4][2];
            {
                uint32_t t0, t1, t2, t3;
                LDSM4(t0, t1, t2, t3, stb + b_off[0] + ko);
                bfr[0][0] = t0; bfr[0][1] = t1; bfr[1][0] = t2; bfr[1][1] = t3;
                LDSM4(t0, t1, t2, t3, stb + b_off[1] + ko);
                bfr[2][0] = t0; bfr[2][1] = t1; bfr[3][0] = t2; bfr[3][1] = t3;
            }
            #pragma unroll
            for (int mi = 0; mi < 4; mi++)
                #pragma unroll
                for (int ni = 0; ni < 4; ni++)
                    mma_16n8k16_f16(acc[mi][ni], afr[mi], bfr[ni]);
        }
    }

    #pragma unroll
    for (int mi = 0; mi < 4; mi++) {
        int r0r = row0 + wm * 64 + mi * 16 + g;
        #pragma unroll
        for (int ni = 0; ni < 4; ni++) {
            int cb = col0 + wn * 32 + ni * 8 + tg * 2;
            float b0 = bias[cb], b1 = bias[cb + 1];
            float v0 = acc[mi][ni][0] + b0, v1 = acc[mi][ni][1] + b1;
            float v2 = acc[mi][ni][2] + b0, v3 = acc[mi][ni][3] + b1;
            if (resid) {
                float2 r0v = *reinterpret_cast<const float2*>(&resid[(size_t)(r0r)     * N + cb]);
                float2 r1v = *reinterpret_cast<const float2*>(&resid[(size_t)(r0r + 8) * N + cb]);
                v0 += r0v.x; v1 += r0v.y; v2 += r1v.x; v3 += r1v.y;
            }
            if (RELU) { v0 = fmaxf(v0, 0.f); v1 = fmaxf(v1, 0.f);
                        v2 = fmaxf(v2, 0.f); v3 = fmaxf(v3, 0.f); }
            if (HALFOUT) {
                __half* Ch = (__half*)Cout;
                *reinterpret_cast<uint32_t*>(&Ch[(size_t)(r0r)     * N + cb]) = pack_h2(make_float2(v0, v1));
                *reinterpret_cast<uint32_t*>(&Ch[(size_t)(r0r + 8) * N + cb]) = pack_h2(make_float2(v2, v3));
            } else {
                float* Cf = (float*)Cout;
                *reinterpret_cast<float2*>(&Cf[(size_t)(r0r)     * N + cb]) = make_float2(v0, v1);
                *reinterpret_cast<float2*>(&Cf[(size_t)(r0r + 8) * N + cb]) = make_float2(v2, v3);
            }
        }
    }
}

// ---------------- fused flash attention (fp16, ldmatrix fragments) ----------------
// Row stride FW=36 words: 36*{0..7} mod 32 all-distinct -> conflict-free LDSM.
#define FW 36
#define FLASH_SMEM ((128 + 64 + 64 + 128) * FW * 4 + 64)

__global__ void __launch_bounds__(256) flash_attn(
    const __half* __restrict__ q, int ldq,
    const __half* __restrict__ k, const __half* __restrict__ v, int ldkv,
    const unsigned char* __restrict__ mqg, const unsigned char* __restrict__ mkg,
    __half* __restrict__ o, int causal)
{
    extern __shared__ char sm[];
    uint32_t smb = smem_u32(sm);
    uint32_t* Qs = reinterpret_cast<uint32_t*>(sm);        // [128][FW]
    uint32_t* Ks = Qs + 128 * FW;                          // [64][FW]
    uint32_t* Vs = Ks + 64 * FW;                           // [64 keys][FW] (NOT transposed)
    uint32_t* Ps = Vs + 64 * FW;                           // [128][FW]
    unsigned char* mks = reinterpret_cast<unsigned char*>(Ps + 128 * FW);
    const uint32_t QS0 = 0, KS0 = 128 * FW * 4, VS0 = (128 + 64) * FW * 4,
                   PS0 = (128 + 64 + 64) * FW * 4;

    int tid = threadIdx.x, lane = tid & 31, wid = tid >> 5;
    int bh = blockIdx.y, b = bh >> 3, h = bh & 7;
    int q0 = blockIdx.x * 128;
    const __half* Qg = q + (size_t)b * Sc * ldq + h * DHc;
    const __half* Kg = k + (size_t)b * Sc * ldkv + h * DHc;
    const __half* Vg = v + (size_t)b * Sc * ldkv + h * DHc;
    int g = lane >> 2, tg = lane & 3;
    int lrow = lane & 7, lj = lane >> 3;
    int rg = wid * 16 + g;
    int qi0 = q0 + rg, qi1 = qi0 + 8;

    // ldmatrix base offsets (within each region)
    uint32_t q_off = QS0 + (uint32_t)(((wid * 16 + (lj & 1) * 8 + lrow) * FW + (lj >> 1) * 4) * 4);
    uint32_t p_off = PS0 + (uint32_t)(((wid * 16 + (lj & 1) * 8 + lrow) * FW + (lj >> 1) * 4) * 4);
    uint32_t k_off[4];
    #pragma unroll
    for (int pr = 0; pr < 4; pr++)
        k_off[pr] = KS0 + (uint32_t)(((pr * 16 + (lane >> 4) * 8 + lrow) * FW
                                      + ((lane >> 3) & 1) * 4) * 4);
    // V trans x4: j=0 (dh ni, keys-lo), j=1 (ni, keys-hi), j=2 (ni+1, keys-lo), j=3 (ni+1, keys-hi)
    // lane row = key = (j&1)*8 + lrow ; col word = (2*pr + (j>>1))*4
    uint32_t v_off[4];
    #pragma unroll
    for (int pr = 0; pr < 4; pr++)
        v_off[pr] = VS0 + (uint32_t)(((((lane >> 3) & 1) * 8 + lrow) * FW
                                      + (2 * pr + (lane >> 4)) * 4) * 4);

    // load Q tile [128 x 64]
    #pragma unroll
    for (int i = 0; i < 4; ++i) {
        int idx = tid + i * 256;
        int r = idx >> 3, c8 = idx & 7;
        uint4 w = *reinterpret_cast<const uint4*>(&Qg[(size_t)(q0 + r) * ldq + c8 * 8]);
        *reinterpret_cast<uint4*>(&Qs[r * FW + c8 * 4]) = w;
    }
    bool mrow0 = mqg[b * Sc + qi0] != 0;
    bool mrow1 = mqg[b * Sc + qi1] != 0;

    float m0 = -1e30f, m1 = -1e30f, l0 = 0.f, l1 = 0.f;
    float oacc[8][4];
    #pragma unroll
    for (int ni = 0; ni < 8; ni++) { oacc[ni][0] = oacc[ni][1] = oacc[ni][2] = oacc[ni][3] = 0.f; }

    int nkt = causal ? ((q0 >> 6) + 2) : (Sc / 64);
    for (int kt = 0; kt < nkt; ++kt) {
        int k0 = kt * 64;
        __syncthreads();
        #pragma unroll
        for (int i = 0; i < 2; ++i) {
            int idx = tid + i * 256;
            int r = idx >> 3, c8 = idx & 7;
            uint4 wk = *reinterpret_cast<const uint4*>(&Kg[(size_t)(k0 + r) * ldkv + c8 * 8]);
            *reinterpret_cast<uint4*>(&Ks[r * FW + c8 * 4]) = wk;
            uint4 wv = *reinterpret_cast<const uint4*>(&Vg[(size_t)(k0 + r) * ldkv + c8 * 8]);
            *reinterpret_cast<uint4*>(&Vs[r * FW + c8 * 4]) = wv;   // untransposed; LDSM.trans later
        }
        if (tid < 64) mks[tid] = mkg[b * Sc + k0 + tid];
        __syncthreads();

        // ---- S = Q @ K^T ----
        float s[8][4];
        #pragma unroll
        for (int ni = 0; ni < 8; ni++) { s[ni][0] = s[ni][1] = s[ni][2] = s[ni][3] = 0.f; }
        #pragma unroll
        for (int ki = 0; ki < 4; ++ki) {
            uint32_t ko = (uint32_t)ki * 32;
            uint32_t a[4];
            LDSM4(a[0], a[1], a[2], a[3], smb + q_off + ko);
            uint32_t bfr[8][2];
            #pragma unroll
            for (int pr = 0; pr < 4; pr++) {
                uint32_t t0, t1, t2, t3;
                LDSM4(t0, t1, t2, t3, smb + k_off[pr] + ko);
                bfr[2 * pr][0] = t0; bfr[2 * pr][1] = t1;
                bfr[2 * pr + 1][0] = t2; bfr[2 * pr + 1][1] = t3;
            }
            #pragma unroll
            for (int ni = 0; ni < 8; ni++)
                mma_16n8k16_f16(s[ni], a, bfr[ni]);
        }

        // ---- scale + mask + online softmax ----
        float rmax0 = neg_inf_f(), rmax1 = neg_inf_f();
        #pragma unroll
        for (int ni = 0; ni < 8; ni++) {
            int cloc = ni * 8 + 2 * tg;
            int cg = k0 + cloc;
            bool mkA = mks[cloc] != 0, mkB = mks[cloc + 1] != 0;
            float v0 = (mrow0 || mkA || (causal && cg     > qi0)) ? neg_inf_f() : s[ni][0] * SCALEc;
            float v1 = (mrow0 || mkB || (causal && cg + 1 > qi0)) ? neg_inf_f() : s[ni][1] * SCALEc;
            float v2 = (mrow1 || mkA || (causal && cg     > qi1)) ? neg_inf_f() : s[ni][2] * SCALEc;
            float v3 = (mrow1 || mkB || (causal && cg + 1 > qi1)) ? neg_inf_f() : s[ni][3] * SCALEc;
            s[ni][0] = v0; s[ni][1] = v1; s[ni][2] = v2; s[ni][3] = v3;
            rmax0 = fmaxf(rmax0, fmaxf(v0, v1));
            rmax1 = fmaxf(rmax1, fmaxf(v2, v3));
        }
        rmax0 = fmaxf(rmax0, __shfl_xor_sync(0xffffffffu, rmax0, 1));
        rmax0 = fmaxf(rmax0, __shfl_xor_sync(0xffffffffu, rmax0, 2));
        rmax1 = fmaxf(rmax1, __shfl_xor_sync(0xffffffffu, rmax1, 1));
        rmax1 = fmaxf(rmax1, __shfl_xor_sync(0xffffffffu, rmax1, 2));

        float mn0 = fmaxf(m0, rmax0), mn1 = fmaxf(m1, rmax1);
        float sc0 = __expf(m0 - mn0), sc1 = __expf(m1 - mn1);
        float rs0 = 0.f, rs1 = 0.f;
        #pragma unroll
        for (int ni = 0; ni < 8; ni++) {
            float p0 = __expf(s[ni][0] - mn0), p1 = __expf(s[ni][1] - mn0);
            float p2 = __expf(s[ni][2] - mn1), p3 = __expf(s[ni][3] - mn1);
            rs0 += p0 + p1; rs1 += p2 + p3;
            Ps[rg * FW + ni * 4 + tg]       = pack_h2(make_float2(p0, p1));
            Ps[(rg + 8) * FW + ni * 4 + tg] = pack_h2(make_float2(p2, p3));
        }
        rs0 += __shfl_xor_sync(0xffffffffu, rs0, 1);
        rs0 += __shfl_xor_sync(0xffffffffu, rs0, 2);
        rs1 += __shfl_xor_sync(0xffffffffu, rs1, 1);
        rs1 += __shfl_xor_sync(0xffffffffu, rs1, 2);
        l0 = l0 * sc0 + rs0; l1 = l1 * sc1 + rs1;
        m0 = mn0; m1 = mn1;
        #pragma unroll
        for (int ni = 0; ni < 8; ni++) {
            oacc[ni][0] *= sc0; oacc[ni][1] *= sc0;
            oacc[ni][2] *= sc1; oacc[ni][3] *= sc1;
        }
        __syncwarp();    // Ps rows are warp-exclusive; order STS vs cross-lane LDSM

        // ---- O += P @ V  (V fragments via ldmatrix.trans; k runs over keys) ----
        #pragma unroll
        for (int ki = 0; ki < 4; ++ki) {
            uint32_t pko = (uint32_t)ki * 32;              // P: k offset in words
            uint32_t vko = (uint32_t)ki * 16 * FW * 4;     // V: key-row offset
            uint32_t a[4];
            LDSM4(a[0], a[1], a[2], a[3], smb + p_off + pko);
            uint32_t bfr[8][2];
            #pragma unroll
            for (int pr = 0; pr < 4; pr++) {
                uint32_t t0, t1, t2, t3;
                LDSM4T(t0, t1, t2, t3, smb + v_off[pr] + vko);
                bfr[2 * pr][0] = t0; bfr[2 * pr][1] = t1;
                bfr[2 * pr + 1][0] = t2; bfr[2 * pr + 1][1] = t3;
            }
            #pragma unroll
            for (int ni = 0; ni < 8; ni++)
                mma_16n8k16_f16(oacc[ni], a, bfr[ni]);
        }
    }

    float inv0 = (l0 > 0.f) ? 1.f / l0 : 0.f;
    float inv1 = (l1 > 0.f) ? 1.f / l1 : 0.f;
    size_t ob0 = ((size_t)b * Sc + qi0) * Dc + h * DHc;
    size_t ob1 = ((size_t)b * Sc + qi1) * Dc + h * DHc;
    #pragma unroll
    for (int ni = 0; ni < 8; ni++) {
        int cc = ni * 8 + 2 * tg;
        *reinterpret_cast<uint32_t*>(&o[ob0 + cc]) =
            pack_h2(make_float2(oacc[ni][0] * inv0, oacc[ni][1] * inv0));
        *reinterpret_cast<uint32_t*>(&o[ob1 + cc]) =
            pack_h2(make_float2(oacc[ni][2] * inv1, oacc[ni][3] * inv1));
    }
}

// ---------------- embedding + PE (+ pad mask), dual fp32/fp16 output ----------------
__global__ void embed_pe_kernel(const int* __restrict__ toks,
                                const float* __restrict__ emb,
                                float* __restrict__ out,
                                __half* __restrict__ outh,
                                unsigned char* __restrict__ mask) {
    int pos = blockIdx.x % Sc;
    int b   = blockIdx.x / Sc;
    int tok = toks[b * Sc + pos];
    int t = threadIdx.x;
    if (t == 0) mask[b * Sc + pos] = (tok == 0) ? 1 : 0;
    const float c = -logf(10000.0f) / (float)Dc;
    size_t base = ((size_t)b * Sc + pos) * Dc;
    #pragma unroll
    for (int d = t; d < Dc; d += 256) {
        int i = d >> 1;
        float freq = __expf((float)(2 * i) * c);
        float ang  = (float)pos * freq;
        float pe   = (d & 1) ? cosf(ang) : sinf(ang);
        float v = emb[(size_t)tok * Dc + d] + pe;
        out[base + d] = v;
        outh[base + d] = __float2half_rn(v);
    }
}

// ---------------- LayerNorm: dual fp32 + fp16 output (warp per row) ----------------
__global__ void __launch_bounds__(256) ln_kernel(const float* __restrict__ xin,
                                                 const float* __restrict__ gamma,
                                                 const float* __restrict__ beta,
                                                 float* __restrict__ out,
                                                 __half* __restrict__ outh) {
    int warp = threadIdx.x >> 5, lane = threadIdx.x & 31;
    size_t row = (size_t)blockIdx.x * 8 + warp;
    size_t base = row * Dc;
    float4 v[4];
    float sum = 0.f;
    #pragma unroll
    for (int i = 0; i < 4; ++i) {
        v[i] = *reinterpret_cast<const float4*>(&xin[base + lane * 4 + i * 128]);
        sum += v[i].x + v[i].y + v[i].z + v[i].w;
    }
    #pragma unroll
    for (int s = 16; s > 0; s >>= 1) sum += __shfl_xor_sync(0xffffffffu, sum, s);
    float mu = sum * (1.0f / Dc);
    float var = 0.f;
    #pragma unroll
    for (int i = 0; i < 4; ++i) {
        v[i].x -= mu; v[i].y -= mu; v[i].z -= mu; v[i].w -= mu;
        var += v[i].x * v[i].x + v[i].y * v[i].y + v[i].z * v[i].z + v[i].w * v[i].w;
    }
    #pragma unroll
    for (int s = 16; s > 0; s >>= 1) var += __shfl_xor_sync(0xffffffffu, var, s);
    float inv = rsqrtf(var * (1.0f / Dc) + EPSc);
    #pragma unroll
    for (int i = 0; i < 4; ++i) {
        int col = lane * 4 + i * 128;
        float4 gv = *reinterpret_cast<const float4*>(&gamma[col]);
        float4 bv = *reinterpret_cast<const float4*>(&beta[col]);
        float4 o;
        o.x = v[i].x * inv * gv.x + bv.x;
        o.y = v[i].y * inv * gv.y + bv.y;
        o.z = v[i].z * inv * gv.z + bv.z;
        o.w = v[i].w * inv * gv.w + bv.w;
        *reinterpret_cast<float4*>(&out[base + col]) = o;
        uint2 hw = make_uint2(pack_h2(make_float2(o.x, o.y)),
                              pack_h2(make_float2(o.z, o.w)));
        *reinterpret_cast<uint2*>(&outh[base + col]) = hw;
    }
}

// ---------------- host orchestration ----------------
static void launch_gemm_f(const __half* A, const __half* BT, const float* bias,
                          const float* resid, float* C, int M, int N, int K) {
    dim3 grid(N / 128, M / 128);
    gemm_mma<false, false><<<grid, 256, GEMM_SMEM>>>(A, BT, bias, resid, C, M, N, K);
}
static void launch_gemm_h(const __half* A, const __half* BT, const float* bias,
                          __half* C, int M, int N, int K, bool relu) {
    dim3 grid(N / 128, M / 128);
    if (relu) gemm_mma<true,  true><<<grid, 256, GEMM_SMEM>>>(A, BT, bias, nullptr, C, M, N, K);
    else      gemm_mma<false, true><<<grid, 256, GEMM_SMEM>>>(A, BT, bias, nullptr, C, M, N, K);
}

static void run_mha(const __half* xqh, const __half* xkvh, bool same,
                    const unsigned char* mq, const unsigned char* mk, int causal,
                    const __half* wT, const float* b, const float* resid,
                    __half* qkvh, __half* qh, __half* attnh, float* outp) {
    dim3 gfl(Sc / 128, Bc * NHc);
    if (same) {
        launch_gemm_h(xqh, wT, b, qkvh, BSc, 3 * Dc, Dc, false);
        flash_attn<<<gfl, 256, FLASH_SMEM>>>(qkvh, 3 * Dc, qkvh + Dc, qkvh + 2 * Dc, 3 * Dc,
                                             mq, mk, attnh, causal);
    } else {
        launch_gemm_h(xqh,  wT,                   b,      qh,   BSc, Dc,     Dc, false);
        launch_gemm_h(xkvh, wT + (size_t)Dc * Dc, b + Dc, qkvh, BSc, 2 * Dc, Dc, false);
        flash_attn<<<gfl, 256, FLASH_SMEM>>>(qh, Dc, qkvh, qkvh + Dc, 2 * Dc,
                                             mq, mk, attnh, causal);
    }
    launch_gemm_f(attnh, wT + 3 * (size_t)Dc * Dc, b + 3 * Dc, resid, outp, BSc, Dc, Dc);
}

extern "C" void kernel_launch(void* const* d_in, const int* in_sizes, int n_in,
                              void* d_out, int out_size) {
    const int*   inputs  = (const int*)d_in[0];
    const int*   outputs = (const int*)d_in[1];
    const float* emi = (const float*)d_in[2];
    const float* emo = (const float*)d_in[3];
    const float* enc_attn_w = (const float*)d_in[4];
    const float* enc_attn_b = (const float*)d_in[5];
    const float* enc_ln     = (const float*)d_in[6];
    const float* enc_ffn_w1 = (const float*)d_in[7];
    const float* enc_ffn_b1 = (const float*)d_in[8];
    const float* enc_ffn_w2 = (const float*)d_in[9];
    const float* enc_ffn_b2 = (const float*)d_in[10];
    const float* dec_self_w  = (const float*)d_in[11];
    const float* dec_self_b  = (const float*)d_in[12];
    const float* dec_cross_w = (const float*)d_in[13];
    const float* dec_cross_b = (const float*)d_in[14];
    const float* dec_ln      = (const float*)d_in[15];
    const float* dec_ffn_w1 = (const float*)d_in[16];
    const float* dec_ffn_b1 = (const float*)d_in[17];
    const float* dec_ffn_w2 = (const float*)d_in[18];
    const float* dec_ffn_b2 = (const float*)d_in[19];

    float *xp, *yp, *tmpp;
    __half *xh, *yh, *qkvh, *qh, *attnh, *hidh;
    __half *wta_enc, *wta_self, *wta_cross, *wt_ef1, *wt_ef2, *wt_df1, *wt_df2;
    unsigned char *mxp, *myp;
    cudaGetSymbolAddress((void**)&xp, g_x);
    cudaGetSymbolAddress((void**)&yp, g_y);
    cudaGetSymbolAddress((void**)&tmpp, g_tmp);
    cudaGetSymbolAddress((void**)&xh, g_xh);
    cudaGetSymbolAddress((void**)&yh, g_yh);
    cudaGetSymbolAddress((void**)&qkvh, g_qkvh);
    cudaGetSymbolAddress((void**)&qh, g_qh);
    cudaGetSymbolAddress((void**)&attnh, g_attnh);
    cudaGetSymbolAddress((void**)&hidh, g_hidh);
    cudaGetSymbolAddress((void**)&mxp, g_mx);
    cudaGetSymbolAddress((void**)&myp, g_my);
    cudaGetSymbolAddress((void**)&wta_enc,   g_wt_enc_attn);
    cudaGetSymbolAddress((void**)&wta_self,  g_wt_dec_self);
    cudaGetSymbolAddress((void**)&wta_cross, g_wt_dec_cross);
    cudaGetSymbolAddress((void**)&wt_ef1, g_wt_enc_f1);
    cudaGetSymbolAddress((void**)&wt_ef2, g_wt_enc_f2);
    cudaGetSymbolAddress((void**)&wt_df1, g_wt_dec_f1);
    cudaGetSymbolAddress((void**)&wt_df2, g_wt_dec_f2);

    cudaFuncSetAttribute(flash_attn, cudaFuncAttributeMaxDynamicSharedMemorySize, FLASH_SMEM);
    cudaFuncSetAttribute(gemm_mma<false, false>, cudaFuncAttributeMaxDynamicSharedMemorySize, GEMM_SMEM);
    cudaFuncSetAttribute(gemm_mma<false, true >, cudaFuncAttributeMaxDynamicSharedMemorySize, GEMM_SMEM);
    cudaFuncSetAttribute(gemm_mma<true,  true >, cudaFuncAttributeMaxDynamicSharedMemorySize, GEMM_SMEM);

    // -------- weight transposes (fp32 -> fp16, [N][K]) --------
    dim3 tblk(32, 8);
    transpose_h<<<dim3(Dc / 32, Dc / 32, Lc * 4), tblk>>>(enc_attn_w,  wta_enc,   Dc, Dc);
    transpose_h<<<dim3(Dc / 32, Dc / 32, Lc * 4), tblk>>>(dec_self_w,  wta_self,  Dc, Dc);
    transpose_h<<<dim3(Dc / 32, Dc / 32, Lc * 4), tblk>>>(dec_cross_w, wta_cross, Dc, Dc);
    transpose_h<<<dim3(HIDc / 32, Dc / 32, Lc), tblk>>>(enc_ffn_w1, wt_ef1, Dc, HIDc);
    transpose_h<<<dim3(Dc / 32, HIDc / 32, Lc), tblk>>>(enc_ffn_w2, wt_ef2, HIDc, Dc);
    transpose_h<<<dim3(HIDc / 32, Dc / 32, Lc), tblk>>>(dec_ffn_w1, wt_df1, Dc, HIDc);
    transpose_h<<<dim3(Dc / 32, HIDc / 32, Lc), tblk>>>(dec_ffn_w2, wt_df2, HIDc, Dc);

    dim3 blk(256);
    embed_pe_kernel<<<BSc, blk>>>(inputs,  emi, xp, xh, mxp);
    embed_pe_kernel<<<BSc, blk>>>(outputs, emo, yp, yh, myp);

    int lng = BSc / 8;   // 512 blocks, warp per row

    // ---------------- encoder ----------------
    for (int l = 0; l < Lc; ++l) {
        const __half* wT = wta_enc + (size_t)l * 4 * Dc * Dc;
        const float* ab = enc_attn_b + (size_t)l * 4 * Dc;
        run_mha(xh, xh, true, mxp, mxp, 0, wT, ab, xp, qkvh, qh, attnh, tmpp);
        const float* ln0 = enc_ln + (((size_t)l * 2 + 0) * 2) * Dc;
        ln_kernel<<<lng, blk>>>(tmpp, ln0, ln0 + Dc, xp, xh);
        launch_gemm_h(xh, wt_ef1 + (size_t)l * Dc * HIDc, enc_ffn_b1 + (size_t)l * HIDc,
                      hidh, BSc, HIDc, Dc, true);
        launch_gemm_f(hidh, wt_ef2 + (size_t)l * Dc * HIDc, enc_ffn_b2 + (size_t)l * Dc,
                      xp, tmpp, BSc, Dc, HIDc);
        const float* ln1 = enc_ln + (((size_t)l * 2 + 1) * 2) * Dc;
        ln_kernel<<<lng, blk>>>(tmpp, ln1, ln1 + Dc, xp, xh);
    }

    // ---------------- decoder ----------------
    float* fout = (float*)d_out;
    for (int l = 0; l < Lc; ++l) {
        const __half* swT = wta_self + (size_t)l * 4 * Dc * Dc;
        const float* sb  = dec_self_b + (size_t)l * 4 * Dc;
        run_mha(yh, yh, true, myp, myp, 1, swT, sb, yp, qkvh, qh, attnh, tmpp);
        const float* ln0 = dec_ln + (((size_t)l * 3 + 0) * 2) * Dc;
        ln_kernel<<<lng, blk>>>(tmpp, ln0, ln0 + Dc, yp, yh);

        const __half* cwT = wta_cross + (size_t)l * 4 * Dc * Dc;
        const float* cb  = dec_cross_b + (size_t)l * 4 * Dc;
        run_mha(yh, xh, false, myp, mxp, 0, cwT, cb, yp, qkvh, qh, attnh, tmpp);
        const float* ln1 = dec_ln + (((size_t)l * 3 + 1) * 2) * Dc;
        ln_kernel<<<lng, blk>>>(tmpp, ln1, ln1 + Dc, yp, yh);

        launch_gemm_h(yh, wt_df1 + (size_t)l * Dc * HIDc, dec_ffn_b1 + (size_t)l * HIDc,
                      hidh, BSc, HIDc, Dc, true);
        launch_gemm_f(hidh, wt_df2 + (size_t)l * Dc * HIDc, dec_ffn_b2 + (size_t)l * Dc,
                      yp, tmpp, BSc, Dc, HIDc);
        const float* ln2 = dec_ln + (((size_t)l * 3 + 2) * 2) * Dc;
        float* dst = (l == Lc - 1) ? fout : yp;
        ln_kernel<<<lng, blk>>>(tmpp, ln2, ln2 + Dc, dst, yh);
    }
    (void)in_sizes; (void)n_in; (void)out_size;
}

// round 12
// speedup vs baseline: 1.9639x; 1.1332x over previous
#include <cuda_runtime.h>
#include <cuda_fp16.h>
#include <math.h>
#include <cstdint>

// ---------------- problem constants ----------------
#define Bc   8
#define Sc   512
#define Dc   512
#define NHc  8
#define DHc  64
#define Lc   6
#define HIDc 2048
#define EPSc 1e-5f
#define BSc  (Bc * Sc)          // 4096 tokens
#define SCALEc 0.125f           // 1/sqrt(64)

// ---------------- device scratch ----------------
__device__ float  g_x[BSc * Dc];
__device__ float  g_y[BSc * Dc];
__device__ float  g_tmp[BSc * Dc];
__device__ __half g_xh[BSc * Dc];
__device__ __half g_yh[BSc * Dc];
__device__ __half g_qkvh[BSc * 3 * Dc];
__device__ __half g_qh[BSc * Dc];
__device__ __half g_attnh[BSc * Dc];
__device__ __half g_hidh[BSc * HIDc];
__device__ unsigned char g_mx[BSc];
__device__ unsigned char g_my[BSc];
// transposed fp16 weights: [N][K]
__device__ __half g_wt_enc_attn[Lc * 4 * Dc * Dc];
__device__ __half g_wt_dec_self[Lc * 4 * Dc * Dc];
__device__ __half g_wt_dec_cross[Lc * 4 * Dc * Dc];
__device__ __half g_wt_enc_f1[Lc * Dc * HIDc];
__device__ __half g_wt_enc_f2[Lc * Dc * HIDc];
__device__ __half g_wt_dec_f1[Lc * Dc * HIDc];
__device__ __half g_wt_dec_f2[Lc * Dc * HIDc];

__device__ __forceinline__ float neg_inf_f() { return __int_as_float(0xff800000u); }

__device__ __forceinline__ uint32_t smem_u32(const void* p) {
    uint32_t a;
    asm("{ .reg .u64 t; cvta.to.shared.u64 t, %1; cvt.u32.u64 %0, t; }" : "=r"(a) : "l"(p));
    return a;
}
__device__ __forceinline__ uint32_t pack_h2(float2 f) {
    __half2 h = __floats2half2_rn(f.x, f.y);
    return *reinterpret_cast<uint32_t*>(&h);
}

__device__ __forceinline__ void mma_16n8k16_f16(float c[4], const uint32_t a[4], const uint32_t b[2]) {
    asm volatile(
        "mma.sync.aligned.m16n8k16.row.col.f32.f16.f16.f32 "
        "{%0,%1,%2,%3}, {%4,%5,%6,%7}, {%8,%9}, {%0,%1,%2,%3};"
        : "+f"(c[0]), "+f"(c[1]), "+f"(c[2]), "+f"(c[3])
        : "r"(a[0]), "r"(a[1]), "r"(a[2]), "r"(a[3]), "r"(b[0]), "r"(b[1]));
}
#define LDSM4(r0, r1, r2, r3, addr) \
    asm volatile("ldmatrix.sync.aligned.m8n8.x4.shared.b16 {%0,%1,%2,%3}, [%4];" \
        : "=r"(r0), "=r"(r1), "=r"(r2), "=r"(r3) : "r"(addr))
#define LDSM4T(r0, r1, r2, r3, addr) \
    asm volatile("ldmatrix.sync.aligned.m8n8.x4.trans.shared.b16 {%0,%1,%2,%3}, [%4];" \
        : "=r"(r0), "=r"(r1), "=r"(r2), "=r"(r3) : "r"(addr))

// ---------------- weight transpose (fp32 -> fp16) ----------------
__global__ void transpose_h(const float* __restrict__ in, __half* __restrict__ out,
                            int R, int C) {
    __shared__ float tile[32][33];
    const float* src = in + (size_t)blockIdx.z * R * C;
    __half* dst = out + (size_t)blockIdx.z * R * C;
    int c0 = blockIdx.x * 32, r0 = blockIdx.y * 32;
    int tx = threadIdx.x, ty = threadIdx.y;
    #pragma unroll
    for (int i = 0; i < 32; i += 8)
        tile[ty + i][tx] = src[(size_t)(r0 + ty + i) * C + c0 + tx];
    __syncthreads();
    #pragma unroll
    for (int i = 0; i < 32; i += 8)
        dst[(size_t)(c0 + ty + i) * R + r0 + tx] = __float2half_rn(tile[tx][ty + i]);
}

// ---------------- fp16 mma GEMM, K-chunk 64, 3-stage cp.async ring ----------------
// 128x128 CTA tile, 8 warps (2M x 4N), warp tile 64x32.
// Row stride 36 words (64 halves + pad): 36*{0..7} mod 32 all-distinct -> LDSM conflict-free.
#define GPAD 36
#define TBUF (128 * GPAD)
#define STG_B32 (2 * TBUF)
#define STAGES 3
#define GEMM_SMEM (STAGES * STG_B32 * 4) // 110592 B -> 2 CTAs/SM

// device-side mainloop shared by both GEMM kernels
template<bool RELU, bool HALFOUT>
__device__ __forceinline__ void gemm_body(const __half* A, const __half* BT,
                                          const float* bias, const float* resid,
                                          void* Cout, int row0, int col0, int N, int K,
                                          uint32_t* gs, uint32_t sbase) {
    int tid = threadIdx.x;
    int lane = tid & 31, wid = tid >> 5;
    int wm = wid & 1, wn = wid >> 1;
    int g = lane >> 2, tg = lane & 3;
    int lrow = lane & 7, lj = lane >> 3;

    uint32_t a_off[4];
    #pragma unroll
    for (int mi = 0; mi < 4; mi++)
        a_off[mi] = (uint32_t)(((wm * 64 + mi * 16 + (lj & 1) * 8 + lrow) * GPAD
                                + (lj >> 1) * 4) * 4);
    uint32_t b_off[2];
    #pragma unroll
    for (int pr = 0; pr < 2; pr++)
        b_off[pr] = (uint32_t)(TBUF * 4
                    + ((wn * 32 + pr * 16 + (lane >> 4) * 8 + lrow) * GPAD
                       + ((lane >> 3) & 1) * 4) * 4);

    float acc[4][4][4];
    #pragma unroll
    for (int mi = 0; mi < 4; mi++)
        #pragma unroll
        for (int ni = 0; ni < 4; ni++)
            #pragma unroll
            for (int r = 0; r < 4; r++) acc[mi][ni][r] = 0.0f;

    int nch = K >> 6;

    {
        uint32_t ab = sbase, bb = sbase + TBUF * 4;
        #pragma unroll
        for (int i = 0; i < 4; ++i) {
            int idx = tid + i * 256;
            int n = idx >> 3, ch = idx & 7;
            const __half* pa = &A[(size_t)(row0 + n) * K + ch * 8];
            asm volatile("cp.async.cg.shared.global [%0], [%1], 16;"
                         :: "r"(ab + (uint32_t)(n * GPAD + ch * 4) * 4), "l"(pa));
            const __half* pb = &BT[(size_t)(col0 + n) * K + ch * 8];
            asm volatile("cp.async.cg.shared.global [%0], [%1], 16;"
                         :: "r"(bb + (uint32_t)(n * GPAD + ch * 4) * 4), "l"(pb));
        }
        asm volatile("cp.async.commit_group;" ::: "memory");
    }

    for (int c = 0; c < nch; ++c) {
        if (c + 1 < nch) {
            int k0 = (c + 1) << 6;
            uint32_t stoff = (uint32_t)(((c + 1) % STAGES) * STG_B32) * 4;
            uint32_t ab = sbase + stoff, bb = ab + TBUF * 4;
            #pragma unroll
            for (int i = 0; i < 4; ++i) {
                int idx = tid + i * 256;
                int n = idx >> 3, ch = idx & 7;
                const __half* pa = &A[(size_t)(row0 + n) * K + k0 + ch * 8];
                asm volatile("cp.async.cg.shared.global [%0], [%1], 16;"
                             :: "r"(ab + (uint32_t)(n * GPAD + ch * 4) * 4), "l"(pa));
                const __half* pb = &BT[(size_t)(col0 + n) * K + k0 + ch * 8];
                asm volatile("cp.async.cg.shared.global [%0], [%1], 16;"
                             :: "r"(bb + (uint32_t)(n * GPAD + ch * 4) * 4), "l"(pb));
            }
        }
        asm volatile("cp.async.commit_group;" ::: "memory");
        asm volatile("cp.async.wait_group 1;" ::: "memory");
        __syncthreads();

        uint32_t stb = sbase + (uint32_t)((c % STAGES) * STG_B32) * 4;

        #pragma unroll
        for (int ki = 0; ki < 4; ++ki) {
            uint32_t ko = (uint32_t)ki * 32;         // 8 words per k-step
            uint32_t afr[4][4];
            #pragma unroll
            for (int mi = 0; mi < 4; mi++)
                LDSM4(afr[mi][0], afr[mi][1], afr[mi][2], afr[mi][3], stb + a_off[mi] + ko);
            uint32_t bfr[4][2];
            {
                uint32_t t0, t1, t2, t3;
                LDSM4(t0, t1, t2, t3, stb + b_off[0] + ko);
                bfr[0][0] = t0; bfr[0][1] = t1; bfr[1][0] = t2; bfr[1][1] = t3;
                LDSM4(t0, t1, t2, t3, stb + b_off[1] + ko);
                bfr[2][0] = t0; bfr[2][1] = t1; bfr[3][0] = t2; bfr[3][1] = t3;
            }
            #pragma unroll
            for (int mi = 0; mi < 4; mi++)
                #pragma unroll
                for (int ni = 0; ni < 4; ni++)
                    mma_16n8k16_f16(acc[mi][ni], afr[mi], bfr[ni]);
        }
    }

    #pragma unroll
    for (int mi = 0; mi < 4; mi++) {
        int r0r = row0 + wm * 64 + mi * 16 + g;
        #pragma unroll
        for (int ni = 0; ni < 4; ni++) {
            int cb = col0 + wn * 32 + ni * 8 + tg * 2;
            float b0 = bias[cb], b1 = bias[cb + 1];
            float v0 = acc[mi][ni][0] + b0, v1 = acc[mi][ni][1] + b1;
            float v2 = acc[mi][ni][2] + b0, v3 = acc[mi][ni][3] + b1;
            if (resid) {
                float2 r0v = *reinterpret_cast<const float2*>(&resid[(size_t)(r0r)     * N + cb]);
                float2 r1v = *reinterpret_cast<const float2*>(&resid[(size_t)(r0r + 8) * N + cb]);
                v0 += r0v.x; v1 += r0v.y; v2 += r1v.x; v3 += r1v.y;
            }
            if (RELU) { v0 = fmaxf(v0, 0.f); v1 = fmaxf(v1, 0.f);
                        v2 = fmaxf(v2, 0.f); v3 = fmaxf(v3, 0.f); }
            if (HALFOUT) {
                __half* Ch = (__half*)Cout;
                *reinterpret_cast<uint32_t*>(&Ch[(size_t)(r0r)     * N + cb]) = pack_h2(make_float2(v0, v1));
                *reinterpret_cast<uint32_t*>(&Ch[(size_t)(r0r + 8) * N + cb]) = pack_h2(make_float2(v2, v3));
            } else {
                float* Cf = (float*)Cout;
                *reinterpret_cast<float2*>(&Cf[(size_t)(r0r)     * N + cb]) = make_float2(v0, v1);
                *reinterpret_cast<float2*>(&Cf[(size_t)(r0r + 8) * N + cb]) = make_float2(v2, v3);
            }
        }
    }
}

template<bool RELU, bool HALFOUT>
__global__ void __launch_bounds__(256) gemm_mma(const __half* __restrict__ A,
                                                const __half* __restrict__ BT,
                                                const float* __restrict__ bias,
                                                const float* __restrict__ resid,
                                                void* __restrict__ Cout,
                                                int M, int N, int K) {
    extern __shared__ uint32_t gs[];
    gemm_body<RELU, HALFOUT>(A, BT, bias, resid, Cout,
                             blockIdx.y * 128, blockIdx.x * 128, N, K, gs, smem_u32(gs));
}

// dual GEMM: job0 (x-blocks [0,xs)) and job1 ([xs, ...)). Same M, K; fp16 out; no relu.
__global__ void __launch_bounds__(256) gemm_dual(const __half* A0, const __half* B0,
                                                 const float* bi0, __half* C0, int N0, int xs,
                                                 const __half* A1, const __half* B1,
                                                 const float* bi1, __half* C1, int N1,
                                                 int K) {
    extern __shared__ uint32_t gs[];
    if ((int)blockIdx.x < xs)
        gemm_body<false, true>(A0, B0, bi0, nullptr, C0,
                               blockIdx.y * 128, blockIdx.x * 128, N0, K, gs, smem_u32(gs));
    else
        gemm_body<false, true>(A1, B1, bi1, nullptr, C1,
                               blockIdx.y * 128, (blockIdx.x - xs) * 128, N1, K, gs, smem_u32(gs));
}

// ---------------- fused flash attention (fp16, ldmatrix, P-in-registers) ----------------
#define FW 36
#define FLASH_SMEM ((128 + 64 + 64) * FW * 4 + 64)

__global__ void __launch_bounds__(256) flash_attn(
    const __half* __restrict__ q, int ldq,
    const __half* __restrict__ k, const __half* __restrict__ v, int ldkv,
    const unsigned char* __restrict__ mqg, const unsigned char* __restrict__ mkg,
    __half* __restrict__ o, int causal)
{
    extern __shared__ char sm[];
    uint32_t smb = smem_u32(sm);
    uint32_t* Qs = reinterpret_cast<uint32_t*>(sm);        // [128][FW]
    uint32_t* Ks = Qs + 128 * FW;                          // [64][FW]
    uint32_t* Vs = Ks + 64 * FW;                           // [64 keys][FW]
    unsigned char* mks = reinterpret_cast<unsigned char*>(Vs + 64 * FW);
    const uint32_t QS0 = 0, KS0 = 128 * FW * 4, VS0 = (128 + 64) * FW * 4;

    int tid = threadIdx.x, lane = tid & 31, wid = tid >> 5;
    int bh = blockIdx.y, b = bh >> 3, h = bh & 7;
    int qt = causal ? ((int)gridDim.x - 1 - (int)blockIdx.x) : (int)blockIdx.x; // heavy first
    int q0 = qt * 128;
    const __half* Qg = q + (size_t)b * Sc * ldq + h * DHc;
    const __half* Kg = k + (size_t)b * Sc * ldkv + h * DHc;
    const __half* Vg = v + (size_t)b * Sc * ldkv + h * DHc;
    int g = lane >> 2, tg = lane & 3;
    int lrow = lane & 7, lj = lane >> 3;
    int rg = wid * 16 + g;
    int qi0 = q0 + rg, qi1 = qi0 + 8;

    uint32_t q_off = QS0 + (uint32_t)(((wid * 16 + (lj & 1) * 8 + lrow) * FW + (lj >> 1) * 4) * 4);
    uint32_t k_off[4];
    #pragma unroll
    for (int pr = 0; pr < 4; pr++)
        k_off[pr] = KS0 + (uint32_t)(((pr * 16 + (lane >> 4) * 8 + lrow) * FW
                                      + ((lane >> 3) & 1) * 4) * 4);
    uint32_t v_off[4];
    #pragma unroll
    for (int pr = 0; pr < 4; pr++)
        v_off[pr] = VS0 + (uint32_t)(((((lane >> 3) & 1) * 8 + lrow) * FW
                                      + (2 * pr + (lane >> 4)) * 4) * 4);

    #pragma unroll
    for (int i = 0; i < 4; ++i) {
        int idx = tid + i * 256;
        int r = idx >> 3, c8 = idx & 7;
        uint4 w = *reinterpret_cast<const uint4*>(&Qg[(size_t)(q0 + r) * ldq + c8 * 8]);
        *reinterpret_cast<uint4*>(&Qs[r * FW + c8 * 4]) = w;
    }
    bool mrow0 = mqg[b * Sc + qi0] != 0;
    bool mrow1 = mqg[b * Sc + qi1] != 0;

    float m0 = -1e30f, m1 = -1e30f, l0 = 0.f, l1 = 0.f;
    float oacc[8][4];
    #pragma unroll
    for (int ni = 0; ni < 8; ni++) { oacc[ni][0] = oacc[ni][1] = oacc[ni][2] = oacc[ni][3] = 0.f; }

    int nkt = causal ? ((q0 >> 6) + 2) : (Sc / 64);
    for (int kt = 0; kt < nkt; ++kt) {
        int k0 = kt * 64;
        __syncthreads();
        #pragma unroll
        for (int i = 0; i < 2; ++i) {
            int idx = tid + i * 256;
            int r = idx >> 3, c8 = idx & 7;
            uint4 wk = *reinterpret_cast<const uint4*>(&Kg[(size_t)(k0 + r) * ldkv + c8 * 8]);
            *reinterpret_cast<uint4*>(&Ks[r * FW + c8 * 4]) = wk;
            uint4 wv = *reinterpret_cast<const uint4*>(&Vg[(size_t)(k0 + r) * ldkv + c8 * 8]);
            *reinterpret_cast<uint4*>(&Vs[r * FW + c8 * 4]) = wv;
        }
        if (tid < 64) mks[tid] = mkg[b * Sc + k0 + tid];
        __syncthreads();

        // ---- S = Q @ K^T ----
        float s[8][4];
        #pragma unroll
        for (int ni = 0; ni < 8; ni++) { s[ni][0] = s[ni][1] = s[ni][2] = s[ni][3] = 0.f; }
        #pragma unroll
        for (int ki = 0; ki < 4; ++ki) {
            uint32_t ko = (uint32_t)ki * 32;
            uint32_t a[4];
            LDSM4(a[0], a[1], a[2], a[3], smb + q_off + ko);
            uint32_t bfr[8][2];
            #pragma unroll
            for (int pr = 0; pr < 4; pr++) {
                uint32_t t0, t1, t2, t3;
                LDSM4(t0, t1, t2, t3, smb + k_off[pr] + ko);
                bfr[2 * pr][0] = t0; bfr[2 * pr][1] = t1;
                bfr[2 * pr + 1][0] = t2; bfr[2 * pr + 1][1] = t3;
            }
            #pragma unroll
            for (int ni = 0; ni < 8; ni++)
                mma_16n8k16_f16(s[ni], a, bfr[ni]);
        }

        // ---- scale + mask + online softmax (P kept in registers) ----
        float rmax0 = neg_inf_f(), rmax1 = neg_inf_f();
        #pragma unroll
        for (int ni = 0; ni < 8; ni++) {
            int cloc = ni * 8 + 2 * tg;
            int cg = k0 + cloc;
            bool mkA = mks[cloc] != 0, mkB = mks[cloc + 1] != 0;
            float v0 = (mrow0 || mkA || (causal && cg     > qi0)) ? neg_inf_f() : s[ni][0] * SCALEc;
            float v1 = (mrow0 || mkB || (causal && cg + 1 > qi0)) ? neg_inf_f() : s[ni][1] * SCALEc;
            float v2 = (mrow1 || mkA || (causal && cg     > qi1)) ? neg_inf_f() : s[ni][2] * SCALEc;
            float v3 = (mrow1 || mkB || (causal && cg + 1 > qi1)) ? neg_inf_f() : s[ni][3] * SCALEc;
            s[ni][0] = v0; s[ni][1] = v1; s[ni][2] = v2; s[ni][3] = v3;
            rmax0 = fmaxf(rmax0, fmaxf(v0, v1));
            rmax1 = fmaxf(rmax1, fmaxf(v2, v3));
        }
        rmax0 = fmaxf(rmax0, __shfl_xor_sync(0xffffffffu, rmax0, 1));
        rmax0 = fmaxf(rmax0, __shfl_xor_sync(0xffffffffu, rmax0, 2));
        rmax1 = fmaxf(rmax1, __shfl_xor_sync(0xffffffffu, rmax1, 1));
        rmax1 = fmaxf(rmax1, __shfl_xor_sync(0xffffffffu, rmax1, 2));

        float mn0 = fmaxf(m0, rmax0), mn1 = fmaxf(m1, rmax1);
        float sc0 = __expf(m0 - mn0), sc1 = __expf(m1 - mn1);
        float rs0 = 0.f, rs1 = 0.f;
        uint32_t pp[8][2];   // P as A-fragments: [ni][0]=rows g, [ni][1]=rows g+8
        #pragma unroll
        for (int ni = 0; ni < 8; ni++) {
            float p0 = __expf(s[ni][0] - mn0), p1 = __expf(s[ni][1] - mn0);
            float p2 = __expf(s[ni][2] - mn1), p3 = __expf(s[ni][3] - mn1);
            rs0 += p0 + p1; rs1 += p2 + p3;
            pp[ni][0] = pack_h2(make_float2(p0, p1));
            pp[ni][1] = pack_h2(make_float2(p2, p3));
        }
        rs0 += __shfl_xor_sync(0xffffffffu, rs0, 1);
        rs0 += __shfl_xor_sync(0xffffffffu, rs0, 2);
        rs1 += __shfl_xor_sync(0xffffffffu, rs1, 1);
        rs1 += __shfl_xor_sync(0xffffffffu, rs1, 2);
        l0 = l0 * sc0 + rs0; l1 = l1 * sc1 + rs1;
        m0 = mn0; m1 = mn1;
        #pragma unroll
        for (int ni = 0; ni < 8; ni++) {
            oacc[ni][0] *= sc0; oacc[ni][1] *= sc0;
            oacc[ni][2] *= sc1; oacc[ni][3] *= sc1;
        }

        // ---- O += P @ V  (P from registers: S C-frag layout == PV A-frag layout) ----
        #pragma unroll
        for (int ki = 0; ki < 4; ++ki) {
            uint32_t vko = (uint32_t)ki * 16 * FW * 4;
            uint32_t a[4] = { pp[2 * ki][0], pp[2 * ki][1],
                              pp[2 * ki + 1][0], pp[2 * ki + 1][1] };
            uint32_t bfr[8][2];
            #pragma unroll
            for (int pr = 0; pr < 4; pr++) {
                uint32_t t0, t1, t2, t3;
                LDSM4T(t0, t1, t2, t3, smb + v_off[pr] + vko);
                bfr[2 * pr][0] = t0; bfr[2 * pr][1] = t1;
                bfr[2 * pr + 1][0] = t2; bfr[2 * pr + 1][1] = t3;
            }
            #pragma unroll
            for (int ni = 0; ni < 8; ni++)
                mma_16n8k16_f16(oacc[ni], a, bfr[ni]);
        }
    }

    float inv0 = (l0 > 0.f) ? 1.f / l0 : 0.f;
    float inv1 = (l1 > 0.f) ? 1.f / l1 : 0.f;
    size_t ob0 = ((size_t)b * Sc + qi0) * Dc + h * DHc;
    size_t ob1 = ((size_t)b * Sc + qi1) * Dc + h * DHc;
    #pragma unroll
    for (int ni = 0; ni < 8; ni++) {
        int cc = ni * 8 + 2 * tg;
        *reinterpret_cast<uint32_t*>(&o[ob0 + cc]) =
            pack_h2(make_float2(oacc[ni][0] * inv0, oacc[ni][1] * inv0));
        *reinterpret_cast<uint32_t*>(&o[ob1 + cc]) =
            pack_h2(make_float2(oacc[ni][2] * inv1, oacc[ni][3] * inv1));
    }
}

// ---------------- embedding + PE (+ pad mask), dual fp32/fp16 output ----------------
__global__ void embed_pe_kernel(const int* __restrict__ toks,
                                const float* __restrict__ emb,
                                float* __restrict__ out,
                                __half* __restrict__ outh,
                                unsigned char* __restrict__ mask) {
    int pos = blockIdx.x % Sc;
    int b   = blockIdx.x / Sc;
    int tok = toks[b * Sc + pos];
    int t = threadIdx.x;
    if (t == 0) mask[b * Sc + pos] = (tok == 0) ? 1 : 0;
    const float c = -logf(10000.0f) / (float)Dc;
    size_t base = ((size_t)b * Sc + pos) * Dc;
    #pragma unroll
    for (int d = t; d < Dc; d += 256) {
        int i = d >> 1;
        float freq = __expf((float)(2 * i) * c);
        float ang  = (float)pos * freq;
        float pe   = (d & 1) ? cosf(ang) : sinf(ang);
        float v = emb[(size_t)tok * Dc + d] + pe;
        out[base + d] = v;
        outh[base + d] = __float2half_rn(v);
    }
}

// ---------------- LayerNorm: dual fp32 + fp16 output (warp per row) ----------------
__global__ void __launch_bounds__(256) ln_kernel(const float* __restrict__ xin,
                                                 const float* __restrict__ gamma,
                                                 const float* __restrict__ beta,
                                                 float* __restrict__ out,
                                                 __half* __restrict__ outh) {
    int warp = threadIdx.x >> 5, lane = threadIdx.x & 31;
    size_t row = (size_t)blockIdx.x * 8 + warp;
    size_t base = row * Dc;
    float4 v[4];
    float sum = 0.f;
    #pragma unroll
    for (int i = 0; i < 4; ++i) {
        v[i] = *reinterpret_cast<const float4*>(&xin[base + lane * 4 + i * 128]);
        sum += v[i].x + v[i].y + v[i].z + v[i].w;
    }
    #pragma unroll
    for (int s = 16; s > 0; s >>= 1) sum += __shfl_xor_sync(0xffffffffu, sum, s);
    float mu = sum * (1.0f / Dc);
    float var = 0.f;
    #pragma unroll
    for (int i = 0; i < 4; ++i) {
        v[i].x -= mu; v[i].y -= mu; v[i].z -= mu; v[i].w -= mu;
        var += v[i].x * v[i].x + v[i].y * v[i].y + v[i].z * v[i].z + v[i].w * v[i].w;
    }
    #pragma unroll
    for (int s = 16; s > 0; s >>= 1) var += __shfl_xor_sync(0xffffffffu, var, s);
    float inv = rsqrtf(var * (1.0f / Dc) + EPSc);
    #pragma unroll
    for (int i = 0; i < 4; ++i) {
        int col = lane * 4 + i * 128;
        float4 gv = *reinterpret_cast<const float4*>(&gamma[col]);
        float4 bv = *reinterpret_cast<const float4*>(&beta[col]);
        float4 o;
        o.x = v[i].x * inv * gv.x + bv.x;
        o.y = v[i].y * inv * gv.y + bv.y;
        o.z = v[i].z * inv * gv.z + bv.z;
        o.w = v[i].w * inv * gv.w + bv.w;
        *reinterpret_cast<float4*>(&out[base + col]) = o;
        uint2 hw = make_uint2(pack_h2(make_float2(o.x, o.y)),
                              pack_h2(make_float2(o.z, o.w)));
        *reinterpret_cast<uint2*>(&outh[base + col]) = hw;
    }
}

// ---------------- host orchestration ----------------
static void launch_gemm_f(const __half* A, const __half* BT, const float* bias,
                          const float* resid, float* C, int M, int N, int K) {
    dim3 grid(N / 128, M / 128);
    gemm_mma<false, false><<<grid, 256, GEMM_SMEM>>>(A, BT, bias, resid, C, M, N, K);
}
static void launch_gemm_h(const __half* A, const __half* BT, const float* bias,
                          __half* C, int M, int N, int K, bool relu) {
    dim3 grid(N / 128, M / 128);
    if (relu) gemm_mma<true,  true><<<grid, 256, GEMM_SMEM>>>(A, BT, bias, nullptr, C, M, N, K);
    else      gemm_mma<false, true><<<grid, 256, GEMM_SMEM>>>(A, BT, bias, nullptr, C, M, N, K);
}

static void run_mha(const __half* xqh, const __half* xkvh, bool same,
                    const unsigned char* mq, const unsigned char* mk, int causal,
                    const __half* wT, const float* b, const float* resid,
                    __half* qkvh, __half* qh, __half* attnh, float* outp) {
    dim3 gfl(Sc / 128, Bc * NHc);
    if (same) {
        launch_gemm_h(xqh, wT, b, qkvh, BSc, 3 * Dc, Dc, false);
        flash_attn<<<gfl, 256, FLASH_SMEM>>>(qkvh, 3 * Dc, qkvh + Dc, qkvh + 2 * Dc, 3 * Dc,
                                             mq, mk, attnh, causal);
    } else {
        // fused Q (N=512, 4 x-blocks) + KV (N=1024, 8 x-blocks) launch
        dim3 gd(4 + 8, BSc / 128);
        gemm_dual<<<gd, 256, GEMM_SMEM>>>(xqh, wT, b, qh, Dc, 4,
                                          xkvh, wT + (size_t)Dc * Dc, b + Dc, qkvh, 2 * Dc,
                                          Dc);
        flash_attn<<<gfl, 256, FLASH_SMEM>>>(qh, Dc, qkvh, qkvh + Dc, 2 * Dc,
                                             mq, mk, attnh, causal);
    }
    launch_gemm_f(attnh, wT + 3 * (size_t)Dc * Dc, b + 3 * Dc, resid, outp, BSc, Dc, Dc);
}

extern "C" void kernel_launch(void* const* d_in, const int* in_sizes, int n_in,
                              void* d_out, int out_size) {
    const int*   inputs  = (const int*)d_in[0];
    const int*   outputs = (const int*)d_in[1];
    const float* emi = (const float*)d_in[2];
    const float* emo = (const float*)d_in[3];
    const float* enc_attn_w = (const float*)d_in[4];
    const float* enc_attn_b = (const float*)d_in[5];
    const float* enc_ln     = (const float*)d_in[6];
    const float* enc_ffn_w1 = (const float*)d_in[7];
    const float* enc_ffn_b1 = (const float*)d_in[8];
    const float* enc_ffn_w2 = (const float*)d_in[9];
    const float* enc_ffn_b2 = (const float*)d_in[10];
    const float* dec_self_w  = (const float*)d_in[11];
    const float* dec_self_b  = (const float*)d_in[12];
    const float* dec_cross_w = (const float*)d_in[13];
    const float* dec_cross_b = (const float*)d_in[14];
    const float* dec_ln      = (const float*)d_in[15];
    const float* dec_ffn_w1 = (const float*)d_in[16];
    const float* dec_ffn_b1 = (const float*)d_in[17];
    const float* dec_ffn_w2 = (const float*)d_in[18];
    const float* dec_ffn_b2 = (const float*)d_in[19];

    float *xp, *yp, *tmpp;
    __half *xh, *yh, *qkvh, *qh, *attnh, *hidh;
    __half *wta_enc, *wta_self, *wta_cross, *wt_ef1, *wt_ef2, *wt_df1, *wt_df2;
    unsigned char *mxp, *myp;
    cudaGetSymbolAddress((void**)&xp, g_x);
    cudaGetSymbolAddress((void**)&yp, g_y);
    cudaGetSymbolAddress((void**)&tmpp, g_tmp);
    cudaGetSymbolAddress((void**)&xh, g_xh);
    cudaGetSymbolAddress((void**)&yh, g_yh);
    cudaGetSymbolAddress((void**)&qkvh, g_qkvh);
    cudaGetSymbolAddress((void**)&qh, g_qh);
    cudaGetSymbolAddress((void**)&attnh, g_attnh);
    cudaGetSymbolAddress((void**)&hidh, g_hidh);
    cudaGetSymbolAddress((void**)&mxp, g_mx);
    cudaGetSymbolAddress((void**)&myp, g_my);
    cudaGetSymbolAddress((void**)&wta_enc,   g_wt_enc_attn);
    cudaGetSymbolAddress((void**)&wta_self,  g_wt_dec_self);
    cudaGetSymbolAddress((void**)&wta_cross, g_wt_dec_cross);
    cudaGetSymbolAddress((void**)&wt_ef1, g_wt_enc_f1);
    cudaGetSymbolAddress((void**)&wt_ef2, g_wt_enc_f2);
    cudaGetSymbolAddress((void**)&wt_df1, g_wt_dec_f1);
    cudaGetSymbolAddress((void**)&wt_df2, g_wt_dec_f2);

    cudaFuncSetAttribute(flash_attn, cudaFuncAttributeMaxDynamicSharedMemorySize, FLASH_SMEM);
    cudaFuncSetAttribute(gemm_mma<false, false>, cudaFuncAttributeMaxDynamicSharedMemorySize, GEMM_SMEM);
    cudaFuncSetAttribute(gemm_mma<false, true >, cudaFuncAttributeMaxDynamicSharedMemorySize, GEMM_SMEM);
    cudaFuncSetAttribute(gemm_mma<true,  true >, cudaFuncAttributeMaxDynamicSharedMemorySize, GEMM_SMEM);
    cudaFuncSetAttribute(gemm_dual, cudaFuncAttributeMaxDynamicSharedMemorySize, GEMM_SMEM);

    // -------- weight transposes (fp32 -> fp16, [N][K]) --------
    dim3 tblk(32, 8);
    transpose_h<<<dim3(Dc / 32, Dc / 32, Lc * 4), tblk>>>(enc_attn_w,  wta_enc,   Dc, Dc);
    transpose_h<<<dim3(Dc / 32, Dc / 32, Lc * 4), tblk>>>(dec_self_w,  wta_self,  Dc, Dc);
    transpose_h<<<dim3(Dc / 32, Dc / 32, Lc * 4), tblk>>>(dec_cross_w, wta_cross, Dc, Dc);
    transpose_h<<<dim3(HIDc / 32, Dc / 32, Lc), tblk>>>(enc_ffn_w1, wt_ef1, Dc, HIDc);
    transpose_h<<<dim3(Dc / 32, HIDc / 32, Lc), tblk>>>(enc_ffn_w2, wt_ef2, HIDc, Dc);
    transpose_h<<<dim3(HIDc / 32, Dc / 32, Lc), tblk>>>(dec_ffn_w1, wt_df1, Dc, HIDc);
    transpose_h<<<dim3(Dc / 32, HIDc / 32, Lc), tblk>>>(dec_ffn_w2, wt_df2, HIDc, Dc);

    dim3 blk(256);
    embed_pe_kernel<<<BSc, blk>>>(inputs,  emi, xp, xh, mxp);
    embed_pe_kernel<<<BSc, blk>>>(outputs, emo, yp, yh, myp);

    int lng = BSc / 8;

    // ---------------- encoder ----------------
    for (int l = 0; l < Lc; ++l) {
        const __half* wT = wta_enc + (size_t)l * 4 * Dc * Dc;
        const float* ab = enc_attn_b + (size_t)l * 4 * Dc;
        run_mha(xh, xh, true, mxp, mxp, 0, wT, ab, xp, qkvh, qh, attnh, tmpp);
        const float* ln0 = enc_ln + (((size_t)l * 2 + 0) * 2) * Dc;
        ln_kernel<<<lng, blk>>>(tmpp, ln0, ln0 + Dc, xp, xh);
        launch_gemm_h(xh, wt_ef1 + (size_t)l * Dc * HIDc, enc_ffn_b1 + (size_t)l * HIDc,
                      hidh, BSc, HIDc, Dc, true);
        launch_gemm_f(hidh, wt_ef2 + (size_t)l * Dc * HIDc, enc_ffn_b2 + (size_t)l * Dc,
                      xp, tmpp, BSc, Dc, HIDc);
        const float* ln1 = enc_ln + (((size_t)l * 2 + 1) * 2) * Dc;
        ln_kernel<<<lng, blk>>>(tmpp, ln1, ln1 + Dc, xp, xh);
    }

    // ---------------- decoder ----------------
    float* fout = (float*)d_out;
    for (int l = 0; l < Lc; ++l) {
        const __half* swT = wta_self + (size_t)l * 4 * Dc * Dc;
        const float* sb  = dec_self_b + (size_t)l * 4 * Dc;
        run_mha(yh, yh, true, myp, myp, 1, swT, sb, yp, qkvh, qh, attnh, tmpp);
        const float* ln0 = dec_ln + (((size_t)l * 3 + 0) * 2) * Dc;
        ln_kernel<<<lng, blk>>>(tmpp, ln0, ln0 + Dc, yp, yh);

        const __half* cwT = wta_cross + (size_t)l * 4 * Dc * Dc;
        const float* cb  = dec_cross_b + (size_t)l * 4 * Dc;
        run_mha(yh, xh, false, myp, mxp, 0, cwT, cb, yp, qkvh, qh, attnh, tmpp);
        const float* ln1 = dec_ln + (((size_t)l * 3 + 1) * 2) * Dc;
        ln_kernel<<<lng, blk>>>(tmpp, ln1, ln1 + Dc, yp, yh);

        launch_gemm_h(yh, wt_df1 + (size_t)l * Dc * HIDc, dec_ffn_b1 + (size_t)l * HIDc,
                      hidh, BSc, HIDc, Dc, true);
        launch_gemm_f(hidh, wt_df2 + (size_t)l * Dc * HIDc, dec_ffn_b2 + (size_t)l * Dc,
                      yp, tmpp, BSc, Dc, HIDc);
        const float* ln2 = dec_ln + (((size_t)l * 3 + 2) * 2) * Dc;
        float* dst = (l == Lc - 1) ? fout : yp;
        ln_kernel<<<lng, blk>>>(tmpp, ln2, ln2 + Dc, dst, yh);
    }
    (void)in_sizes; (void)n_in; (void)out_size;
}

// round 13
// speedup vs baseline: 1.9800x; 1.0082x over previous
#include <cuda_runtime.h>
#include <cuda_fp16.h>
#include <math.h>
#include <cstdint>

// ---------------- problem constants ----------------
#define Bc   8
#define Sc   512
#define Dc   512
#define NHc  8
#define DHc  64
#define Lc   6
#define HIDc 2048
#define EPSc 1e-5f
#define BSc  (Bc * Sc)          // 4096 tokens
#define SCALEc 0.125f           // 1/sqrt(64)

// ---------------- device scratch ----------------
__device__ float  g_x[BSc * Dc];
__device__ float  g_y[BSc * Dc];
__device__ float  g_tmp[BSc * Dc];
__device__ __half g_xh[BSc * Dc];
__device__ __half g_yh[BSc * Dc];
__device__ __half g_qkvh[BSc * 3 * Dc];
__device__ __half g_qh[BSc * Dc];
__device__ __half g_attnh[BSc * Dc];
__device__ __half g_hidh[BSc * HIDc];
__device__ __half g_kvh[(size_t)Lc * BSc * 2 * Dc];   // all-layer cross KV cache (50 MB)
__device__ unsigned char g_mx[BSc];
__device__ unsigned char g_my[BSc];
// transposed fp16 weights: [N][K]
__device__ __half g_wt_enc_attn[Lc * 4 * Dc * Dc];
__device__ __half g_wt_dec_self[Lc * 4 * Dc * Dc];
__device__ __half g_wt_dec_cross[Lc * 4 * Dc * Dc];
__device__ __half g_wt_enc_f1[Lc * Dc * HIDc];
__device__ __half g_wt_enc_f2[Lc * Dc * HIDc];
__device__ __half g_wt_dec_f1[Lc * Dc * HIDc];
__device__ __half g_wt_dec_f2[Lc * Dc * HIDc];

__device__ __forceinline__ float neg_inf_f() { return __int_as_float(0xff800000u); }

__device__ __forceinline__ uint32_t smem_u32(const void* p) {
    uint32_t a;
    asm("{ .reg .u64 t; cvta.to.shared.u64 t, %1; cvt.u32.u64 %0, t; }" : "=r"(a) : "l"(p));
    return a;
}
__device__ __forceinline__ uint32_t pack_h2(float2 f) {
    __half2 h = __floats2half2_rn(f.x, f.y);
    return *reinterpret_cast<uint32_t*>(&h);
}

__device__ __forceinline__ void mma_16n8k16_f16(float c[4], const uint32_t a[4], const uint32_t b[2]) {
    asm volatile(
        "mma.sync.aligned.m16n8k16.row.col.f32.f16.f16.f32 "
        "{%0,%1,%2,%3}, {%4,%5,%6,%7}, {%8,%9}, {%0,%1,%2,%3};"
        : "+f"(c[0]), "+f"(c[1]), "+f"(c[2]), "+f"(c[3])
        : "r"(a[0]), "r"(a[1]), "r"(a[2]), "r"(a[3]), "r"(b[0]), "r"(b[1]));
}
#define LDSM4(r0, r1, r2, r3, addr) \
    asm volatile("ldmatrix.sync.aligned.m8n8.x4.shared.b16 {%0,%1,%2,%3}, [%4];" \
        : "=r"(r0), "=r"(r1), "=r"(r2), "=r"(r3) : "r"(addr))
#define LDSM4T(r0, r1, r2, r3, addr) \
    asm volatile("ldmatrix.sync.aligned.m8n8.x4.trans.shared.b16 {%0,%1,%2,%3}, [%4];" \
        : "=r"(r0), "=r"(r1), "=r"(r2), "=r"(r3) : "r"(addr))

// ---------------- weight transpose (fp32 -> fp16) ----------------
__global__ void transpose_h(const float* __restrict__ in, __half* __restrict__ out,
                            int R, int C) {
    __shared__ float tile[32][33];
    const float* src = in + (size_t)blockIdx.z * R * C;
    __half* dst = out + (size_t)blockIdx.z * R * C;
    int c0 = blockIdx.x * 32, r0 = blockIdx.y * 32;
    int tx = threadIdx.x, ty = threadIdx.y;
    #pragma unroll
    for (int i = 0; i < 32; i += 8)
        tile[ty + i][tx] = src[(size_t)(r0 + ty + i) * C + c0 + tx];
    __syncthreads();
    #pragma unroll
    for (int i = 0; i < 32; i += 8)
        dst[(size_t)(c0 + ty + i) * R + r0 + tx] = __float2half_rn(tile[tx][ty + i]);
}

// ---------------- fp16 mma GEMM, K-chunk 64, 3-stage cp.async ring ----------------
#define GPAD 36
#define TBUF (128 * GPAD)
#define STG_B32 (2 * TBUF)
#define STAGES 3
#define GEMM_SMEM (STAGES * STG_B32 * 4) // 110592 B -> 2 CTAs/SM

template<bool RELU, bool HALFOUT>
__device__ __forceinline__ void gemm_body(const __half* A, const __half* BT,
                                          const float* bias, const float* resid,
                                          void* Cout, int row0, int col0, int N, int K,
                                          uint32_t* gs, uint32_t sbase) {
    int tid = threadIdx.x;
    int lane = tid & 31, wid = tid >> 5;
    int wm = wid & 1, wn = wid >> 1;
    int g = lane >> 2, tg = lane & 3;
    int lrow = lane & 7, lj = lane >> 3;

    uint32_t a_off[4];
    #pragma unroll
    for (int mi = 0; mi < 4; mi++)
        a_off[mi] = (uint32_t)(((wm * 64 + mi * 16 + (lj & 1) * 8 + lrow) * GPAD
                                + (lj >> 1) * 4) * 4);
    uint32_t b_off[2];
    #pragma unroll
    for (int pr = 0; pr < 2; pr++)
        b_off[pr] = (uint32_t)(TBUF * 4
                    + ((wn * 32 + pr * 16 + (lane >> 4) * 8 + lrow) * GPAD
                       + ((lane >> 3) & 1) * 4) * 4);

    float acc[4][4][4];
    #pragma unroll
    for (int mi = 0; mi < 4; mi++)
        #pragma unroll
        for (int ni = 0; ni < 4; ni++)
            #pragma unroll
            for (int r = 0; r < 4; r++) acc[mi][ni][r] = 0.0f;

    int nch = K >> 6;

    {
        uint32_t ab = sbase, bb = sbase + TBUF * 4;
        #pragma unroll
        for (int i = 0; i < 4; ++i) {
            int idx = tid + i * 256;
            int n = idx >> 3, ch = idx & 7;
            const __half* pa = &A[(size_t)(row0 + n) * K + ch * 8];
            asm volatile("cp.async.cg.shared.global [%0], [%1], 16;"
                         :: "r"(ab + (uint32_t)(n * GPAD + ch * 4) * 4), "l"(pa));
            const __half* pb = &BT[(size_t)(col0 + n) * K + ch * 8];
            asm volatile("cp.async.cg.shared.global [%0], [%1], 16;"
                         :: "r"(bb + (uint32_t)(n * GPAD + ch * 4) * 4), "l"(pb));
        }
        asm volatile("cp.async.commit_group;" ::: "memory");
    }

    for (int c = 0; c < nch; ++c) {
        if (c + 1 < nch) {
            int k0 = (c + 1) << 6;
            uint32_t stoff = (uint32_t)(((c + 1) % STAGES) * STG_B32) * 4;
            uint32_t ab = sbase + stoff, bb = ab + TBUF * 4;
            #pragma unroll
            for (int i = 0; i < 4; ++i) {
                int idx = tid + i * 256;
                int n = idx >> 3, ch = idx & 7;
                const __half* pa = &A[(size_t)(row0 + n) * K + k0 + ch * 8];
                asm volatile("cp.async.cg.shared.global [%0], [%1], 16;"
                             :: "r"(ab + (uint32_t)(n * GPAD + ch * 4) * 4), "l"(pa));
                const __half* pb = &BT[(size_t)(col0 + n) * K + k0 + ch * 8];
                asm volatile("cp.async.cg.shared.global [%0], [%1], 16;"
                             :: "r"(bb + (uint32_t)(n * GPAD + ch * 4) * 4), "l"(pb));
            }
        }
        asm volatile("cp.async.commit_group;" ::: "memory");
        asm volatile("cp.async.wait_group 1;" ::: "memory");
        __syncthreads();

        uint32_t stb = sbase + (uint32_t)((c % STAGES) * STG_B32) * 4;

        #pragma unroll
        for (int ki = 0; ki < 4; ++ki) {
            uint32_t ko = (uint32_t)ki * 32;
            uint32_t afr[4][4];
            #pragma unroll
            for (int mi = 0; mi < 4; mi++)
                LDSM4(afr[mi][0], afr[mi][1], afr[mi][2], afr[mi][3], stb + a_off[mi] + ko);
            uint32_t bfr[4][2];
            {
                uint32_t t0, t1, t2, t3;
                LDSM4(t0, t1, t2, t3, stb + b_off[0] + ko);
                bfr[0][0] = t0; bfr[0][1] = t1; bfr[1][0] = t2; bfr[1][1] = t3;
                LDSM4(t0, t1, t2, t3, stb + b_off[1] + ko);
                bfr[2][0] = t0; bfr[2][1] = t1; bfr[3][0] = t2; bfr[3][1] = t3;
            }
            #pragma unroll
            for (int mi = 0; mi < 4; mi++)
                #pragma unroll
                for (int ni = 0; ni < 4; ni++)
                    mma_16n8k16_f16(acc[mi][ni], afr[mi], bfr[ni]);
        }
    }

    #pragma unroll
    for (int mi = 0; mi < 4; mi++) {
        int r0r = row0 + wm * 64 + mi * 16 + g;
        #pragma unroll
        for (int ni = 0; ni < 4; ni++) {
            int cb = col0 + wn * 32 + ni * 8 + tg * 2;
            float b0 = bias[cb], b1 = bias[cb + 1];
            float v0 = acc[mi][ni][0] + b0, v1 = acc[mi][ni][1] + b1;
            float v2 = acc[mi][ni][2] + b0, v3 = acc[mi][ni][3] + b1;
            if (resid) {
                float2 r0v = *reinterpret_cast<const float2*>(&resid[(size_t)(r0r)     * N + cb]);
                float2 r1v = *reinterpret_cast<const float2*>(&resid[(size_t)(r0r + 8) * N + cb]);
                v0 += r0v.x; v1 += r0v.y; v2 += r1v.x; v3 += r1v.y;
            }
            if (RELU) { v0 = fmaxf(v0, 0.f); v1 = fmaxf(v1, 0.f);
                        v2 = fmaxf(v2, 0.f); v3 = fmaxf(v3, 0.f); }
            if (HALFOUT) {
                __half* Ch = (__half*)Cout;
                *reinterpret_cast<uint32_t*>(&Ch[(size_t)(r0r)     * N + cb]) = pack_h2(make_float2(v0, v1));
                *reinterpret_cast<uint32_t*>(&Ch[(size_t)(r0r + 8) * N + cb]) = pack_h2(make_float2(v2, v3));
            } else {
                float* Cf = (float*)Cout;
                *reinterpret_cast<float2*>(&Cf[(size_t)(r0r)     * N + cb]) = make_float2(v0, v1);
                *reinterpret_cast<float2*>(&Cf[(size_t)(r0r + 8) * N + cb]) = make_float2(v2, v3);
            }
        }
    }
}

template<bool RELU, bool HALFOUT>
__global__ void __launch_bounds__(256) gemm_mma(const __half* __restrict__ A,
                                                const __half* __restrict__ BT,
                                                const float* __restrict__ bias,
                                                const float* __restrict__ resid,
                                                void* __restrict__ Cout,
                                                int M, int N, int K) {
    extern __shared__ uint32_t gs[];
    gemm_body<RELU, HALFOUT>(A, BT, bias, resid, Cout,
                             blockIdx.y * 128, blockIdx.x * 128, N, K, gs, smem_u32(gs));
}

// batched cross-attn KV projection for ALL layers: z = layer.
__global__ void __launch_bounds__(256) gemm_kv_all(const __half* __restrict__ A,
                                                   const __half* __restrict__ wbase,
                                                   const float* __restrict__ bbase,
                                                   __half* __restrict__ Cbase) {
    extern __shared__ uint32_t gs[];
    int l = blockIdx.z;
    const __half* BT = wbase + (size_t)l * 4 * Dc * Dc + (size_t)Dc * Dc;  // K,V weights
    const float* bias = bbase + (size_t)l * 4 * Dc + Dc;
    __half* C = Cbase + (size_t)l * BSc * 2 * Dc;
    gemm_body<false, true>(A, BT, bias, nullptr, C,
                           blockIdx.y * 128, blockIdx.x * 128, 2 * Dc, Dc, gs, smem_u32(gs));
}

// ---------------- fused flash attention: q-tile 64, 128 threads, 512 CTAs ----------------
#define FW 36
#define FLASH_SMEM ((64 + 64 + 64) * FW * 4 + 64)

__global__ void __launch_bounds__(128) flash_attn(
    const __half* __restrict__ q, int ldq,
    const __half* __restrict__ k, const __half* __restrict__ v, int ldkv,
    const unsigned char* __restrict__ mqg, const unsigned char* __restrict__ mkg,
    __half* __restrict__ o, int causal)
{
    extern __shared__ char sm[];
    uint32_t smb = smem_u32(sm);
    uint32_t* Qs = reinterpret_cast<uint32_t*>(sm);        // [64][FW]
    uint32_t* Ks = Qs + 64 * FW;                           // [64][FW]
    uint32_t* Vs = Ks + 64 * FW;                           // [64][FW]
    unsigned char* mks = reinterpret_cast<unsigned char*>(Vs + 64 * FW);
    const uint32_t QS0 = 0, KS0 = 64 * FW * 4, VS0 = 128 * FW * 4;

    int tid = threadIdx.x, lane = tid & 31, wid = tid >> 5;   // 4 warps
    int bh = blockIdx.y, b = bh >> 3, h = bh & 7;
    int qt = causal ? ((int)gridDim.x - 1 - (int)blockIdx.x) : (int)blockIdx.x;
    int q0 = qt * 64;
    const __half* Qg = q + (size_t)b * Sc * ldq + h * DHc;
    const __half* Kg = k + (size_t)b * Sc * ldkv + h * DHc;
    const __half* Vg = v + (size_t)b * Sc * ldkv + h * DHc;
    int g = lane >> 2, tg = lane & 3;
    int lrow = lane & 7, lj = lane >> 3;
    int rg = wid * 16 + g;
    int qi0 = q0 + rg, qi1 = qi0 + 8;

    uint32_t q_off = QS0 + (uint32_t)(((wid * 16 + (lj & 1) * 8 + lrow) * FW + (lj >> 1) * 4) * 4);
    uint32_t k_off[4];
    #pragma unroll
    for (int pr = 0; pr < 4; pr++)
        k_off[pr] = KS0 + (uint32_t)(((pr * 16 + (lane >> 4) * 8 + lrow) * FW
                                      + ((lane >> 3) & 1) * 4) * 4);
    uint32_t v_off[4];
    #pragma unroll
    for (int pr = 0; pr < 4; pr++)
        v_off[pr] = VS0 + (uint32_t)(((((lane >> 3) & 1) * 8 + lrow) * FW
                                      + (2 * pr + (lane >> 4)) * 4) * 4);

    #pragma unroll
    for (int i = 0; i < 4; ++i) {          // 64 rows x 8 chunks / 128 threads
        int idx = tid + i * 128;
        int r = idx >> 3, c8 = idx & 7;
        uint4 w = *reinterpret_cast<const uint4*>(&Qg[(size_t)(q0 + r) * ldq + c8 * 8]);
        *reinterpret_cast<uint4*>(&Qs[r * FW + c8 * 4]) = w;
    }
    bool mrow0 = mqg[b * Sc + qi0] != 0;
    bool mrow1 = mqg[b * Sc + qi1] != 0;

    float m0 = -1e30f, m1 = -1e30f, l0 = 0.f, l1 = 0.f;
    float oacc[8][4];
    #pragma unroll
    for (int ni = 0; ni < 8; ni++) { oacc[ni][0] = oacc[ni][1] = oacc[ni][2] = oacc[ni][3] = 0.f; }

    int nkt = causal ? ((q0 >> 6) + 1) : (Sc / 64);
    for (int kt = 0; kt < nkt; ++kt) {
        int k0 = kt * 64;
        __syncthreads();
        #pragma unroll
        for (int i = 0; i < 4; ++i) {
            int idx = tid + i * 128;
            int r = idx >> 3, c8 = idx & 7;
            uint4 wk = *reinterpret_cast<const uint4*>(&Kg[(size_t)(k0 + r) * ldkv + c8 * 8]);
            *reinterpret_cast<uint4*>(&Ks[r * FW + c8 * 4]) = wk;
            uint4 wv = *reinterpret_cast<const uint4*>(&Vg[(size_t)(k0 + r) * ldkv + c8 * 8]);
            *reinterpret_cast<uint4*>(&Vs[r * FW + c8 * 4]) = wv;
        }
        if (tid < 64) mks[tid] = mkg[b * Sc + k0 + tid];
        __syncthreads();

        // ---- S = Q @ K^T ----
        float s[8][4];
        #pragma unroll
        for (int ni = 0; ni < 8; ni++) { s[ni][0] = s[ni][1] = s[ni][2] = s[ni][3] = 0.f; }
        #pragma unroll
        for (int ki = 0; ki < 4; ++ki) {
            uint32_t ko = (uint32_t)ki * 32;
            uint32_t a[4];
            LDSM4(a[0], a[1], a[2], a[3], smb + q_off + ko);
            uint32_t bfr[8][2];
            #pragma unroll
            for (int pr = 0; pr < 4; pr++) {
                uint32_t t0, t1, t2, t3;
                LDSM4(t0, t1, t2, t3, smb + k_off[pr] + ko);
                bfr[2 * pr][0] = t0; bfr[2 * pr][1] = t1;
                bfr[2 * pr + 1][0] = t2; bfr[2 * pr + 1][1] = t3;
            }
            #pragma unroll
            for (int ni = 0; ni < 8; ni++)
                mma_16n8k16_f16(s[ni], a, bfr[ni]);
        }

        // ---- scale + mask + online softmax (P in registers) ----
        float rmax0 = neg_inf_f(), rmax1 = neg_inf_f();
        #pragma unroll
        for (int ni = 0; ni < 8; ni++) {
            int cloc = ni * 8 + 2 * tg;
            int cg = k0 + cloc;
            bool mkA = mks[cloc] != 0, mkB = mks[cloc + 1] != 0;
            float v0 = (mrow0 || mkA || (causal && cg     > qi0)) ? neg_inf_f() : s[ni][0] * SCALEc;
            float v1 = (mrow0 || mkB || (causal && cg + 1 > qi0)) ? neg_inf_f() : s[ni][1] * SCALEc;
            float v2 = (mrow1 || mkA || (causal && cg     > qi1)) ? neg_inf_f() : s[ni][2] * SCALEc;
            float v3 = (mrow1 || mkB || (causal && cg + 1 > qi1)) ? neg_inf_f() : s[ni][3] * SCALEc;
            s[ni][0] = v0; s[ni][1] = v1; s[ni][2] = v2; s[ni][3] = v3;
            rmax0 = fmaxf(rmax0, fmaxf(v0, v1));
            rmax1 = fmaxf(rmax1, fmaxf(v2, v3));
        }
        rmax0 = fmaxf(rmax0, __shfl_xor_sync(0xffffffffu, rmax0, 1));
        rmax0 = fmaxf(rmax0, __shfl_xor_sync(0xffffffffu, rmax0, 2));
        rmax1 = fmaxf(rmax1, __shfl_xor_sync(0xffffffffu, rmax1, 1));
        rmax1 = fmaxf(rmax1, __shfl_xor_sync(0xffffffffu, rmax1, 2));

        float mn0 = fmaxf(m0, rmax0), mn1 = fmaxf(m1, rmax1);
        float sc0 = __expf(m0 - mn0), sc1 = __expf(m1 - mn1);
        float rs0 = 0.f, rs1 = 0.f;
        uint32_t pp[8][2];
        #pragma unroll
        for (int ni = 0; ni < 8; ni++) {
            float p0 = __expf(s[ni][0] - mn0), p1 = __expf(s[ni][1] - mn0);
            float p2 = __expf(s[ni][2] - mn1), p3 = __expf(s[ni][3] - mn1);
            rs0 += p0 + p1; rs1 += p2 + p3;
            pp[ni][0] = pack_h2(make_float2(p0, p1));
            pp[ni][1] = pack_h2(make_float2(p2, p3));
        }
        rs0 += __shfl_xor_sync(0xffffffffu, rs0, 1);
        rs0 += __shfl_xor_sync(0xffffffffu, rs0, 2);
        rs1 += __shfl_xor_sync(0xffffffffu, rs1, 1);
        rs1 += __shfl_xor_sync(0xffffffffu, rs1, 2);
        l0 = l0 * sc0 + rs0; l1 = l1 * sc1 + rs1;
        m0 = mn0; m1 = mn1;
        #pragma unroll
        for (int ni = 0; ni < 8; ni++) {
            oacc[ni][0] *= sc0; oacc[ni][1] *= sc0;
            oacc[ni][2] *= sc1; oacc[ni][3] *= sc1;
        }

        // ---- O += P @ V ----
        #pragma unroll
        for (int ki = 0; ki < 4; ++ki) {
            uint32_t vko = (uint32_t)ki * 16 * FW * 4;
            uint32_t a[4] = { pp[2 * ki][0], pp[2 * ki][1],
                              pp[2 * ki + 1][0], pp[2 * ki + 1][1] };
            uint32_t bfr[8][2];
            #pragma unroll
            for (int pr = 0; pr < 4; pr++) {
                uint32_t t0, t1, t2, t3;
                LDSM4T(t0, t1, t2, t3, smb + v_off[pr] + vko);
                bfr[2 * pr][0] = t0; bfr[2 * pr][1] = t1;
                bfr[2 * pr + 1][0] = t2; bfr[2 * pr + 1][1] = t3;
            }
            #pragma unroll
            for (int ni = 0; ni < 8; ni++)
                mma_16n8k16_f16(oacc[ni], a, bfr[ni]);
        }
    }

    float inv0 = (l0 > 0.f) ? 1.f / l0 : 0.f;
    float inv1 = (l1 > 0.f) ? 1.f / l1 : 0.f;
    size_t ob0 = ((size_t)b * Sc + qi0) * Dc + h * DHc;
    size_t ob1 = ((size_t)b * Sc + qi1) * Dc + h * DHc;
    #pragma unroll
    for (int ni = 0; ni < 8; ni++) {
        int cc = ni * 8 + 2 * tg;
        *reinterpret_cast<uint32_t*>(&o[ob0 + cc]) =
            pack_h2(make_float2(oacc[ni][0] * inv0, oacc[ni][1] * inv0));
        *reinterpret_cast<uint32_t*>(&o[ob1 + cc]) =
            pack_h2(make_float2(oacc[ni][2] * inv1, oacc[ni][3] * inv1));
    }
}

// ---------------- embedding + PE (+ pad mask), dual fp32/fp16 output ----------------
__global__ void embed_pe_kernel(const int* __restrict__ toks,
                                const float* __restrict__ emb,
                                float* __restrict__ out,
                                __half* __restrict__ outh,
                                unsigned char* __restrict__ mask) {
    int pos = blockIdx.x % Sc;
    int b   = blockIdx.x / Sc;
    int tok = toks[b * Sc + pos];
    int t = threadIdx.x;
    if (t == 0) mask[b * Sc + pos] = (tok == 0) ? 1 : 0;
    const float c = -logf(10000.0f) / (float)Dc;
    size_t base = ((size_t)b * Sc + pos) * Dc;
    #pragma unroll
    for (int d = t; d < Dc; d += 256) {
        int i = d >> 1;
        float freq = __expf((float)(2 * i) * c);
        float ang  = (float)pos * freq;
        float pe   = (d & 1) ? cosf(ang) : sinf(ang);
        float v = emb[(size_t)tok * Dc + d] + pe;
        out[base + d] = v;
        outh[base + d] = __float2half_rn(v);
    }
}

// ---------------- LayerNorm: dual fp32 + fp16 output (warp per row) ----------------
__global__ void __launch_bounds__(256) ln_kernel(const float* __restrict__ xin,
                                                 const float* __restrict__ gamma,
                                                 const float* __restrict__ beta,
                                                 float* __restrict__ out,
                                                 __half* __restrict__ outh) {
    int warp = threadIdx.x >> 5, lane = threadIdx.x & 31;
    size_t row = (size_t)blockIdx.x * 8 + warp;
    size_t base = row * Dc;
    float4 v[4];
    float sum = 0.f;
    #pragma unroll
    for (int i = 0; i < 4; ++i) {
        v[i] = *reinterpret_cast<const float4*>(&xin[base + lane * 4 + i * 128]);
        sum += v[i].x + v[i].y + v[i].z + v[i].w;
    }
    #pragma unroll
    for (int s = 16; s > 0; s >>= 1) sum += __shfl_xor_sync(0xffffffffu, sum, s);
    float mu = sum * (1.0f / Dc);
    float var = 0.f;
    #pragma unroll
    for (int i = 0; i < 4; ++i) {
        v[i].x -= mu; v[i].y -= mu; v[i].z -= mu; v[i].w -= mu;
        var += v[i].x * v[i].x + v[i].y * v[i].y + v[i].z * v[i].z + v[i].w * v[i].w;
    }
    #pragma unroll
    for (int s = 16; s > 0; s >>= 1) var += __shfl_xor_sync(0xffffffffu, var, s);
    float inv = rsqrtf(var * (1.0f / Dc) + EPSc);
    #pragma unroll
    for (int i = 0; i < 4; ++i) {
        int col = lane * 4 + i * 128;
        float4 gv = *reinterpret_cast<const float4*>(&gamma[col]);
        float4 bv = *reinterpret_cast<const float4*>(&beta[col]);
        float4 o;
        o.x = v[i].x * inv * gv.x + bv.x;
        o.y = v[i].y * inv * gv.y + bv.y;
        o.z = v[i].z * inv * gv.z + bv.z;
        o.w = v[i].w * inv * gv.w + bv.w;
        *reinterpret_cast<float4*>(&out[base + col]) = o;
        uint2 hw = make_uint2(pack_h2(make_float2(o.x, o.y)),
                              pack_h2(make_float2(o.z, o.w)));
        *reinterpret_cast<uint2*>(&outh[base + col]) = hw;
    }
}

// ---------------- host orchestration ----------------
static void launch_gemm_f(const __half* A, const __half* BT, const float* bias,
                          const float* resid, float* C, int M, int N, int K) {
    dim3 grid(N / 128, M / 128);
    gemm_mma<false, false><<<grid, 256, GEMM_SMEM>>>(A, BT, bias, resid, C, M, N, K);
}
static void launch_gemm_h(const __half* A, const __half* BT, const float* bias,
                          __half* C, int M, int N, int K, bool relu) {
    dim3 grid(N / 128, M / 128);
    if (relu) gemm_mma<true,  true><<<grid, 256, GEMM_SMEM>>>(A, BT, bias, nullptr, C, M, N, K);
    else      gemm_mma<false, true><<<grid, 256, GEMM_SMEM>>>(A, BT, bias, nullptr, C, M, N, K);
}

extern "C" void kernel_launch(void* const* d_in, const int* in_sizes, int n_in,
                              void* d_out, int out_size) {
    const int*   inputs  = (const int*)d_in[0];
    const int*   outputs = (const int*)d_in[1];
    const float* emi = (const float*)d_in[2];
    const float* emo = (const float*)d_in[3];
    const float* enc_attn_w = (const float*)d_in[4];
    const float* enc_attn_b = (const float*)d_in[5];
    const float* enc_ln     = (const float*)d_in[6];
    const float* enc_ffn_w1 = (const float*)d_in[7];
    const float* enc_ffn_b1 = (const float*)d_in[8];
    const float* enc_ffn_w2 = (const float*)d_in[9];
    const float* enc_ffn_b2 = (const float*)d_in[10];
    const float* dec_self_w  = (const float*)d_in[11];
    const float* dec_self_b  = (const float*)d_in[12];
    const float* dec_cross_w = (const float*)d_in[13];
    const float* dec_cross_b = (const float*)d_in[14];
    const float* dec_ln      = (const float*)d_in[15];
    const float* dec_ffn_w1 = (const float*)d_in[16];
    const float* dec_ffn_b1 = (const float*)d_in[17];
    const float* dec_ffn_w2 = (const float*)d_in[18];
    const float* dec_ffn_b2 = (const float*)d_in[19];

    float *xp, *yp, *tmpp;
    __half *xh, *yh, *qkvh, *qh, *attnh, *hidh, *kvh;
    __half *wta_enc, *wta_self, *wta_cross, *wt_ef1, *wt_ef2, *wt_df1, *wt_df2;
    unsigned char *mxp, *myp;
    cudaGetSymbolAddress((void**)&xp, g_x);
    cudaGetSymbolAddress((void**)&yp, g_y);
    cudaGetSymbolAddress((void**)&tmpp, g_tmp);
    cudaGetSymbolAddress((void**)&xh, g_xh);
    cudaGetSymbolAddress((void**)&yh, g_yh);
    cudaGetSymbolAddress((void**)&qkvh, g_qkvh);
    cudaGetSymbolAddress((void**)&qh, g_qh);
    cudaGetSymbolAddress((void**)&attnh, g_attnh);
    cudaGetSymbolAddress((void**)&hidh, g_hidh);
    cudaGetSymbolAddress((void**)&kvh, g_kvh);
    cudaGetSymbolAddress((void**)&mxp, g_mx);
    cudaGetSymbolAddress((void**)&myp, g_my);
    cudaGetSymbolAddress((void**)&wta_enc,   g_wt_enc_attn);
    cudaGetSymbolAddress((void**)&wta_self,  g_wt_dec_self);
    cudaGetSymbolAddress((void**)&wta_cross, g_wt_dec_cross);
    cudaGetSymbolAddress((void**)&wt_ef1, g_wt_enc_f1);
    cudaGetSymbolAddress((void**)&wt_ef2, g_wt_enc_f2);
    cudaGetSymbolAddress((void**)&wt_df1, g_wt_dec_f1);
    cudaGetSymbolAddress((void**)&wt_df2, g_wt_dec_f2);

    cudaFuncSetAttribute(flash_attn, cudaFuncAttributeMaxDynamicSharedMemorySize, FLASH_SMEM);
    cudaFuncSetAttribute(gemm_mma<false, false>, cudaFuncAttributeMaxDynamicSharedMemorySize, GEMM_SMEM);
    cudaFuncSetAttribute(gemm_mma<false, true >, cudaFuncAttributeMaxDynamicSharedMemorySize, GEMM_SMEM);
    cudaFuncSetAttribute(gemm_mma<true,  true >, cudaFuncAttributeMaxDynamicSharedMemorySize, GEMM_SMEM);
    cudaFuncSetAttribute(gemm_kv_all, cudaFuncAttributeMaxDynamicSharedMemorySize, GEMM_SMEM);

    // -------- weight transposes (fp32 -> fp16, [N][K]) --------
    dim3 tblk(32, 8);
    transpose_h<<<dim3(Dc / 32, Dc / 32, Lc * 4), tblk>>>(enc_attn_w,  wta_enc,   Dc, Dc);
    transpose_h<<<dim3(Dc / 32, Dc / 32, Lc * 4), tblk>>>(dec_self_w,  wta_self,  Dc, Dc);
    transpose_h<<<dim3(Dc / 32, Dc / 32, Lc * 4), tblk>>>(dec_cross_w, wta_cross, Dc, Dc);
    transpose_h<<<dim3(HIDc / 32, Dc / 32, Lc), tblk>>>(enc_ffn_w1, wt_ef1, Dc, HIDc);
    transpose_h<<<dim3(Dc / 32, HIDc / 32, Lc), tblk>>>(enc_ffn_w2, wt_ef2, HIDc, Dc);
    transpose_h<<<dim3(HIDc / 32, Dc / 32, Lc), tblk>>>(dec_ffn_w1, wt_df1, Dc, HIDc);
    transpose_h<<<dim3(Dc / 32, HIDc / 32, Lc), tblk>>>(dec_ffn_w2, wt_df2, HIDc, Dc);

    dim3 blk(256);
    embed_pe_kernel<<<BSc, blk>>>(inputs,  emi, xp, xh, mxp);
    embed_pe_kernel<<<BSc, blk>>>(outputs, emo, yp, yh, myp);

    int lng = BSc / 8;
    dim3 gfl(Sc / 64, Bc * NHc);          // 512 CTAs, 128 threads

    // ---------------- encoder ----------------
    for (int l = 0; l < Lc; ++l) {
        const __half* wT = wta_enc + (size_t)l * 4 * Dc * Dc;
        const float* ab = enc_attn_b + (size_t)l * 4 * Dc;
        launch_gemm_h(xh, wT, ab, qkvh, BSc, 3 * Dc, Dc, false);
        flash_attn<<<gfl, 128, FLASH_SMEM>>>(qkvh, 3 * Dc, qkvh + Dc, qkvh + 2 * Dc, 3 * Dc,
                                             mxp, mxp, attnh, 0);
        launch_gemm_f(attnh, wT + 3 * (size_t)Dc * Dc, ab + 3 * Dc, xp, tmpp, BSc, Dc, Dc);
        const float* ln0 = enc_ln + (((size_t)l * 2 + 0) * 2) * Dc;
        ln_kernel<<<lng, blk>>>(tmpp, ln0, ln0 + Dc, xp, xh);
        launch_gemm_h(xh, wt_ef1 + (size_t)l * Dc * HIDc, enc_ffn_b1 + (size_t)l * HIDc,
                      hidh, BSc, HIDc, Dc, true);
        launch_gemm_f(hidh, wt_ef2 + (size_t)l * Dc * HIDc, enc_ffn_b2 + (size_t)l * Dc,
                      xp, tmpp, BSc, Dc, HIDc);
        const float* ln1 = enc_ln + (((size_t)l * 2 + 1) * 2) * Dc;
        ln_kernel<<<lng, blk>>>(tmpp, ln1, ln1 + Dc, xp, xh);
    }

    // -------- all-layer cross KV projections in one batched launch --------
    {
        dim3 gkv(2 * Dc / 128, BSc / 128, Lc);   // (8, 32, 6) = 1536 CTAs
        gemm_kv_all<<<gkv, 256, GEMM_SMEM>>>(xh, wta_cross, dec_cross_b, kvh);
    }

    // ---------------- decoder ----------------
    float* fout = (float*)d_out;
    for (int l = 0; l < Lc; ++l) {
        const __half* swT = wta_self + (size_t)l * 4 * Dc * Dc;
        const float* sb  = dec_self_b + (size_t)l * 4 * Dc;
        launch_gemm_h(yh, swT, sb, qkvh, BSc, 3 * Dc, Dc, false);
        flash_attn<<<gfl, 128, FLASH_SMEM>>>(qkvh, 3 * Dc, qkvh + Dc, qkvh + 2 * Dc, 3 * Dc,
                                             myp, myp, attnh, 1);
        launch_gemm_f(attnh, swT + 3 * (size_t)Dc * Dc, sb + 3 * Dc, yp, tmpp, BSc, Dc, Dc);
        const float* ln0 = dec_ln + (((size_t)l * 3 + 0) * 2) * Dc;
        ln_kernel<<<lng, blk>>>(tmpp, ln0, ln0 + Dc, yp, yh);

        const __half* cwT = wta_cross + (size_t)l * 4 * Dc * Dc;
        const float* cb  = dec_cross_b + (size_t)l * 4 * Dc;
        __half* kv = kvh + (size_t)l * BSc * 2 * Dc;
        launch_gemm_h(yh, cwT, cb, qh, BSc, Dc, Dc, false);
        flash_attn<<<gfl, 128, FLASH_SMEM>>>(qh, Dc, kv, kv + Dc, 2 * Dc,
                                             myp, mxp, attnh, 0);
        launch_gemm_f(attnh, cwT + 3 * (size_t)Dc * Dc, cb + 3 * Dc, yp, tmpp, BSc, Dc, Dc);
        const float* ln1 = dec_ln + (((size_t)l * 3 + 1) * 2) * Dc;
        ln_kernel<<<lng, blk>>>(tmpp, ln1, ln1 + Dc, yp, yh);

        launch_gemm_h(yh, wt_df1 + (size_t)l * Dc * HIDc, dec_ffn_b1 + (size_t)l * HIDc,
                      hidh, BSc, HIDc, Dc, true);
        launch_gemm_f(hidh, wt_df2 + (size_t)l * Dc * HIDc, dec_ffn_b2 + (size_t)l * Dc,
                      yp, tmpp, BSc, Dc, HIDc);
        const float* ln2 = dec_ln + (((size_t)l * 3 + 2) * 2) * Dc;
        float* dst = (l == Lc - 1) ? fout : yp;
        ln_kernel<<<lng, blk>>>(tmpp, ln2, ln2 + Dc, dst, yh);
    }
    (void)in_sizes; (void)n_in; (void)out_size;
}